// round 1
// baseline (speedup 1.0000x reference)
#include <cuda_runtime.h>

// ---------------- problem constants ----------------
#define SEQ   2048
#define HID   1024
#define H3    3072
#define NHEAD 16
#define HD    64
#define WIN   128
#define GSTRIDE 64

// scratch (device globals — no cudaMalloc allowed)
__device__ float g_qkv[SEQ * H3];     // [S, 3H]: q | k | v
__device__ float g_attn[SEQ * HID];   // attention output [S, H]

// ---------------- SGEMM: C[M,N] = A[M,K] * B[N,K]^T (both K-major) ----------------
template<int BM, int BN, int BK>
__global__ __launch_bounds__(256) void sgemm_tn(const float* __restrict__ A,
                                                const float* __restrict__ B,
                                                float* __restrict__ C,
                                                int M, int N, int K) {
    __shared__ float As[BK][BM + 4];
    __shared__ float Bs[BK][BN + 4];

    const int t  = threadIdx.x;
    const int tx = t & 15;
    const int ty = t >> 4;

    const float* Ab = A + (size_t)(blockIdx.y * BM) * K;
    const float* Bb = B + (size_t)(blockIdx.x * BN) * K;

    float acc[8][8];
#pragma unroll
    for (int r = 0; r < 8; r++)
#pragma unroll
        for (int s = 0; s < 8; s++) acc[r][s] = 0.f;

    const int lrow = t >> 1;        // 0..127
    const int lcol = (t & 1) * 4;   // 0 or 4

    for (int k0 = 0; k0 < K; k0 += BK) {
        float4 a4 = *(const float4*)(Ab + (size_t)lrow * K + k0 + lcol);
        float4 b4 = *(const float4*)(Bb + (size_t)lrow * K + k0 + lcol);
        As[lcol + 0][lrow] = a4.x; As[lcol + 1][lrow] = a4.y;
        As[lcol + 2][lrow] = a4.z; As[lcol + 3][lrow] = a4.w;
        Bs[lcol + 0][lrow] = b4.x; Bs[lcol + 1][lrow] = b4.y;
        Bs[lcol + 2][lrow] = b4.z; Bs[lcol + 3][lrow] = b4.w;
        __syncthreads();

#pragma unroll
        for (int kk = 0; kk < BK; kk++) {
            float ar[8], br[8];
#pragma unroll
            for (int r = 0; r < 8; r++) ar[r] = As[kk][ty + 16 * r];
#pragma unroll
            for (int s = 0; s < 8; s++) br[s] = Bs[kk][tx + 16 * s];
#pragma unroll
            for (int r = 0; r < 8; r++)
#pragma unroll
                for (int s = 0; s < 8; s++) acc[r][s] += ar[r] * br[s];
        }
        __syncthreads();
    }

#pragma unroll
    for (int r = 0; r < 8; r++) {
        const int m = blockIdx.y * BM + ty + 16 * r;
#pragma unroll
        for (int s = 0; s < 8; s++) {
            const int n = blockIdx.x * BN + tx + 16 * s;
            C[(size_t)m * N + n] = acc[r][s];
        }
    }
}

// ---------------- local (band + global-col) attention ----------------
// one thread = one query; block = 64 queries of one head
__global__ __launch_bounds__(64) void attn_local() {
    const int qt  = blockIdx.x;      // 0..31
    const int h   = blockIdx.y;      // 0..15
    const int tid = threadIdx.x;     // 0..63
    const int q0  = qt * 64;
    const int qi  = q0 + tid;

    __shared__ float Ks[32][64];
    __shared__ float Vs[32][64];

    float q[64], o[64];
    const float* qrow = g_qkv + (size_t)qi * H3 + h * HD;
#pragma unroll
    for (int d = 0; d < 64; d++) { q[d] = qrow[d] * 0.125f; o[d] = 0.f; }

    float m = -1e30f, l = 0.f;

    const int kstart = (q0 - WIN) > 0 ? (q0 - WIN) : 0;
    const int kend   = (q0 + 64 + WIN) < SEQ ? (q0 + 64 + WIN) : SEQ;

    // ---- phase 1: band tiles, mask |qi-kj| <= WIN ----
    for (int kt = kstart; kt < kend; kt += 32) {
        __syncthreads();
#pragma unroll
        for (int i = 0; i < 32; i++) {
            Ks[i][tid] = g_qkv[(size_t)(kt + i) * H3 + HID     + h * HD + tid];
            Vs[i][tid] = g_qkv[(size_t)(kt + i) * H3 + 2 * HID + h * HD + tid];
        }
        __syncthreads();

        for (int j = 0; j < 32; j++) {
            const int kj = kt + j;
            int dist = qi - kj; if (dist < 0) dist = -dist;
            if (dist <= WIN) {
                float s0 = 0.f, s1 = 0.f, s2 = 0.f, s3 = 0.f;
#pragma unroll
                for (int d = 0; d < 64; d += 4) {
                    s0 += q[d + 0] * Ks[j][d + 0];
                    s1 += q[d + 1] * Ks[j][d + 1];
                    s2 += q[d + 2] * Ks[j][d + 2];
                    s3 += q[d + 3] * Ks[j][d + 3];
                }
                const float s = (s0 + s1) + (s2 + s3);
                if (s > m) {
                    const float c = __expf(m - s);
                    l = l * c + 1.f;
#pragma unroll
                    for (int d = 0; d < 64; d++) o[d] = o[d] * c + Vs[j][d];
                    m = s;
                } else {
                    const float p = __expf(s - m);
                    l += p;
#pragma unroll
                    for (int d = 0; d < 64; d++) o[d] += p * Vs[j][d];
                }
            }
        }
    }

    // ---- phase 2: global columns outside the band (|qi-kj| > WIN) ----
    __syncthreads();
#pragma unroll
    for (int i = 0; i < 32; i++) {
        const int kj = i * GSTRIDE;
        Ks[i][tid] = g_qkv[(size_t)kj * H3 + HID     + h * HD + tid];
        Vs[i][tid] = g_qkv[(size_t)kj * H3 + 2 * HID + h * HD + tid];
    }
    __syncthreads();

    for (int j = 0; j < 32; j++) {
        const int kj = j * GSTRIDE;
        int dist = qi - kj; if (dist < 0) dist = -dist;
        if (dist > WIN) {
            float s0 = 0.f, s1 = 0.f, s2 = 0.f, s3 = 0.f;
#pragma unroll
            for (int d = 0; d < 64; d += 4) {
                s0 += q[d + 0] * Ks[j][d + 0];
                s1 += q[d + 1] * Ks[j][d + 1];
                s2 += q[d + 2] * Ks[j][d + 2];
                s3 += q[d + 3] * Ks[j][d + 3];
            }
            const float s = (s0 + s1) + (s2 + s3);
            if (s > m) {
                const float c = __expf(m - s);
                l = l * c + 1.f;
#pragma unroll
                for (int d = 0; d < 64; d++) o[d] = o[d] * c + Vs[j][d];
                m = s;
            } else {
                const float p = __expf(s - m);
                l += p;
#pragma unroll
                for (int d = 0; d < 64; d++) o[d] += p * Vs[j][d];
            }
        }
    }

    const float inv = 1.f / l;
    float* orow = g_attn + (size_t)qi * HID + h * HD;
#pragma unroll
    for (int d = 0; d < 64; d++) orow[d] = o[d] * inv;
}

// ---------------- global rows: qi % 64 == 0 attend to ALL keys ----------------
// one block = one (head, global query); 64 threads split the 2048 keys
__global__ __launch_bounds__(64) void attn_global() {
    const int gq  = blockIdx.x;      // 0..31
    const int h   = blockIdx.y;      // 0..15
    const int tid = threadIdx.x;     // 0..63
    const int qi  = gq * 64;

    __shared__ float qsh[64];
    __shared__ float sm[64], sl[64];
    __shared__ float red[64][65];

    qsh[tid] = g_qkv[(size_t)qi * H3 + h * HD + tid] * 0.125f;
    __syncthreads();

    float m = -1e30f, l = 0.f, o[64];
#pragma unroll
    for (int d = 0; d < 64; d++) o[d] = 0.f;

    for (int kj = tid; kj < SEQ; kj += 64) {
        const float* kr = g_qkv + (size_t)kj * H3 + HID + h * HD;
        const float* vr = kr + HID;
        float s0 = 0.f, s1 = 0.f, s2 = 0.f, s3 = 0.f;
#pragma unroll
        for (int d = 0; d < 64; d += 4) {
            s0 += qsh[d + 0] * kr[d + 0];
            s1 += qsh[d + 1] * kr[d + 1];
            s2 += qsh[d + 2] * kr[d + 2];
            s3 += qsh[d + 3] * kr[d + 3];
        }
        const float s = (s0 + s1) + (s2 + s3);
        if (s > m) {
            const float c = __expf(m - s);
            l = l * c + 1.f;
#pragma unroll
            for (int d = 0; d < 64; d++) o[d] = o[d] * c + vr[d];
            m = s;
        } else {
            const float p = __expf(s - m);
            l += p;
#pragma unroll
            for (int d = 0; d < 64; d++) o[d] += p * vr[d];
        }
    }

    sm[tid] = m; sl[tid] = l;
    __syncthreads();

    float M = -1e30f;
    for (int t2 = 0; t2 < 64; t2++) M = fmaxf(M, sm[t2]);
    float L = 0.f;
    for (int t2 = 0; t2 < 64; t2++) L += sl[t2] * __expf(sm[t2] - M);

    const float w = __expf(m - M);
#pragma unroll
    for (int d = 0; d < 64; d++) red[tid][d] = o[d] * w;
    __syncthreads();

    float sum = 0.f;
    for (int t2 = 0; t2 < 64; t2++) sum += red[t2][tid];
    g_attn[(size_t)qi * HID + h * HD + tid] = sum / L;
}

// ---------------- launch ----------------
extern "C" void kernel_launch(void* const* d_in, const int* in_sizes, int n_in,
                              void* d_out, int out_size) {
    const float* x    = (const float*)d_in[0];   // [1, 2048, 1024]
    const float* Wqkv = (const float*)d_in[1];   // [3072, 1024]
    const float* Wout = (const float*)d_in[2];   // [1024, 1024]
    float* out = (float*)d_out;                  // [1, 2048, 1024]

    float* qkv = nullptr;
    float* attn = nullptr;
    cudaGetSymbolAddress((void**)&qkv,  g_qkv);
    cudaGetSymbolAddress((void**)&attn, g_attn);

    // 1) qkv = x @ Wqkv^T    [2048, 3072]
    {
        dim3 grid(H3 / 128, SEQ / 128);
        sgemm_tn<128, 128, 8><<<grid, 256>>>(x, Wqkv, qkv, SEQ, H3, HID);
    }
    // 2) sparse attention -> g_attn
    {
        dim3 grid(SEQ / 64, NHEAD);
        attn_local<<<grid, 64>>>();
        attn_global<<<grid, 64>>>();   // overwrites global rows
    }
    // 3) out = attn @ Wout^T   [2048, 1024]
    {
        dim3 grid(HID / 128, SEQ / 128);
        sgemm_tn<128, 128, 8><<<grid, 256>>>(attn, Wout, out, SEQ, HID, HID);
    }
}

// round 2
// speedup vs baseline: 1.2011x; 1.2011x over previous
#include <cuda_runtime.h>

// ---------------- problem constants ----------------
#define SEQ   2048
#define HID   1024
#define H3    3072
#define NHEAD 16
#define HD    64
#define WIN   128
#define GSTRIDE 64

// scratch (device globals — no cudaMalloc allowed)
__device__ float g_qkv[SEQ * H3];     // [S, 3H]: q | k | v
__device__ float g_attn[SEQ * HID];   // attention output [S, H]

// ---------------- SGEMM: C[M,N] = A[M,K] * B[N,K]^T (both K-major) ----------------
template<int BM, int BN, int BK>
__global__ __launch_bounds__(256) void sgemm_tn(const float* __restrict__ A,
                                                const float* __restrict__ B,
                                                float* __restrict__ C,
                                                int M, int N, int K) {
    __shared__ float As[BK][BM + 4];
    __shared__ float Bs[BK][BN + 4];

    const int t  = threadIdx.x;
    const int tx = t & 15;
    const int ty = t >> 4;

    const float* Ab = A + (size_t)(blockIdx.y * BM) * K;
    const float* Bb = B + (size_t)(blockIdx.x * BN) * K;

    float acc[8][8];
#pragma unroll
    for (int r = 0; r < 8; r++)
#pragma unroll
        for (int s = 0; s < 8; s++) acc[r][s] = 0.f;

    const int lrow = t >> 1;        // 0..127
    const int lcol = (t & 1) * 8;   // 0 or 8

    for (int k0 = 0; k0 < K; k0 += BK) {
        float4 a4 = *(const float4*)(Ab + (size_t)lrow * K + k0 + lcol);
        float4 a5 = *(const float4*)(Ab + (size_t)lrow * K + k0 + lcol + 4);
        float4 b4 = *(const float4*)(Bb + (size_t)lrow * K + k0 + lcol);
        float4 b5 = *(const float4*)(Bb + (size_t)lrow * K + k0 + lcol + 4);
        As[lcol + 0][lrow] = a4.x; As[lcol + 1][lrow] = a4.y;
        As[lcol + 2][lrow] = a4.z; As[lcol + 3][lrow] = a4.w;
        As[lcol + 4][lrow] = a5.x; As[lcol + 5][lrow] = a5.y;
        As[lcol + 6][lrow] = a5.z; As[lcol + 7][lrow] = a5.w;
        Bs[lcol + 0][lrow] = b4.x; Bs[lcol + 1][lrow] = b4.y;
        Bs[lcol + 2][lrow] = b4.z; Bs[lcol + 3][lrow] = b4.w;
        Bs[lcol + 4][lrow] = b5.x; Bs[lcol + 5][lrow] = b5.y;
        Bs[lcol + 6][lrow] = b5.z; Bs[lcol + 7][lrow] = b5.w;
        __syncthreads();

#pragma unroll
        for (int kk = 0; kk < BK; kk++) {
            float ar[8], br[8];
#pragma unroll
            for (int r = 0; r < 8; r++) ar[r] = As[kk][ty + 16 * r];
#pragma unroll
            for (int s = 0; s < 8; s++) br[s] = Bs[kk][tx + 16 * s];
#pragma unroll
            for (int r = 0; r < 8; r++)
#pragma unroll
                for (int s = 0; s < 8; s++) acc[r][s] += ar[r] * br[s];
        }
        __syncthreads();
    }

#pragma unroll
    for (int r = 0; r < 8; r++) {
        const int m = blockIdx.y * BM + ty + 16 * r;
#pragma unroll
        for (int s = 0; s < 8; s++) {
            const int n = blockIdx.x * BN + tx + 16 * s;
            C[(size_t)m * N + n] = acc[r][s];
        }
    }
}

// ================= local (band + global-col) attention =================
// 256 threads: 64 queries x 4 "parts"; part p owns dims [16p, 16p+16)
__global__ __launch_bounds__(256) void attn_local() {
    const int qt   = blockIdx.x;      // 0..31
    const int h    = blockIdx.y;      // 0..15
    const int tid  = threadIdx.x;
    const int ql   = tid >> 2;        // 0..63
    const int part = tid & 3;         // 0..3
    const int q0   = qt * 64;
    const int qi   = q0 + ql;
    const int db   = part * 16;

    __shared__ float Ks[32][68];
    __shared__ float Vs[32][68];

    float q[16], o[16];
    {
        const float* qrow = g_qkv + (size_t)qi * H3 + h * HD + db;
#pragma unroll
        for (int i = 0; i < 16; i += 4) {
            float4 v = *(const float4*)(qrow + i);
            q[i] = v.x * 0.125f; q[i+1] = v.y * 0.125f;
            q[i+2] = v.z * 0.125f; q[i+3] = v.w * 0.125f;
            o[i] = 0.f; o[i+1] = 0.f; o[i+2] = 0.f; o[i+3] = 0.f;
        }
    }
    float m = -1e30f, l = 0.f;

    const int kstart = (q0 - WIN) > 0 ? (q0 - WIN) : 0;
    const int kend   = (q0 + 64 + WIN) < SEQ ? (q0 + 64 + WIN) : SEQ;

    // ---- phase 1: band tiles ----
    for (int kt = kstart; kt < kend; kt += 32) {
        __syncthreads();
        {
            int idx = tid;
#pragma unroll
            for (int rep = 0; rep < 2; rep++, idx += 256) {
                int r = idx >> 4, c = (idx & 15) << 2;
                const float* src = g_qkv + (size_t)(kt + r) * H3 + HID + h * HD + c;
                *(float4*)&Ks[r][c] = *(const float4*)src;
                *(float4*)&Vs[r][c] = *(const float4*)(src + HID);
            }
        }
        __syncthreads();

#pragma unroll 4
        for (int j = 0; j < 32; j++) {
            const int kj = kt + j;
            float s = 0.f;
#pragma unroll
            for (int i = 0; i < 16; i += 4) {
                float4 kv = *(const float4*)&Ks[j][db + i];
                s += q[i] * kv.x + q[i+1] * kv.y + q[i+2] * kv.z + q[i+3] * kv.w;
            }
            s += __shfl_xor_sync(0xffffffffu, s, 1);
            s += __shfl_xor_sync(0xffffffffu, s, 2);
            int dist = qi - kj; if (dist < 0) dist = -dist;
            if (dist <= WIN) {
                if (s > m) {
                    const float c = __expf(m - s);
                    l = l * c + 1.f;
#pragma unroll
                    for (int i = 0; i < 16; i += 4) {
                        float4 vv = *(const float4*)&Vs[j][db + i];
                        o[i]   = o[i]   * c + vv.x; o[i+1] = o[i+1] * c + vv.y;
                        o[i+2] = o[i+2] * c + vv.z; o[i+3] = o[i+3] * c + vv.w;
                    }
                    m = s;
                } else {
                    const float p = __expf(s - m);
                    l += p;
#pragma unroll
                    for (int i = 0; i < 16; i += 4) {
                        float4 vv = *(const float4*)&Vs[j][db + i];
                        o[i]   += p * vv.x; o[i+1] += p * vv.y;
                        o[i+2] += p * vv.z; o[i+3] += p * vv.w;
                    }
                }
            }
        }
    }

    // ---- phase 2: global columns outside the band ----
    __syncthreads();
    {
        int idx = tid;
#pragma unroll
        for (int rep = 0; rep < 2; rep++, idx += 256) {
            int r = idx >> 4, c = (idx & 15) << 2;
            const float* src = g_qkv + (size_t)(r * GSTRIDE) * H3 + HID + h * HD + c;
            *(float4*)&Ks[r][c] = *(const float4*)src;
            *(float4*)&Vs[r][c] = *(const float4*)(src + HID);
        }
    }
    __syncthreads();

    for (int j = 0; j < 32; j++) {
        const int kj = j * GSTRIDE;
        float s = 0.f;
#pragma unroll
        for (int i = 0; i < 16; i += 4) {
            float4 kv = *(const float4*)&Ks[j][db + i];
            s += q[i] * kv.x + q[i+1] * kv.y + q[i+2] * kv.z + q[i+3] * kv.w;
        }
        s += __shfl_xor_sync(0xffffffffu, s, 1);
        s += __shfl_xor_sync(0xffffffffu, s, 2);
        int dist = qi - kj; if (dist < 0) dist = -dist;
        if (dist > WIN) {
            if (s > m) {
                const float c = __expf(m - s);
                l = l * c + 1.f;
#pragma unroll
                for (int i = 0; i < 16; i += 4) {
                    float4 vv = *(const float4*)&Vs[j][db + i];
                    o[i]   = o[i]   * c + vv.x; o[i+1] = o[i+1] * c + vv.y;
                    o[i+2] = o[i+2] * c + vv.z; o[i+3] = o[i+3] * c + vv.w;
                }
                m = s;
            } else {
                const float p = __expf(s - m);
                l += p;
#pragma unroll
                for (int i = 0; i < 16; i += 4) {
                    float4 vv = *(const float4*)&Vs[j][db + i];
                    o[i]   += p * vv.x; o[i+1] += p * vv.y;
                    o[i+2] += p * vv.z; o[i+3] += p * vv.w;
                }
            }
        }
    }

    const float inv = 1.f / l;
    float* orow = g_attn + (size_t)qi * HID + h * HD + db;
#pragma unroll
    for (int i = 0; i < 16; i += 4) {
        float4 v;
        v.x = o[i] * inv; v.y = o[i+1] * inv; v.z = o[i+2] * inv; v.w = o[i+3] * inv;
        *(float4*)(orow + i) = v;
    }
}

// ================= global rows: qi % 64 == 0 attend to ALL keys =================
// block = (8 global queries, 1 head); 256 threads = 8 ql x 8 klane x 4 part
__global__ __launch_bounds__(256) void attn_global() {
    const int gq8 = blockIdx.x;       // 0..3
    const int h   = blockIdx.y;       // 0..15
    const int tid = threadIdx.x;
    const int ql    = tid >> 5;       // 0..7  (one warp per query)
    const int klane = (tid >> 2) & 7; // 0..7
    const int part  = tid & 3;        // 0..3
    const int qi    = (gq8 * 8 + ql) * 64;
    const int db    = part * 16;

    __shared__ float Ks[32][68];
    __shared__ float Vs[32][68];
    __shared__ float sm[8][8];
    __shared__ float sl[8][8];
    __shared__ float red[8][8][64];   // [ql][klane][dim]

    float q[16], o[16];
    {
        const float* qrow = g_qkv + (size_t)qi * H3 + h * HD + db;
#pragma unroll
        for (int i = 0; i < 16; i += 4) {
            float4 v = *(const float4*)(qrow + i);
            q[i] = v.x * 0.125f; q[i+1] = v.y * 0.125f;
            q[i+2] = v.z * 0.125f; q[i+3] = v.w * 0.125f;
            o[i] = 0.f; o[i+1] = 0.f; o[i+2] = 0.f; o[i+3] = 0.f;
        }
    }
    float m = -1e30f, l = 0.f;

    for (int kt = 0; kt < SEQ; kt += 32) {
        __syncthreads();
        {
            int idx = tid;
#pragma unroll
            for (int rep = 0; rep < 2; rep++, idx += 256) {
                int r = idx >> 4, c = (idx & 15) << 2;
                const float* src = g_qkv + (size_t)(kt + r) * H3 + HID + h * HD + c;
                *(float4*)&Ks[r][c] = *(const float4*)src;
                *(float4*)&Vs[r][c] = *(const float4*)(src + HID);
            }
        }
        __syncthreads();

#pragma unroll
        for (int w = 0; w < 4; w++) {
            const int j = klane + 8 * w;
            float s = 0.f;
#pragma unroll
            for (int i = 0; i < 16; i += 4) {
                float4 kv = *(const float4*)&Ks[j][db + i];
                s += q[i] * kv.x + q[i+1] * kv.y + q[i+2] * kv.z + q[i+3] * kv.w;
            }
            s += __shfl_xor_sync(0xffffffffu, s, 1);
            s += __shfl_xor_sync(0xffffffffu, s, 2);
            if (s > m) {
                const float c = __expf(m - s);
                l = l * c + 1.f;
#pragma unroll
                for (int i = 0; i < 16; i += 4) {
                    float4 vv = *(const float4*)&Vs[j][db + i];
                    o[i]   = o[i]   * c + vv.x; o[i+1] = o[i+1] * c + vv.y;
                    o[i+2] = o[i+2] * c + vv.z; o[i+3] = o[i+3] * c + vv.w;
                }
                m = s;
            } else {
                const float p = __expf(s - m);
                l += p;
#pragma unroll
                for (int i = 0; i < 16; i += 4) {
                    float4 vv = *(const float4*)&Vs[j][db + i];
                    o[i]   += p * vv.x; o[i+1] += p * vv.y;
                    o[i+2] += p * vv.z; o[i+3] += p * vv.w;
                }
            }
        }
    }

    // ---- split-softmax merge across the 8 klanes of each query ----
    __syncthreads();
    if (part == 0) { sm[ql][klane] = m; sl[ql][klane] = l; }
    __syncthreads();

    float M = -1e30f;
#pragma unroll
    for (int t2 = 0; t2 < 8; t2++) M = fmaxf(M, sm[ql][t2]);
    const float w = __expf(m - M);
#pragma unroll
    for (int i = 0; i < 16; i++) red[ql][klane][db + i] = o[i] * w;
    __syncthreads();

    for (int idx = tid; idx < 512; idx += 256) {
        const int ql2 = idx >> 6;
        const int d   = idx & 63;
        float M2 = -1e30f;
#pragma unroll
        for (int t2 = 0; t2 < 8; t2++) M2 = fmaxf(M2, sm[ql2][t2]);
        float L2 = 0.f;
#pragma unroll
        for (int t2 = 0; t2 < 8; t2++) L2 += sl[ql2][t2] * __expf(sm[ql2][t2] - M2);
        float sum = 0.f;
#pragma unroll
        for (int t2 = 0; t2 < 8; t2++) sum += red[ql2][t2][d];
        const int qi2 = (gq8 * 8 + ql2) * 64;
        g_attn[(size_t)qi2 * HID + h * HD + d] = sum / L2;
    }
}

// ---------------- launch ----------------
extern "C" void kernel_launch(void* const* d_in, const int* in_sizes, int n_in,
                              void* d_out, int out_size) {
    const float* x    = (const float*)d_in[0];   // [1, 2048, 1024]
    const float* Wqkv = (const float*)d_in[1];   // [3072, 1024]
    const float* Wout = (const float*)d_in[2];   // [1024, 1024]
    float* out = (float*)d_out;                  // [1, 2048, 1024]

    float* qkv = nullptr;
    float* attn = nullptr;
    cudaGetSymbolAddress((void**)&qkv,  g_qkv);
    cudaGetSymbolAddress((void**)&attn, g_attn);

    // 1) qkv = x @ Wqkv^T    [2048, 3072]
    {
        dim3 grid(H3 / 128, SEQ / 128);
        sgemm_tn<128, 128, 16><<<grid, 256>>>(x, Wqkv, qkv, SEQ, H3, HID);
    }
    // 2) sparse attention -> g_attn
    {
        dim3 gl(SEQ / 64, NHEAD);
        attn_local<<<gl, 256>>>();
        dim3 gg(4, NHEAD);
        attn_global<<<gg, 256>>>();   // overwrites global rows
    }
    // 3) out = attn @ Wout^T   [2048, 1024]
    {
        dim3 grid(HID / 128, SEQ / 128);
        sgemm_tn<128, 128, 16><<<grid, 256>>>(attn, Wout, out, SEQ, HID, HID);
    }
}

// round 3
// speedup vs baseline: 1.2226x; 1.0179x over previous
#include <cuda_runtime.h>

// ---------------- problem constants ----------------
#define SEQ   2048
#define HID   1024
#define H3    3072
#define NHEAD 16
#define HD    64
#define WIN   128
#define GSTRIDE 64

typedef unsigned long long u64;

// ---------------- packed f32x2 helpers (sm_103a FFMA2 path) ----------------
__device__ __forceinline__ u64 fma2(u64 a, u64 b, u64 c) {
    u64 d; asm("fma.rn.f32x2 %0, %1, %2, %3;" : "=l"(d) : "l"(a), "l"(b), "l"(c)); return d;
}
__device__ __forceinline__ u64 mul2(u64 a, u64 b) {
    u64 d; asm("mul.rn.f32x2 %0, %1, %2;" : "=l"(d) : "l"(a), "l"(b)); return d;
}
__device__ __forceinline__ u64 pack2(float lo, float hi) {
    u64 d; asm("mov.b64 %0, {%1, %2};" : "=l"(d) : "f"(lo), "f"(hi)); return d;
}
__device__ __forceinline__ u64 dup2(float x) { return pack2(x, x); }
__device__ __forceinline__ void unpack2(u64 v, float& lo, float& hi) {
    asm("mov.b64 {%0, %1}, %2;" : "=f"(lo), "=f"(hi) : "l"(v));
}

// scratch (device globals — no cudaMalloc allowed)
__device__ float g_qkv[SEQ * H3];     // [S, 3H]: q | k | v
__device__ float g_attn[SEQ * HID];   // attention output [S, H]

// ---------------- SGEMM v3: C[M,N] = A[M,K] * B[N,K]^T via FFMA2 ----------------
// BM=BN=128, 256 threads, thread tile 8x8 (contiguous m and n), acc packed f32x2
template<int BK>
__global__ __launch_bounds__(256) void sgemm2(const float* __restrict__ A,
                                              const float* __restrict__ B,
                                              float* __restrict__ C,
                                              int M, int N, int K) {
    __shared__ float As[BK][128 + 4];
    __shared__ float Bs[BK][128 + 4];

    const int t  = threadIdx.x;
    const int tx = t & 15;   // n-tile: cols tx*8 .. tx*8+7
    const int ty = t >> 4;   // m-tile: rows ty*8 .. ty*8+7

    const float* Ab = A + (size_t)(blockIdx.y * 128) * K;
    const float* Bb = B + (size_t)(blockIdx.x * 128) * K;

    u64 acc[8][4];
#pragma unroll
    for (int r = 0; r < 8; r++)
#pragma unroll
        for (int p = 0; p < 4; p++) acc[r][p] = 0ull;

    const int lrow = t >> 1;        // 0..127
    const int lcol = (t & 1) * 8;   // 0 or 8

    for (int k0 = 0; k0 < K; k0 += BK) {
        float4 a4 = *(const float4*)(Ab + (size_t)lrow * K + k0 + lcol);
        float4 a5 = *(const float4*)(Ab + (size_t)lrow * K + k0 + lcol + 4);
        float4 b4 = *(const float4*)(Bb + (size_t)lrow * K + k0 + lcol);
        float4 b5 = *(const float4*)(Bb + (size_t)lrow * K + k0 + lcol + 4);
        As[lcol + 0][lrow] = a4.x; As[lcol + 1][lrow] = a4.y;
        As[lcol + 2][lrow] = a4.z; As[lcol + 3][lrow] = a4.w;
        As[lcol + 4][lrow] = a5.x; As[lcol + 5][lrow] = a5.y;
        As[lcol + 6][lrow] = a5.z; As[lcol + 7][lrow] = a5.w;
        Bs[lcol + 0][lrow] = b4.x; Bs[lcol + 1][lrow] = b4.y;
        Bs[lcol + 2][lrow] = b4.z; Bs[lcol + 3][lrow] = b4.w;
        Bs[lcol + 4][lrow] = b5.x; Bs[lcol + 5][lrow] = b5.y;
        Bs[lcol + 6][lrow] = b5.z; Bs[lcol + 7][lrow] = b5.w;
        __syncthreads();

#pragma unroll
        for (int kk = 0; kk < BK; kk++) {
            float4 a0 = *(const float4*)&As[kk][ty * 8];
            float4 a1 = *(const float4*)&As[kk][ty * 8 + 4];
            float4 b0 = *(const float4*)&Bs[kk][tx * 8];
            float4 b1 = *(const float4*)&Bs[kk][tx * 8 + 4];
            u64 br[4];
            br[0] = pack2(b0.x, b0.y); br[1] = pack2(b0.z, b0.w);
            br[2] = pack2(b1.x, b1.y); br[3] = pack2(b1.z, b1.w);
            u64 ar[8];
            ar[0] = dup2(a0.x); ar[1] = dup2(a0.y); ar[2] = dup2(a0.z); ar[3] = dup2(a0.w);
            ar[4] = dup2(a1.x); ar[5] = dup2(a1.y); ar[6] = dup2(a1.z); ar[7] = dup2(a1.w);
#pragma unroll
            for (int r = 0; r < 8; r++)
#pragma unroll
                for (int p = 0; p < 4; p++) acc[r][p] = fma2(ar[r], br[p], acc[r][p]);
        }
        __syncthreads();
    }

#pragma unroll
    for (int r = 0; r < 8; r++) {
        const int m = blockIdx.y * 128 + ty * 8 + r;
        float o0, o1, o2, o3, o4, o5, o6, o7;
        unpack2(acc[r][0], o0, o1); unpack2(acc[r][1], o2, o3);
        unpack2(acc[r][2], o4, o5); unpack2(acc[r][3], o6, o7);
        float* crow = C + (size_t)m * N + blockIdx.x * 128 + tx * 8;
        float4 v0; v0.x = o0; v0.y = o1; v0.z = o2; v0.w = o3;
        float4 v1; v1.x = o4; v1.y = o5; v1.z = o6; v1.w = o7;
        *(float4*)crow = v0;
        *(float4*)(crow + 4) = v1;
    }
}

// ================= local (band + global-col) attention =================
// 256 threads: 64 queries x 4 "parts"; part p owns dims [16p, 16p+16)
__global__ __launch_bounds__(256) void attn_local() {
    const int qt   = blockIdx.x;      // 0..31
    const int h    = blockIdx.y;      // 0..15
    const int tid  = threadIdx.x;
    const int ql   = tid >> 2;        // 0..63
    const int part = tid & 3;         // 0..3
    const int q0   = qt * 64;
    const int qi   = q0 + ql;
    const int db   = part * 16;

    __shared__ float Ks[32][68];
    __shared__ float Vs[32][68];

    u64 q2[8], o2[8];
    {
        const float* qrow = g_qkv + (size_t)qi * H3 + h * HD + db;
#pragma unroll
        for (int i = 0; i < 4; i++) {
            float4 v = *(const float4*)(qrow + i * 4);
            q2[2*i]   = pack2(v.x * 0.125f, v.y * 0.125f);
            q2[2*i+1] = pack2(v.z * 0.125f, v.w * 0.125f);
            o2[2*i] = 0ull; o2[2*i+1] = 0ull;
        }
    }
    float m = -1e30f, l = 0.f;

    const int kstart = (q0 - WIN) > 0 ? (q0 - WIN) : 0;
    const int kend   = (q0 + 64 + WIN) < SEQ ? (q0 + 64 + WIN) : SEQ;

    // ---- phase 1: band tiles ----
    for (int kt = kstart; kt < kend; kt += 32) {
        __syncthreads();
        {
            int idx = tid;
#pragma unroll
            for (int rep = 0; rep < 2; rep++, idx += 256) {
                int r = idx >> 4, c = (idx & 15) << 2;
                const float* src = g_qkv + (size_t)(kt + r) * H3 + HID + h * HD + c;
                *(float4*)&Ks[r][c] = *(const float4*)src;
                *(float4*)&Vs[r][c] = *(const float4*)(src + HID);
            }
        }
        __syncthreads();

#pragma unroll 4
        for (int j = 0; j < 32; j++) {
            const int kj = kt + j;
            u64 s2 = 0ull;
#pragma unroll
            for (int i = 0; i < 4; i++) {
                float4 kv = *(const float4*)&Ks[j][db + i * 4];
                s2 = fma2(q2[2*i],   pack2(kv.x, kv.y), s2);
                s2 = fma2(q2[2*i+1], pack2(kv.z, kv.w), s2);
            }
            float slo, shi; unpack2(s2, slo, shi);
            float s = slo + shi;
            s += __shfl_xor_sync(0xffffffffu, s, 1);
            s += __shfl_xor_sync(0xffffffffu, s, 2);

            int dist = qi - kj; if (dist < 0) dist = -dist;
            const bool ok = (dist <= WIN);
            const float mn = ok ? fmaxf(m, s) : m;
            const float c  = __expf(m - mn);
            const float p  = ok ? __expf(s - mn) : 0.f;
            l = l * c + p;
            m = mn;
            const u64 c2 = dup2(c), p2 = dup2(p);
#pragma unroll
            for (int i = 0; i < 4; i++) {
                float4 vv = *(const float4*)&Vs[j][db + i * 4];
                u64 va = pack2(vv.x, vv.y), vb = pack2(vv.z, vv.w);
                o2[2*i]   = fma2(o2[2*i],   c2, mul2(p2, va));
                o2[2*i+1] = fma2(o2[2*i+1], c2, mul2(p2, vb));
            }
        }
    }

    // ---- phase 2: global columns outside the band ----
    __syncthreads();
    {
        int idx = tid;
#pragma unroll
        for (int rep = 0; rep < 2; rep++, idx += 256) {
            int r = idx >> 4, c = (idx & 15) << 2;
            const float* src = g_qkv + (size_t)(r * GSTRIDE) * H3 + HID + h * HD + c;
            *(float4*)&Ks[r][c] = *(const float4*)src;
            *(float4*)&Vs[r][c] = *(const float4*)(src + HID);
        }
    }
    __syncthreads();

    for (int j = 0; j < 32; j++) {
        const int kj = j * GSTRIDE;
        u64 s2 = 0ull;
#pragma unroll
        for (int i = 0; i < 4; i++) {
            float4 kv = *(const float4*)&Ks[j][db + i * 4];
            s2 = fma2(q2[2*i],   pack2(kv.x, kv.y), s2);
            s2 = fma2(q2[2*i+1], pack2(kv.z, kv.w), s2);
        }
        float slo, shi; unpack2(s2, slo, shi);
        float s = slo + shi;
        s += __shfl_xor_sync(0xffffffffu, s, 1);
        s += __shfl_xor_sync(0xffffffffu, s, 2);

        int dist = qi - kj; if (dist < 0) dist = -dist;
        const bool ok = (dist > WIN);
        const float mn = ok ? fmaxf(m, s) : m;
        const float c  = __expf(m - mn);
        const float p  = ok ? __expf(s - mn) : 0.f;
        l = l * c + p;
        m = mn;
        const u64 c2 = dup2(c), p2 = dup2(p);
#pragma unroll
        for (int i = 0; i < 4; i++) {
            float4 vv = *(const float4*)&Vs[j][db + i * 4];
            u64 va = pack2(vv.x, vv.y), vb = pack2(vv.z, vv.w);
            o2[2*i]   = fma2(o2[2*i],   c2, mul2(p2, va));
            o2[2*i+1] = fma2(o2[2*i+1], c2, mul2(p2, vb));
        }
    }

    const float inv = 1.f / l;
    float* orow = g_attn + (size_t)qi * HID + h * HD + db;
#pragma unroll
    for (int i = 0; i < 4; i++) {
        float a, b, c, d;
        unpack2(o2[2*i], a, b); unpack2(o2[2*i+1], c, d);
        float4 v; v.x = a * inv; v.y = b * inv; v.z = c * inv; v.w = d * inv;
        *(float4*)(orow + i * 4) = v;
    }
}

// ================= global rows: qi % 64 == 0 attend to ALL keys =================
// block = (8 global queries, 1 head); 256 threads = 8 ql x 8 klane x 4 part
__global__ __launch_bounds__(256) void attn_global() {
    const int gq8 = blockIdx.x;       // 0..3
    const int h   = blockIdx.y;       // 0..15
    const int tid = threadIdx.x;
    const int ql    = tid >> 5;       // 0..7  (one warp per query)
    const int klane = (tid >> 2) & 7; // 0..7
    const int part  = tid & 3;        // 0..3
    const int qi    = (gq8 * 8 + ql) * 64;
    const int db    = part * 16;

    __shared__ float Ks[32][68];
    __shared__ float Vs[32][68];
    __shared__ float sm[8][8];
    __shared__ float sl[8][8];
    __shared__ float red[8][8][64];   // [ql][klane][dim]

    u64 q2[8], o2[8];
    {
        const float* qrow = g_qkv + (size_t)qi * H3 + h * HD + db;
#pragma unroll
        for (int i = 0; i < 4; i++) {
            float4 v = *(const float4*)(qrow + i * 4);
            q2[2*i]   = pack2(v.x * 0.125f, v.y * 0.125f);
            q2[2*i+1] = pack2(v.z * 0.125f, v.w * 0.125f);
            o2[2*i] = 0ull; o2[2*i+1] = 0ull;
        }
    }
    float m = -1e30f, l = 0.f;

    for (int kt = 0; kt < SEQ; kt += 32) {
        __syncthreads();
        {
            int idx = tid;
#pragma unroll
            for (int rep = 0; rep < 2; rep++, idx += 256) {
                int r = idx >> 4, c = (idx & 15) << 2;
                const float* src = g_qkv + (size_t)(kt + r) * H3 + HID + h * HD + c;
                *(float4*)&Ks[r][c] = *(const float4*)src;
                *(float4*)&Vs[r][c] = *(const float4*)(src + HID);
            }
        }
        __syncthreads();

#pragma unroll
        for (int w = 0; w < 4; w++) {
            const int j = klane + 8 * w;
            u64 s2 = 0ull;
#pragma unroll
            for (int i = 0; i < 4; i++) {
                float4 kv = *(const float4*)&Ks[j][db + i * 4];
                s2 = fma2(q2[2*i],   pack2(kv.x, kv.y), s2);
                s2 = fma2(q2[2*i+1], pack2(kv.z, kv.w), s2);
            }
            float slo, shi; unpack2(s2, slo, shi);
            float s = slo + shi;
            s += __shfl_xor_sync(0xffffffffu, s, 1);
            s += __shfl_xor_sync(0xffffffffu, s, 2);

            const float mn = fmaxf(m, s);
            const float c  = __expf(m - mn);
            const float p  = __expf(s - mn);
            l = l * c + p;
            m = mn;
            const u64 c2 = dup2(c), p2 = dup2(p);
#pragma unroll
            for (int i = 0; i < 4; i++) {
                float4 vv = *(const float4*)&Vs[j][db + i * 4];
                u64 va = pack2(vv.x, vv.y), vb = pack2(vv.z, vv.w);
                o2[2*i]   = fma2(o2[2*i],   c2, mul2(p2, va));
                o2[2*i+1] = fma2(o2[2*i+1], c2, mul2(p2, vb));
            }
        }
    }

    // ---- split-softmax merge across the 8 klanes of each query ----
    __syncthreads();
    if (part == 0) { sm[ql][klane] = m; sl[ql][klane] = l; }
    __syncthreads();

    float M = -1e30f;
#pragma unroll
    for (int t2 = 0; t2 < 8; t2++) M = fmaxf(M, sm[ql][t2]);
    const float w = __expf(m - M);
#pragma unroll
    for (int i = 0; i < 8; i++) {
        float a, b;
        unpack2(o2[i], a, b);
        red[ql][klane][db + 2*i]     = a * w;
        red[ql][klane][db + 2*i + 1] = b * w;
    }
    __syncthreads();

    for (int idx = tid; idx < 512; idx += 256) {
        const int ql2 = idx >> 6;
        const int d   = idx & 63;
        float M2 = -1e30f;
#pragma unroll
        for (int t2 = 0; t2 < 8; t2++) M2 = fmaxf(M2, sm[ql2][t2]);
        float L2 = 0.f;
#pragma unroll
        for (int t2 = 0; t2 < 8; t2++) L2 += sl[ql2][t2] * __expf(sm[ql2][t2] - M2);
        float sum = 0.f;
#pragma unroll
        for (int t2 = 0; t2 < 8; t2++) sum += red[ql2][t2][d];
        const int qi2 = (gq8 * 8 + ql2) * 64;
        g_attn[(size_t)qi2 * HID + h * HD + d] = sum / L2;
    }
}

// ---------------- launch ----------------
extern "C" void kernel_launch(void* const* d_in, const int* in_sizes, int n_in,
                              void* d_out, int out_size) {
    const float* x    = (const float*)d_in[0];   // [1, 2048, 1024]
    const float* Wqkv = (const float*)d_in[1];   // [3072, 1024]
    const float* Wout = (const float*)d_in[2];   // [1024, 1024]
    float* out = (float*)d_out;                  // [1, 2048, 1024]

    float* qkv = nullptr;
    float* attn = nullptr;
    cudaGetSymbolAddress((void**)&qkv,  g_qkv);
    cudaGetSymbolAddress((void**)&attn, g_attn);

    // 1) qkv = x @ Wqkv^T    [2048, 3072]
    {
        dim3 grid(H3 / 128, SEQ / 128);
        sgemm2<16><<<grid, 256>>>(x, Wqkv, qkv, SEQ, H3, HID);
    }
    // 2) sparse attention -> g_attn
    {
        dim3 gl(SEQ / 64, NHEAD);
        attn_local<<<gl, 256>>>();
        dim3 gg(4, NHEAD);
        attn_global<<<gg, 256>>>();   // overwrites global rows
    }
    // 3) out = attn @ Wout^T   [2048, 1024]
    {
        dim3 grid(HID / 128, SEQ / 128);
        sgemm2<16><<<grid, 256>>>(attn, Wout, out, SEQ, HID, HID);
    }
}

// round 5
// speedup vs baseline: 1.5719x; 1.2856x over previous
#include <cuda_runtime.h>
#include <cuda_bf16.h>
#include <cstdint>

// ---------------- problem constants ----------------
#define SEQ   2048
#define HID   1024
#define H3    3072
#define NHEAD 16
#define HD    64
#define WIN   128
#define GSTRIDE 64

typedef unsigned long long u64;

// ---------------- packed f32x2 helpers (attention kernels) ----------------
__device__ __forceinline__ u64 fma2(u64 a, u64 b, u64 c) {
    u64 d; asm("fma.rn.f32x2 %0, %1, %2, %3;" : "=l"(d) : "l"(a), "l"(b), "l"(c)); return d;
}
__device__ __forceinline__ u64 mul2(u64 a, u64 b) {
    u64 d; asm("mul.rn.f32x2 %0, %1, %2;" : "=l"(d) : "l"(a), "l"(b)); return d;
}
__device__ __forceinline__ u64 pack2(float lo, float hi) {
    u64 d; asm("mov.b64 %0, {%1, %2};" : "=l"(d) : "f"(lo), "f"(hi)); return d;
}
__device__ __forceinline__ u64 dup2(float x) { return pack2(x, x); }
__device__ __forceinline__ void unpack2(u64 v, float& lo, float& hi) {
    asm("mov.b64 {%0, %1}, %2;" : "=f"(lo), "=f"(hi) : "l"(v));
}

// ---------------- warp MMA: m16n8k16 bf16 (baseline PTX, valid on sm_103) ----------------
__device__ __forceinline__ void mma16816(float& c0, float& c1, float& c2, float& c3,
                                         uint32_t a0, uint32_t a1, uint32_t a2, uint32_t a3,
                                         uint32_t b0, uint32_t b1) {
    asm volatile(
        "mma.sync.aligned.m16n8k16.row.col.f32.bf16.bf16.f32 "
        "{%0,%1,%2,%3}, {%4,%5,%6,%7}, {%8,%9}, {%0,%1,%2,%3};"
        : "+f"(c0), "+f"(c1), "+f"(c2), "+f"(c3)
        : "r"(a0), "r"(a1), "r"(a2), "r"(a3), "r"(b0), "r"(b1));
}

// ---------------- scratch (device globals) ----------------
__device__ float g_qkv[SEQ * H3];
__device__ float g_attn[SEQ * HID];
__device__ __nv_bfloat16 g_x0[SEQ * HID],  g_x1[SEQ * HID];
__device__ __nv_bfloat16 g_wq0[H3 * HID],  g_wq1[H3 * HID];
__device__ __nv_bfloat16 g_a0[SEQ * HID],  g_a1[SEQ * HID];
__device__ __nv_bfloat16 g_wo0[HID * HID], g_wo1[HID * HID];

// ---------------- fp32 -> (bf16 hi, bf16 lo) split ----------------
__global__ __launch_bounds__(256) void split_bf16(const float* __restrict__ in,
                                                  __nv_bfloat16* __restrict__ hi,
                                                  __nv_bfloat16* __restrict__ lo,
                                                  int n4) {
    int i = blockIdx.x * blockDim.x + threadIdx.x;
    if (i >= n4) return;
    float4 v = ((const float4*)in)[i];
    __nv_bfloat16 h0 = __float2bfloat16(v.x), h1 = __float2bfloat16(v.y);
    __nv_bfloat16 h2 = __float2bfloat16(v.z), h3 = __float2bfloat16(v.w);
    __nv_bfloat16 l0 = __float2bfloat16(v.x - __bfloat162float(h0));
    __nv_bfloat16 l1 = __float2bfloat16(v.y - __bfloat162float(h1));
    __nv_bfloat16 l2 = __float2bfloat16(v.z - __bfloat162float(h2));
    __nv_bfloat16 l3 = __float2bfloat16(v.w - __bfloat162float(h3));
    __nv_bfloat162* hp = (__nv_bfloat162*)hi;
    __nv_bfloat162* lp = (__nv_bfloat162*)lo;
    hp[2 * i]     = __nv_bfloat162(h0, h1);
    hp[2 * i + 1] = __nv_bfloat162(h2, h3);
    lp[2 * i]     = __nv_bfloat162(l0, l1);
    lp[2 * i + 1] = __nv_bfloat162(l2, l3);
}

// ---------------- tensor-core GEMM: C[M,N] = A[M,K] @ B[N,K]^T ----------------
// A,B as bf16 (hi,lo); C fp32 with 3-term split accumulation.
// 128x128 tile, 8 warps = 2(M) x 4(N), warp tile 64x32 = 4x4 m16n8k16 frags.
#define SSTR 40   // smem row stride (bf16 elems); bank-conflict-free fragment loads

__global__ __launch_bounds__(256) void gemm_mma(const __nv_bfloat16* __restrict__ A0g,
                                                const __nv_bfloat16* __restrict__ A1g,
                                                const __nv_bfloat16* __restrict__ B0g,
                                                const __nv_bfloat16* __restrict__ B1g,
                                                float* __restrict__ C,
                                                int M, int N, int K) {
    __shared__ __nv_bfloat16 As0[128][SSTR];
    __shared__ __nv_bfloat16 As1[128][SSTR];
    __shared__ __nv_bfloat16 Bs0[128][SSTR];
    __shared__ __nv_bfloat16 Bs1[128][SSTR];

    const int tid = threadIdx.x;
    const int wid = tid >> 5;
    const int lane = tid & 31;
    const int g = lane >> 2;     // 0..7
    const int t = lane & 3;      // 0..3
    const int warp_m = (wid & 1) * 64;   // 0 or 64
    const int warp_n = (wid >> 1) * 32;  // 0,32,64,96

    const int tile_m = blockIdx.y * 128;
    const int tile_n = blockIdx.x * 128;

    float acc[4][4][4];
#pragma unroll
    for (int im = 0; im < 4; im++)
#pragma unroll
        for (int jn = 0; jn < 4; jn++)
#pragma unroll
            for (int c = 0; c < 4; c++) acc[im][jn][c] = 0.f;

    for (int k0 = 0; k0 < K; k0 += 32) {
        // ---- stage 4 buffers: 128 rows x 32 bf16 each ----
#pragma unroll
        for (int rep = 0; rep < 2; rep++) {
            const int idx = tid + 256 * rep;       // 0..511
            const int row = idx >> 2;
            const int c8  = (idx & 3) * 8;
            const size_t goA = (size_t)(tile_m + row) * K + k0 + c8;
            const size_t goB = (size_t)(tile_n + row) * K + k0 + c8;
            *(uint4*)&As0[row][c8] = *(const uint4*)(A0g + goA);
            *(uint4*)&As1[row][c8] = *(const uint4*)(A1g + goA);
            *(uint4*)&Bs0[row][c8] = *(const uint4*)(B0g + goB);
            *(uint4*)&Bs1[row][c8] = *(const uint4*)(B1g + goB);
        }
        __syncthreads();

#pragma unroll
        for (int ks = 0; ks < 32; ks += 16) {
            // ---- load fragments ----
            uint32_t aH[4][4], aL[4][4];
#pragma unroll
            for (int im = 0; im < 4; im++) {
                const int r = warp_m + im * 16 + g;
                const int c = ks + 2 * t;
                aH[im][0] = *(const uint32_t*)&As0[r][c];
                aH[im][1] = *(const uint32_t*)&As0[r + 8][c];
                aH[im][2] = *(const uint32_t*)&As0[r][c + 8];
                aH[im][3] = *(const uint32_t*)&As0[r + 8][c + 8];
                aL[im][0] = *(const uint32_t*)&As1[r][c];
                aL[im][1] = *(const uint32_t*)&As1[r + 8][c];
                aL[im][2] = *(const uint32_t*)&As1[r][c + 8];
                aL[im][3] = *(const uint32_t*)&As1[r + 8][c + 8];
            }
            uint32_t bH[4][2], bL[4][2];
#pragma unroll
            for (int jn = 0; jn < 4; jn++) {
                const int n = warp_n + jn * 8 + g;
                const int c = ks + 2 * t;
                bH[jn][0] = *(const uint32_t*)&Bs0[n][c];
                bH[jn][1] = *(const uint32_t*)&Bs0[n][c + 8];
                bL[jn][0] = *(const uint32_t*)&Bs1[n][c];
                bL[jn][1] = *(const uint32_t*)&Bs1[n][c + 8];
            }
            // ---- 4x4 x 3 terms ----
#pragma unroll
            for (int im = 0; im < 4; im++)
#pragma unroll
                for (int jn = 0; jn < 4; jn++) {
                    float* a = acc[im][jn];
                    mma16816(a[0], a[1], a[2], a[3],
                             aH[im][0], aH[im][1], aH[im][2], aH[im][3],
                             bH[jn][0], bH[jn][1]);
                    mma16816(a[0], a[1], a[2], a[3],
                             aH[im][0], aH[im][1], aH[im][2], aH[im][3],
                             bL[jn][0], bL[jn][1]);
                    mma16816(a[0], a[1], a[2], a[3],
                             aL[im][0], aL[im][1], aL[im][2], aL[im][3],
                             bH[jn][0], bH[jn][1]);
                }
        }
        __syncthreads();
    }

    // ---- epilogue ----
#pragma unroll
    for (int im = 0; im < 4; im++) {
        const int row = tile_m + warp_m + im * 16 + g;
#pragma unroll
        for (int jn = 0; jn < 4; jn++) {
            const int col = tile_n + warp_n + jn * 8 + 2 * t;
            float2 v0; v0.x = acc[im][jn][0]; v0.y = acc[im][jn][1];
            float2 v1; v1.x = acc[im][jn][2]; v1.y = acc[im][jn][3];
            *(float2*)(C + (size_t)row * N + col)       = v0;
            *(float2*)(C + (size_t)(row + 8) * N + col) = v1;
        }
    }
}

// ================= local (band + global-col) attention =================
__global__ __launch_bounds__(256) void attn_local() {
    const int qt   = blockIdx.x;
    const int h    = blockIdx.y;
    const int tid  = threadIdx.x;
    const int ql   = tid >> 2;
    const int part = tid & 3;
    const int q0   = qt * 64;
    const int qi   = q0 + ql;
    const int db   = part * 16;

    __shared__ float Ks[32][68];
    __shared__ float Vs[32][68];

    u64 q2[8], o2[8];
    {
        const float* qrow = g_qkv + (size_t)qi * H3 + h * HD + db;
#pragma unroll
        for (int i = 0; i < 4; i++) {
            float4 v = *(const float4*)(qrow + i * 4);
            q2[2*i]   = pack2(v.x * 0.125f, v.y * 0.125f);
            q2[2*i+1] = pack2(v.z * 0.125f, v.w * 0.125f);
            o2[2*i] = 0ull; o2[2*i+1] = 0ull;
        }
    }
    float m = -1e30f, l = 0.f;

    const int kstart = (q0 - WIN) > 0 ? (q0 - WIN) : 0;
    const int kend   = (q0 + 64 + WIN) < SEQ ? (q0 + 64 + WIN) : SEQ;

    for (int kt = kstart; kt < kend; kt += 32) {
        __syncthreads();
        {
            int idx = tid;
#pragma unroll
            for (int rep = 0; rep < 2; rep++, idx += 256) {
                int r = idx >> 4, c = (idx & 15) << 2;
                const float* src = g_qkv + (size_t)(kt + r) * H3 + HID + h * HD + c;
                *(float4*)&Ks[r][c] = *(const float4*)src;
                *(float4*)&Vs[r][c] = *(const float4*)(src + HID);
            }
        }
        __syncthreads();

#pragma unroll 4
        for (int j = 0; j < 32; j++) {
            const int kj = kt + j;
            u64 s2 = 0ull;
#pragma unroll
            for (int i = 0; i < 4; i++) {
                float4 kv = *(const float4*)&Ks[j][db + i * 4];
                s2 = fma2(q2[2*i],   pack2(kv.x, kv.y), s2);
                s2 = fma2(q2[2*i+1], pack2(kv.z, kv.w), s2);
            }
            float slo, shi; unpack2(s2, slo, shi);
            float s = slo + shi;
            s += __shfl_xor_sync(0xffffffffu, s, 1);
            s += __shfl_xor_sync(0xffffffffu, s, 2);

            int dist = qi - kj; if (dist < 0) dist = -dist;
            const bool ok = (dist <= WIN);
            const float mn = ok ? fmaxf(m, s) : m;
            const float c  = __expf(m - mn);
            const float p  = ok ? __expf(s - mn) : 0.f;
            l = l * c + p;
            m = mn;
            const u64 c2 = dup2(c), p2 = dup2(p);
#pragma unroll
            for (int i = 0; i < 4; i++) {
                float4 vv = *(const float4*)&Vs[j][db + i * 4];
                u64 va = pack2(vv.x, vv.y), vb = pack2(vv.z, vv.w);
                o2[2*i]   = fma2(o2[2*i],   c2, mul2(p2, va));
                o2[2*i+1] = fma2(o2[2*i+1], c2, mul2(p2, vb));
            }
        }
    }

    __syncthreads();
    {
        int idx = tid;
#pragma unroll
        for (int rep = 0; rep < 2; rep++, idx += 256) {
            int r = idx >> 4, c = (idx & 15) << 2;
            const float* src = g_qkv + (size_t)(r * GSTRIDE) * H3 + HID + h * HD + c;
            *(float4*)&Ks[r][c] = *(const float4*)src;
            *(float4*)&Vs[r][c] = *(const float4*)(src + HID);
        }
    }
    __syncthreads();

    for (int j = 0; j < 32; j++) {
        const int kj = j * GSTRIDE;
        u64 s2 = 0ull;
#pragma unroll
        for (int i = 0; i < 4; i++) {
            float4 kv = *(const float4*)&Ks[j][db + i * 4];
            s2 = fma2(q2[2*i],   pack2(kv.x, kv.y), s2);
            s2 = fma2(q2[2*i+1], pack2(kv.z, kv.w), s2);
        }
        float slo, shi; unpack2(s2, slo, shi);
        float s = slo + shi;
        s += __shfl_xor_sync(0xffffffffu, s, 1);
        s += __shfl_xor_sync(0xffffffffu, s, 2);

        int dist = qi - kj; if (dist < 0) dist = -dist;
        const bool ok = (dist > WIN);
        const float mn = ok ? fmaxf(m, s) : m;
        const float c  = __expf(m - mn);
        const float p  = ok ? __expf(s - mn) : 0.f;
        l = l * c + p;
        m = mn;
        const u64 c2 = dup2(c), p2 = dup2(p);
#pragma unroll
        for (int i = 0; i < 4; i++) {
            float4 vv = *(const float4*)&Vs[j][db + i * 4];
            u64 va = pack2(vv.x, vv.y), vb = pack2(vv.z, vv.w);
            o2[2*i]   = fma2(o2[2*i],   c2, mul2(p2, va));
            o2[2*i+1] = fma2(o2[2*i+1], c2, mul2(p2, vb));
        }
    }

    const float inv = 1.f / l;
    float* orow = g_attn + (size_t)qi * HID + h * HD + db;
#pragma unroll
    for (int i = 0; i < 4; i++) {
        float a, b, c, d;
        unpack2(o2[2*i], a, b); unpack2(o2[2*i+1], c, d);
        float4 v; v.x = a * inv; v.y = b * inv; v.z = c * inv; v.w = d * inv;
        *(float4*)(orow + i * 4) = v;
    }
}

// ================= global rows =================
__global__ __launch_bounds__(256) void attn_global() {
    const int gq8 = blockIdx.x;
    const int h   = blockIdx.y;
    const int tid = threadIdx.x;
    const int ql    = tid >> 5;
    const int klane = (tid >> 2) & 7;
    const int part  = tid & 3;
    const int qi    = (gq8 * 8 + ql) * 64;
    const int db    = part * 16;

    __shared__ float Ks[32][68];
    __shared__ float Vs[32][68];
    __shared__ float sm[8][8];
    __shared__ float sl[8][8];
    __shared__ float red[8][8][64];

    u64 q2[8], o2[8];
    {
        const float* qrow = g_qkv + (size_t)qi * H3 + h * HD + db;
#pragma unroll
        for (int i = 0; i < 4; i++) {
            float4 v = *(const float4*)(qrow + i * 4);
            q2[2*i]   = pack2(v.x * 0.125f, v.y * 0.125f);
            q2[2*i+1] = pack2(v.z * 0.125f, v.w * 0.125f);
            o2[2*i] = 0ull; o2[2*i+1] = 0ull;
        }
    }
    float m = -1e30f, l = 0.f;

    for (int kt = 0; kt < SEQ; kt += 32) {
        __syncthreads();
        {
            int idx = tid;
#pragma unroll
            for (int rep = 0; rep < 2; rep++, idx += 256) {
                int r = idx >> 4, c = (idx & 15) << 2;
                const float* src = g_qkv + (size_t)(kt + r) * H3 + HID + h * HD + c;
                *(float4*)&Ks[r][c] = *(const float4*)src;
                *(float4*)&Vs[r][c] = *(const float4*)(src + HID);
            }
        }
        __syncthreads();

#pragma unroll
        for (int w = 0; w < 4; w++) {
            const int j = klane + 8 * w;
            u64 s2 = 0ull;
#pragma unroll
            for (int i = 0; i < 4; i++) {
                float4 kv = *(const float4*)&Ks[j][db + i * 4];
                s2 = fma2(q2[2*i],   pack2(kv.x, kv.y), s2);
                s2 = fma2(q2[2*i+1], pack2(kv.z, kv.w), s2);
            }
            float slo, shi; unpack2(s2, slo, shi);
            float s = slo + shi;
            s += __shfl_xor_sync(0xffffffffu, s, 1);
            s += __shfl_xor_sync(0xffffffffu, s, 2);

            const float mn = fmaxf(m, s);
            const float c  = __expf(m - mn);
            const float p  = __expf(s - mn);
            l = l * c + p;
            m = mn;
            const u64 c2 = dup2(c), p2 = dup2(p);
#pragma unroll
            for (int i = 0; i < 4; i++) {
                float4 vv = *(const float4*)&Vs[j][db + i * 4];
                u64 va = pack2(vv.x, vv.y), vb = pack2(vv.z, vv.w);
                o2[2*i]   = fma2(o2[2*i],   c2, mul2(p2, va));
                o2[2*i+1] = fma2(o2[2*i+1], c2, mul2(p2, vb));
            }
        }
    }

    __syncthreads();
    if (part == 0) { sm[ql][klane] = m; sl[ql][klane] = l; }
    __syncthreads();

    float M = -1e30f;
#pragma unroll
    for (int t2 = 0; t2 < 8; t2++) M = fmaxf(M, sm[ql][t2]);
    const float w = __expf(m - M);
#pragma unroll
    for (int i = 0; i < 8; i++) {
        float a, b;
        unpack2(o2[i], a, b);
        red[ql][klane][db + 2*i]     = a * w;
        red[ql][klane][db + 2*i + 1] = b * w;
    }
    __syncthreads();

    for (int idx = tid; idx < 512; idx += 256) {
        const int ql2 = idx >> 6;
        const int d   = idx & 63;
        float M2 = -1e30f;
#pragma unroll
        for (int t2 = 0; t2 < 8; t2++) M2 = fmaxf(M2, sm[ql2][t2]);
        float L2 = 0.f;
#pragma unroll
        for (int t2 = 0; t2 < 8; t2++) L2 += sl[ql2][t2] * __expf(sm[ql2][t2] - M2);
        float sum = 0.f;
#pragma unroll
        for (int t2 = 0; t2 < 8; t2++) sum += red[ql2][t2][d];
        const int qi2 = (gq8 * 8 + ql2) * 64;
        g_attn[(size_t)qi2 * HID + h * HD + d] = sum / L2;
    }
}

// ---------------- launch ----------------
extern "C" void kernel_launch(void* const* d_in, const int* in_sizes, int n_in,
                              void* d_out, int out_size) {
    const float* x    = (const float*)d_in[0];
    const float* Wqkv = (const float*)d_in[1];
    const float* Wout = (const float*)d_in[2];
    float* out = (float*)d_out;

    float *qkv = nullptr, *attn = nullptr;
    cudaGetSymbolAddress((void**)&qkv,  g_qkv);
    cudaGetSymbolAddress((void**)&attn, g_attn);
    __nv_bfloat16 *x0, *x1, *wq0, *wq1, *a0, *a1, *wo0, *wo1;
    cudaGetSymbolAddress((void**)&x0,  g_x0);  cudaGetSymbolAddress((void**)&x1,  g_x1);
    cudaGetSymbolAddress((void**)&wq0, g_wq0); cudaGetSymbolAddress((void**)&wq1, g_wq1);
    cudaGetSymbolAddress((void**)&a0,  g_a0);  cudaGetSymbolAddress((void**)&a1,  g_a1);
    cudaGetSymbolAddress((void**)&wo0, g_wo0); cudaGetSymbolAddress((void**)&wo1, g_wo1);

    // 0) split inputs to bf16 hi/lo
    split_bf16<<<(SEQ * HID / 4 + 255) / 256, 256>>>(x, x0, x1, SEQ * HID / 4);
    split_bf16<<<(H3 * HID / 4 + 255) / 256, 256>>>(Wqkv, wq0, wq1, H3 * HID / 4);
    split_bf16<<<(HID * HID / 4 + 255) / 256, 256>>>(Wout, wo0, wo1, HID * HID / 4);

    // 1) qkv = x @ Wqkv^T  [2048, 3072]  (tensor cores, bf16 split)
    gemm_mma<<<dim3(H3 / 128, SEQ / 128), 256>>>(x0, x1, wq0, wq1, qkv, SEQ, H3, HID);

    // 2) sparse attention -> g_attn
    {
        dim3 gl(SEQ / 64, NHEAD);
        attn_local<<<gl, 256>>>();
        dim3 gg(4, NHEAD);
        attn_global<<<gg, 256>>>();
    }

    // 3) out = attn @ Wout^T  [2048, 1024]  (tensor cores, bf16 split)
    split_bf16<<<(SEQ * HID / 4 + 255) / 256, 256>>>(attn, a0, a1, SEQ * HID / 4);
    gemm_mma<<<dim3(HID / 128, SEQ / 128), 256>>>(a0, a1, wo0, wo1, out, SEQ, HID, HID);
}

// round 6
// speedup vs baseline: 1.9616x; 1.2480x over previous
#include <cuda_runtime.h>
#include <cuda_bf16.h>
#include <cstdint>

// ---------------- problem constants ----------------
#define SEQ   2048
#define HID   1024
#define H3    3072
#define NHEAD 16
#define HD    64
#define WIN   128
#define GSTRIDE 64

typedef unsigned long long u64;

// ---------------- packed f32x2 helpers ----------------
__device__ __forceinline__ u64 fma2(u64 a, u64 b, u64 c) {
    u64 d; asm("fma.rn.f32x2 %0, %1, %2, %3;" : "=l"(d) : "l"(a), "l"(b), "l"(c)); return d;
}
__device__ __forceinline__ u64 mul2(u64 a, u64 b) {
    u64 d; asm("mul.rn.f32x2 %0, %1, %2;" : "=l"(d) : "l"(a), "l"(b)); return d;
}
__device__ __forceinline__ u64 pack2(float lo, float hi) {
    u64 d; asm("mov.b64 %0, {%1, %2};" : "=l"(d) : "f"(lo), "f"(hi)); return d;
}
__device__ __forceinline__ u64 dup2(float x) { return pack2(x, x); }
__device__ __forceinline__ void unpack2(u64 v, float& lo, float& hi) {
    asm("mov.b64 {%0, %1}, %2;" : "=f"(lo), "=f"(hi) : "l"(v));
}

// ---------------- mma / ldmatrix / cp.async helpers (baseline PTX) ----------------
__device__ __forceinline__ void mma16816(float& c0, float& c1, float& c2, float& c3,
                                         uint32_t a0, uint32_t a1, uint32_t a2, uint32_t a3,
                                         uint32_t b0, uint32_t b1) {
    asm volatile(
        "mma.sync.aligned.m16n8k16.row.col.f32.bf16.bf16.f32 "
        "{%0,%1,%2,%3}, {%4,%5,%6,%7}, {%8,%9}, {%0,%1,%2,%3};"
        : "+f"(c0), "+f"(c1), "+f"(c2), "+f"(c3)
        : "r"(a0), "r"(a1), "r"(a2), "r"(a3), "r"(b0), "r"(b1));
}
__device__ __forceinline__ void ldm_x4(uint32_t& r0, uint32_t& r1, uint32_t& r2, uint32_t& r3,
                                       uint32_t addr) {
    asm volatile("ldmatrix.sync.aligned.m8n8.x4.shared.b16 {%0,%1,%2,%3}, [%4];"
                 : "=r"(r0), "=r"(r1), "=r"(r2), "=r"(r3) : "r"(addr));
}
__device__ __forceinline__ uint32_t smem_u32(const void* p) {
    uint32_t a;
    asm("{ .reg .u64 t; cvta.to.shared.u64 t, %1; cvt.u32.u64 %0, t; }" : "=r"(a) : "l"(p));
    return a;
}
__device__ __forceinline__ void cp16(uint32_t saddr, const void* gptr) {
    asm volatile("cp.async.cg.shared.global [%0], [%1], 16;" :: "r"(saddr), "l"(gptr));
}
#define CP_COMMIT() asm volatile("cp.async.commit_group;" ::: "memory")
#define CP_WAIT1()  asm volatile("cp.async.wait_group 1;" ::: "memory")

// ---------------- scratch (device globals) ----------------
__device__ float g_qkv[SEQ * H3];
__device__ float g_attn[SEQ * HID];
__device__ __nv_bfloat16 g_x0[SEQ * HID],  g_x1[SEQ * HID];
__device__ __nv_bfloat16 g_wq0[H3 * HID],  g_wq1[H3 * HID];
__device__ __nv_bfloat16 g_a0[SEQ * HID],  g_a1[SEQ * HID];
__device__ __nv_bfloat16 g_wo0[HID * HID], g_wo1[HID * HID];

// ---------------- fp32 -> (bf16 hi, bf16 lo) split ----------------
__global__ __launch_bounds__(256) void split_bf16(const float* __restrict__ in,
                                                  __nv_bfloat16* __restrict__ hi,
                                                  __nv_bfloat16* __restrict__ lo,
                                                  int n4) {
    int i = blockIdx.x * blockDim.x + threadIdx.x;
    if (i >= n4) return;
    float4 v = ((const float4*)in)[i];
    __nv_bfloat16 h0 = __float2bfloat16(v.x), h1 = __float2bfloat16(v.y);
    __nv_bfloat16 h2 = __float2bfloat16(v.z), h3 = __float2bfloat16(v.w);
    __nv_bfloat16 l0 = __float2bfloat16(v.x - __bfloat162float(h0));
    __nv_bfloat16 l1 = __float2bfloat16(v.y - __bfloat162float(h1));
    __nv_bfloat16 l2 = __float2bfloat16(v.z - __bfloat162float(h2));
    __nv_bfloat16 l3 = __float2bfloat16(v.w - __bfloat162float(h3));
    __nv_bfloat162* hp = (__nv_bfloat162*)hi;
    __nv_bfloat162* lp = (__nv_bfloat162*)lo;
    hp[2 * i]     = __nv_bfloat162(h0, h1);
    hp[2 * i + 1] = __nv_bfloat162(h2, h3);
    lp[2 * i]     = __nv_bfloat162(l0, l1);
    lp[2 * i + 1] = __nv_bfloat162(l2, l3);
}

// ---------------- tensor-core GEMM v3: cp.async double-buffer + ldmatrix ----------------
// C[M,N] = A[M,K] @ B[N,K]^T with 2-way bf16 split (3 MMA terms).
// 128x128 tile, 8 warps = 2(M) x 4(N), warp tile 64x32, BK=32, 2 smem stages.
#define SSTR 40                  // bf16 elems/row (80B): ldmatrix conflict-free
#define BUFE (128 * SSTR)        // elems per buffer
#define STGE (4 * BUFE)          // elems per stage (A0,A1,B0,B1)
#define GT_SMEM (2 * STGE * 2)   // bytes (two stages)

__global__ __launch_bounds__(256) void gemm_mma(const __nv_bfloat16* __restrict__ A0g,
                                                const __nv_bfloat16* __restrict__ A1g,
                                                const __nv_bfloat16* __restrict__ B0g,
                                                const __nv_bfloat16* __restrict__ B1g,
                                                float* __restrict__ C,
                                                int M, int N, int K) {
    extern __shared__ __nv_bfloat16 smg[];
    const uint32_t sbase = smem_u32(smg);

    const int tid = threadIdx.x;
    const int wid = tid >> 5;
    const int lane = tid & 31;
    const int g = lane >> 2;
    const int t = lane & 3;
    const int warp_m = (wid & 1) * 64;
    const int warp_n = (wid >> 1) * 32;
    const int tile_m = blockIdx.y * 128;
    const int tile_n = blockIdx.x * 128;

    // ldmatrix per-lane address components
    const int a_row = warp_m + ((lane >> 3) & 1) * 8 + (lane & 7);
    const int a_col = (lane >> 4) * 8;
    const int b_row = warp_n + (lane >> 4) * 8 + (lane & 7);
    const int b_col = ((lane >> 3) & 1) * 8;

    float acc[4][4][4];
#pragma unroll
    for (int im = 0; im < 4; im++)
#pragma unroll
        for (int jn = 0; jn < 4; jn++)
#pragma unroll
            for (int c = 0; c < 4; c++) acc[im][jn][c] = 0.f;

    // staging: per thread 2 reps x 4 buffers of 16B
    const int srow = tid >> 2;
    const int sc16 = (tid & 3) * 8;

    auto load_stage = [&](int st, int k0) {
        const uint32_t sb = sbase + (uint32_t)st * STGE * 2;
#pragma unroll
        for (int rep = 0; rep < 2; rep++) {
            const int row = srow + rep * 64;
            const uint32_t so = (uint32_t)(row * SSTR + sc16) * 2;
            const size_t goA = (size_t)(tile_m + row) * K + k0 + sc16;
            const size_t goB = (size_t)(tile_n + row) * K + k0 + sc16;
            cp16(sb + 0 * BUFE * 2 + so, A0g + goA);
            cp16(sb + 1 * BUFE * 2 + so, A1g + goA);
            cp16(sb + 2 * BUFE * 2 + so, B0g + goB);
            cp16(sb + 3 * BUFE * 2 + so, B1g + goB);
        }
    };

    const int nchunks = K >> 5;
    load_stage(0, 0);
    CP_COMMIT();

    for (int ch = 0; ch < nchunks; ch++) {
        if (ch + 1 < nchunks) load_stage((ch + 1) & 1, (ch + 1) << 5);
        CP_COMMIT();
        CP_WAIT1();
        __syncthreads();

        const uint32_t sb = sbase + (uint32_t)(ch & 1) * STGE * 2;
#pragma unroll
        for (int ks = 0; ks < 32; ks += 16) {
            uint32_t aH[4][4], aL[4][4], bH[4][2], bL[4][2];
#pragma unroll
            for (int im = 0; im < 4; im++) {
                const uint32_t ad = sb + (uint32_t)((a_row + im * 16) * SSTR + ks + a_col) * 2;
                ldm_x4(aH[im][0], aH[im][1], aH[im][2], aH[im][3], ad);
                ldm_x4(aL[im][0], aL[im][1], aL[im][2], aL[im][3], ad + BUFE * 2);
            }
#pragma unroll
            for (int jp = 0; jp < 2; jp++) {
                const uint32_t bd = sb + 2 * BUFE * 2
                                  + (uint32_t)((b_row + jp * 16) * SSTR + ks + b_col) * 2;
                ldm_x4(bH[2 * jp][0], bH[2 * jp][1], bH[2 * jp + 1][0], bH[2 * jp + 1][1], bd);
                ldm_x4(bL[2 * jp][0], bL[2 * jp][1], bL[2 * jp + 1][0], bL[2 * jp + 1][1], bd + BUFE * 2);
            }
#pragma unroll
            for (int im = 0; im < 4; im++)
#pragma unroll
                for (int jn = 0; jn < 4; jn++) {
                    float* a = acc[im][jn];
                    mma16816(a[0], a[1], a[2], a[3],
                             aH[im][0], aH[im][1], aH[im][2], aH[im][3],
                             bH[jn][0], bH[jn][1]);
                    mma16816(a[0], a[1], a[2], a[3],
                             aH[im][0], aH[im][1], aH[im][2], aH[im][3],
                             bL[jn][0], bL[jn][1]);
                    mma16816(a[0], a[1], a[2], a[3],
                             aL[im][0], aL[im][1], aL[im][2], aL[im][3],
                             bH[jn][0], bH[jn][1]);
                }
        }
        __syncthreads();
    }

    // ---- epilogue ----
#pragma unroll
    for (int im = 0; im < 4; im++) {
        const int row = tile_m + warp_m + im * 16 + g;
#pragma unroll
        for (int jn = 0; jn < 4; jn++) {
            const int col = tile_n + warp_n + jn * 8 + 2 * t;
            float2 v0; v0.x = acc[im][jn][0]; v0.y = acc[im][jn][1];
            float2 v1; v1.x = acc[im][jn][2]; v1.y = acc[im][jn][3];
            *(float2*)(C + (size_t)row * N + col)       = v0;
            *(float2*)(C + (size_t)(row + 8) * N + col) = v1;
        }
    }
}

// ================= local (band + global-col) attention =================
// 256 threads: 64 queries x 4 parts; batch-of-16 softmax (scores -> batch max ->
// single rescale -> accumulate).
__global__ __launch_bounds__(256) void attn_local() {
    const int qt   = blockIdx.x;
    const int h    = blockIdx.y;
    const int tid  = threadIdx.x;
    const int ql   = tid >> 2;
    const int part = tid & 3;
    const int q0   = qt * 64;
    const int qi   = q0 + ql;
    const int db   = part * 16;

    __shared__ float Ks[32][68];
    __shared__ float Vs[32][68];

    u64 q2[8], o2[8];
    {
        const float* qrow = g_qkv + (size_t)qi * H3 + h * HD + db;
#pragma unroll
        for (int i = 0; i < 4; i++) {
            float4 v = *(const float4*)(qrow + i * 4);
            q2[2*i]   = pack2(v.x * 0.125f, v.y * 0.125f);
            q2[2*i+1] = pack2(v.z * 0.125f, v.w * 0.125f);
            o2[2*i] = 0ull; o2[2*i+1] = 0ull;
        }
    }
    float m = -1e30f, l = 0.f;

    const int kstart = (q0 - WIN) > 0 ? (q0 - WIN) : 0;
    const int kend   = (q0 + 64 + WIN) < SEQ ? (q0 + 64 + WIN) : SEQ;

    for (int kt = kstart; kt < kend; kt += 32) {
        __syncthreads();
        {
            int idx = tid;
#pragma unroll
            for (int rep = 0; rep < 2; rep++, idx += 256) {
                int r = idx >> 4, c = (idx & 15) << 2;
                const float* src = g_qkv + (size_t)(kt + r) * H3 + HID + h * HD + c;
                *(float4*)&Ks[r][c] = *(const float4*)src;
                *(float4*)&Vs[r][c] = *(const float4*)(src + HID);
            }
        }
        __syncthreads();

#pragma unroll
        for (int half = 0; half < 2; half++) {
            float s[16];
#pragma unroll
            for (int j16 = 0; j16 < 16; j16++) {
                const int j = half * 16 + j16;
                const int kj = kt + j;
                u64 s2 = 0ull;
#pragma unroll
                for (int i = 0; i < 4; i++) {
                    float4 kv = *(const float4*)&Ks[j][db + i * 4];
                    s2 = fma2(q2[2*i],   pack2(kv.x, kv.y), s2);
                    s2 = fma2(q2[2*i+1], pack2(kv.z, kv.w), s2);
                }
                float slo, shi; unpack2(s2, slo, shi);
                float sv = slo + shi;
                sv += __shfl_xor_sync(0xffffffffu, sv, 1);
                sv += __shfl_xor_sync(0xffffffffu, sv, 2);
                int dist = qi - kj; if (dist < 0) dist = -dist;
                s[j16] = (dist <= WIN) ? sv : -1e30f;
            }
            float tmax = s[0];
#pragma unroll
            for (int j16 = 1; j16 < 16; j16++) tmax = fmaxf(tmax, s[j16]);
            if (tmax > -1e29f) {
                const float mn = fmaxf(m, tmax);
                const float c = __expf(m - mn);
                m = mn; l *= c;
                const u64 c2 = dup2(c);
#pragma unroll
                for (int i = 0; i < 8; i++) o2[i] = mul2(o2[i], c2);
#pragma unroll
                for (int j16 = 0; j16 < 16; j16++) {
                    const int j = half * 16 + j16;
                    const float p = __expf(s[j16] - m);
                    l += p;
                    const u64 p2 = dup2(p);
#pragma unroll
                    for (int i = 0; i < 4; i++) {
                        float4 vv = *(const float4*)&Vs[j][db + i * 4];
                        o2[2*i]   = fma2(p2, pack2(vv.x, vv.y), o2[2*i]);
                        o2[2*i+1] = fma2(p2, pack2(vv.z, vv.w), o2[2*i+1]);
                    }
                }
            }
        }
    }

    // ---- phase 2: global columns outside the band ----
    __syncthreads();
    {
        int idx = tid;
#pragma unroll
        for (int rep = 0; rep < 2; rep++, idx += 256) {
            int r = idx >> 4, c = (idx & 15) << 2;
            const float* src = g_qkv + (size_t)(r * GSTRIDE) * H3 + HID + h * HD + c;
            *(float4*)&Ks[r][c] = *(const float4*)src;
            *(float4*)&Vs[r][c] = *(const float4*)(src + HID);
        }
    }
    __syncthreads();

#pragma unroll
    for (int half = 0; half < 2; half++) {
        float s[16];
#pragma unroll
        for (int j16 = 0; j16 < 16; j16++) {
            const int j = half * 16 + j16;
            const int kj = j * GSTRIDE;
            u64 s2 = 0ull;
#pragma unroll
            for (int i = 0; i < 4; i++) {
                float4 kv = *(const float4*)&Ks[j][db + i * 4];
                s2 = fma2(q2[2*i],   pack2(kv.x, kv.y), s2);
                s2 = fma2(q2[2*i+1], pack2(kv.z, kv.w), s2);
            }
            float slo, shi; unpack2(s2, slo, shi);
            float sv = slo + shi;
            sv += __shfl_xor_sync(0xffffffffu, sv, 1);
            sv += __shfl_xor_sync(0xffffffffu, sv, 2);
            int dist = qi - kj; if (dist < 0) dist = -dist;
            s[j16] = (dist > WIN) ? sv : -1e30f;
        }
        float tmax = s[0];
#pragma unroll
        for (int j16 = 1; j16 < 16; j16++) tmax = fmaxf(tmax, s[j16]);
        if (tmax > -1e29f) {
            const float mn = fmaxf(m, tmax);
            const float c = __expf(m - mn);
            m = mn; l *= c;
            const u64 c2 = dup2(c);
#pragma unroll
            for (int i = 0; i < 8; i++) o2[i] = mul2(o2[i], c2);
#pragma unroll
            for (int j16 = 0; j16 < 16; j16++) {
                const int j = half * 16 + j16;
                const float p = __expf(s[j16] - m);
                l += p;
                const u64 p2 = dup2(p);
#pragma unroll
                for (int i = 0; i < 4; i++) {
                    float4 vv = *(const float4*)&Vs[j][db + i * 4];
                    o2[2*i]   = fma2(p2, pack2(vv.x, vv.y), o2[2*i]);
                    o2[2*i+1] = fma2(p2, pack2(vv.z, vv.w), o2[2*i+1]);
                }
            }
        }
    }

    const float inv = 1.f / l;
    float* orow = g_attn + (size_t)qi * HID + h * HD + db;
#pragma unroll
    for (int i = 0; i < 4; i++) {
        float a, b, c, d;
        unpack2(o2[2*i], a, b); unpack2(o2[2*i+1], c, d);
        float4 v; v.x = a * inv; v.y = b * inv; v.z = c * inv; v.w = d * inv;
        *(float4*)(orow + i * 4) = v;
    }
}

// ================= global rows =================
__global__ __launch_bounds__(256) void attn_global() {
    const int gq8 = blockIdx.x;
    const int h   = blockIdx.y;
    const int tid = threadIdx.x;
    const int ql    = tid >> 5;
    const int klane = (tid >> 2) & 7;
    const int part  = tid & 3;
    const int qi    = (gq8 * 8 + ql) * 64;
    const int db    = part * 16;

    __shared__ float Ks[32][68];
    __shared__ float Vs[32][68];
    __shared__ float sm[8][8];
    __shared__ float sl[8][8];
    __shared__ float red[8][8][64];

    u64 q2[8], o2[8];
    {
        const float* qrow = g_qkv + (size_t)qi * H3 + h * HD + db;
#pragma unroll
        for (int i = 0; i < 4; i++) {
            float4 v = *(const float4*)(qrow + i * 4);
            q2[2*i]   = pack2(v.x * 0.125f, v.y * 0.125f);
            q2[2*i+1] = pack2(v.z * 0.125f, v.w * 0.125f);
            o2[2*i] = 0ull; o2[2*i+1] = 0ull;
        }
    }
    float m = -1e30f, l = 0.f;

    for (int kt = 0; kt < SEQ; kt += 32) {
        __syncthreads();
        {
            int idx = tid;
#pragma unroll
            for (int rep = 0; rep < 2; rep++, idx += 256) {
                int r = idx >> 4, c = (idx & 15) << 2;
                const float* src = g_qkv + (size_t)(kt + r) * H3 + HID + h * HD + c;
                *(float4*)&Ks[r][c] = *(const float4*)src;
                *(float4*)&Vs[r][c] = *(const float4*)(src + HID);
            }
        }
        __syncthreads();

        // batch-of-4 softmax per klane
        float s[4];
#pragma unroll
        for (int w = 0; w < 4; w++) {
            const int j = klane + 8 * w;
            u64 s2 = 0ull;
#pragma unroll
            for (int i = 0; i < 4; i++) {
                float4 kv = *(const float4*)&Ks[j][db + i * 4];
                s2 = fma2(q2[2*i],   pack2(kv.x, kv.y), s2);
                s2 = fma2(q2[2*i+1], pack2(kv.z, kv.w), s2);
            }
            float slo, shi; unpack2(s2, slo, shi);
            float sv = slo + shi;
            sv += __shfl_xor_sync(0xffffffffu, sv, 1);
            sv += __shfl_xor_sync(0xffffffffu, sv, 2);
            s[w] = sv;
        }
        float tmax = fmaxf(fmaxf(s[0], s[1]), fmaxf(s[2], s[3]));
        const float mn = fmaxf(m, tmax);
        const float c = __expf(m - mn);
        m = mn; l *= c;
        const u64 c2 = dup2(c);
#pragma unroll
        for (int i = 0; i < 8; i++) o2[i] = mul2(o2[i], c2);
#pragma unroll
        for (int w = 0; w < 4; w++) {
            const int j = klane + 8 * w;
            const float p = __expf(s[w] - m);
            l += p;
            const u64 p2 = dup2(p);
#pragma unroll
            for (int i = 0; i < 4; i++) {
                float4 vv = *(const float4*)&Vs[j][db + i * 4];
                o2[2*i]   = fma2(p2, pack2(vv.x, vv.y), o2[2*i]);
                o2[2*i+1] = fma2(p2, pack2(vv.z, vv.w), o2[2*i+1]);
            }
        }
    }

    __syncthreads();
    if (part == 0) { sm[ql][klane] = m; sl[ql][klane] = l; }
    __syncthreads();

    float M = -1e30f;
#pragma unroll
    for (int t2 = 0; t2 < 8; t2++) M = fmaxf(M, sm[ql][t2]);
    const float w = __expf(m - M);
#pragma unroll
    for (int i = 0; i < 8; i++) {
        float a, b;
        unpack2(o2[i], a, b);
        red[ql][klane][db + 2*i]     = a * w;
        red[ql][klane][db + 2*i + 1] = b * w;
    }
    __syncthreads();

    for (int idx = tid; idx < 512; idx += 256) {
        const int ql2 = idx >> 6;
        const int d   = idx & 63;
        float M2 = -1e30f;
#pragma unroll
        for (int t2 = 0; t2 < 8; t2++) M2 = fmaxf(M2, sm[ql2][t2]);
        float L2 = 0.f;
#pragma unroll
        for (int t2 = 0; t2 < 8; t2++) L2 += sl[ql2][t2] * __expf(sm[ql2][t2] - M2);
        float sum = 0.f;
#pragma unroll
        for (int t2 = 0; t2 < 8; t2++) sum += red[ql2][t2][d];
        const int qi2 = (gq8 * 8 + ql2) * 64;
        g_attn[(size_t)qi2 * HID + h * HD + d] = sum / L2;
    }
}

// ---------------- launch ----------------
extern "C" void kernel_launch(void* const* d_in, const int* in_sizes, int n_in,
                              void* d_out, int out_size) {
    const float* x    = (const float*)d_in[0];
    const float* Wqkv = (const float*)d_in[1];
    const float* Wout = (const float*)d_in[2];
    float* out = (float*)d_out;

    float *qkv = nullptr, *attn = nullptr;
    cudaGetSymbolAddress((void**)&qkv,  g_qkv);
    cudaGetSymbolAddress((void**)&attn, g_attn);
    __nv_bfloat16 *x0, *x1, *wq0, *wq1, *a0, *a1, *wo0, *wo1;
    cudaGetSymbolAddress((void**)&x0,  g_x0);  cudaGetSymbolAddress((void**)&x1,  g_x1);
    cudaGetSymbolAddress((void**)&wq0, g_wq0); cudaGetSymbolAddress((void**)&wq1, g_wq1);
    cudaGetSymbolAddress((void**)&a0,  g_a0);  cudaGetSymbolAddress((void**)&a1,  g_a1);
    cudaGetSymbolAddress((void**)&wo0, g_wo0); cudaGetSymbolAddress((void**)&wo1, g_wo1);

    cudaFuncSetAttribute(gemm_mma, cudaFuncAttributeMaxDynamicSharedMemorySize, GT_SMEM);

    // 0) split inputs to bf16 hi/lo
    split_bf16<<<(SEQ * HID / 4 + 255) / 256, 256>>>(x, x0, x1, SEQ * HID / 4);
    split_bf16<<<(H3 * HID / 4 + 255) / 256, 256>>>(Wqkv, wq0, wq1, H3 * HID / 4);
    split_bf16<<<(HID * HID / 4 + 255) / 256, 256>>>(Wout, wo0, wo1, HID * HID / 4);

    // 1) qkv = x @ Wqkv^T  [2048, 3072]
    gemm_mma<<<dim3(H3 / 128, SEQ / 128), 256, GT_SMEM>>>(x0, x1, wq0, wq1, qkv, SEQ, H3, HID);

    // 2) sparse attention -> g_attn
    {
        dim3 gl(SEQ / 64, NHEAD);
        attn_local<<<gl, 256>>>();
        dim3 gg(4, NHEAD);
        attn_global<<<gg, 256>>>();
    }

    // 3) out = attn @ Wout^T  [2048, 1024]
    split_bf16<<<(SEQ * HID / 4 + 255) / 256, 256>>>(attn, a0, a1, SEQ * HID / 4);
    gemm_mma<<<dim3(HID / 128, SEQ / 128), 256, GT_SMEM>>>(a0, a1, wo0, wo1, out, SEQ, HID, HID);
}

// round 7
// speedup vs baseline: 3.4712x; 1.7696x over previous
#include <cuda_runtime.h>
#include <cuda_bf16.h>
#include <cstdint>

// ---------------- problem constants ----------------
#define SEQ   2048
#define HID   1024
#define H3    3072
#define NHEAD 16
#define HD    64
#define WIN   128
#define GSTRIDE 64

typedef unsigned long long u64;

// ---------------- packed f32x2 helpers ----------------
__device__ __forceinline__ u64 fma2(u64 a, u64 b, u64 c) {
    u64 d; asm("fma.rn.f32x2 %0, %1, %2, %3;" : "=l"(d) : "l"(a), "l"(b), "l"(c)); return d;
}
__device__ __forceinline__ u64 mul2(u64 a, u64 b) {
    u64 d; asm("mul.rn.f32x2 %0, %1, %2;" : "=l"(d) : "l"(a), "l"(b)); return d;
}
__device__ __forceinline__ u64 pack2(float lo, float hi) {
    u64 d; asm("mov.b64 %0, {%1, %2};" : "=l"(d) : "f"(lo), "f"(hi)); return d;
}
__device__ __forceinline__ u64 dup2(float x) { return pack2(x, x); }
__device__ __forceinline__ void unpack2(u64 v, float& lo, float& hi) {
    asm("mov.b64 {%0, %1}, %2;" : "=f"(lo), "=f"(hi) : "l"(v));
}

// ---------------- mma / ldmatrix / cp.async helpers ----------------
__device__ __forceinline__ void mma16816(float& c0, float& c1, float& c2, float& c3,
                                         uint32_t a0, uint32_t a1, uint32_t a2, uint32_t a3,
                                         uint32_t b0, uint32_t b1) {
    asm volatile(
        "mma.sync.aligned.m16n8k16.row.col.f32.bf16.bf16.f32 "
        "{%0,%1,%2,%3}, {%4,%5,%6,%7}, {%8,%9}, {%0,%1,%2,%3};"
        : "+f"(c0), "+f"(c1), "+f"(c2), "+f"(c3)
        : "r"(a0), "r"(a1), "r"(a2), "r"(a3), "r"(b0), "r"(b1));
}
__device__ __forceinline__ void ldm_x4(uint32_t& r0, uint32_t& r1, uint32_t& r2, uint32_t& r3,
                                       uint32_t addr) {
    asm volatile("ldmatrix.sync.aligned.m8n8.x4.shared.b16 {%0,%1,%2,%3}, [%4];"
                 : "=r"(r0), "=r"(r1), "=r"(r2), "=r"(r3) : "r"(addr));
}
__device__ __forceinline__ uint32_t smem_u32(const void* p) {
    uint32_t a;
    asm("{ .reg .u64 t; cvta.to.shared.u64 t, %1; cvt.u32.u64 %0, t; }" : "=r"(a) : "l"(p));
    return a;
}
__device__ __forceinline__ void cp16(uint32_t saddr, const void* gptr) {
    asm volatile("cp.async.cg.shared.global [%0], [%1], 16;" :: "r"(saddr), "l"(gptr));
}
#define CP_COMMIT() asm volatile("cp.async.commit_group;" ::: "memory")
#define CP_WAIT1()  asm volatile("cp.async.wait_group 1;" ::: "memory")

// bf16 hi/lo split helpers
__device__ __forceinline__ void bsplit(float x, __nv_bfloat16& hi, __nv_bfloat16& lo) {
    hi = __float2bfloat16(x);
    lo = __float2bfloat16(x - __bfloat162float(hi));
}
// pack two floats as bf16x2 (a in low half) plus the bf16x2 of the residuals
__device__ __forceinline__ void psplit2(float a, float b, uint32_t& hi, uint32_t& lo) {
    uint32_t hp;
    asm("cvt.rn.bf16x2.f32 %0, %1, %2;" : "=r"(hp) : "f"(b), "f"(a));
    const float ha = __uint_as_float(hp << 16);
    const float hb = __uint_as_float(hp & 0xffff0000u);
    uint32_t lp;
    asm("cvt.rn.bf16x2.f32 %0, %1, %2;" : "=r"(lp) : "f"(b - hb), "f"(a - ha));
    hi = hp; lo = lp;
}

// ---------------- scratch (device globals) ----------------
__device__ float g_qkv[SEQ * H3];
__device__ float g_attn[SEQ * HID];
__device__ __nv_bfloat16 g_x0[SEQ * HID],  g_x1[SEQ * HID];
__device__ __nv_bfloat16 g_wq0[H3 * HID],  g_wq1[H3 * HID];
__device__ __nv_bfloat16 g_a0[SEQ * HID],  g_a1[SEQ * HID];
__device__ __nv_bfloat16 g_wo0[HID * HID], g_wo1[HID * HID];

// ---------------- fp32 -> (bf16 hi, bf16 lo) split ----------------
__global__ __launch_bounds__(256) void split_bf16(const float* __restrict__ in,
                                                  __nv_bfloat16* __restrict__ hi,
                                                  __nv_bfloat16* __restrict__ lo,
                                                  int n4) {
    int i = blockIdx.x * blockDim.x + threadIdx.x;
    if (i >= n4) return;
    float4 v = ((const float4*)in)[i];
    __nv_bfloat16 h0 = __float2bfloat16(v.x), h1 = __float2bfloat16(v.y);
    __nv_bfloat16 h2 = __float2bfloat16(v.z), h3 = __float2bfloat16(v.w);
    __nv_bfloat16 l0 = __float2bfloat16(v.x - __bfloat162float(h0));
    __nv_bfloat16 l1 = __float2bfloat16(v.y - __bfloat162float(h1));
    __nv_bfloat16 l2 = __float2bfloat16(v.z - __bfloat162float(h2));
    __nv_bfloat16 l3 = __float2bfloat16(v.w - __bfloat162float(h3));
    __nv_bfloat162* hp = (__nv_bfloat162*)hi;
    __nv_bfloat162* lp = (__nv_bfloat162*)lo;
    hp[2 * i]     = __nv_bfloat162(h0, h1);
    hp[2 * i + 1] = __nv_bfloat162(h2, h3);
    lp[2 * i]     = __nv_bfloat162(l0, l1);
    lp[2 * i + 1] = __nv_bfloat162(l2, l3);
}

// ---------------- tensor-core GEMM (unchanged from R6) ----------------
#define SSTR 40
#define BUFE (128 * SSTR)
#define STGE (4 * BUFE)
#define GT_SMEM (2 * STGE * 2)

__global__ __launch_bounds__(256) void gemm_mma(const __nv_bfloat16* __restrict__ A0g,
                                                const __nv_bfloat16* __restrict__ A1g,
                                                const __nv_bfloat16* __restrict__ B0g,
                                                const __nv_bfloat16* __restrict__ B1g,
                                                float* __restrict__ C,
                                                int M, int N, int K) {
    extern __shared__ __nv_bfloat16 smg[];
    const uint32_t sbase = smem_u32(smg);

    const int tid = threadIdx.x;
    const int wid = tid >> 5;
    const int lane = tid & 31;
    const int g = lane >> 2;
    const int t = lane & 3;
    const int warp_m = (wid & 1) * 64;
    const int warp_n = (wid >> 1) * 32;
    const int tile_m = blockIdx.y * 128;
    const int tile_n = blockIdx.x * 128;

    const int a_row = warp_m + ((lane >> 3) & 1) * 8 + (lane & 7);
    const int a_col = (lane >> 4) * 8;
    const int b_row = warp_n + (lane >> 4) * 8 + (lane & 7);
    const int b_col = ((lane >> 3) & 1) * 8;

    float acc[4][4][4];
#pragma unroll
    for (int im = 0; im < 4; im++)
#pragma unroll
        for (int jn = 0; jn < 4; jn++)
#pragma unroll
            for (int c = 0; c < 4; c++) acc[im][jn][c] = 0.f;

    const int srow = tid >> 2;
    const int sc16 = (tid & 3) * 8;

    auto load_stage = [&](int st, int k0) {
        const uint32_t sb = sbase + (uint32_t)st * STGE * 2;
#pragma unroll
        for (int rep = 0; rep < 2; rep++) {
            const int row = srow + rep * 64;
            const uint32_t so = (uint32_t)(row * SSTR + sc16) * 2;
            const size_t goA = (size_t)(tile_m + row) * K + k0 + sc16;
            const size_t goB = (size_t)(tile_n + row) * K + k0 + sc16;
            cp16(sb + 0 * BUFE * 2 + so, A0g + goA);
            cp16(sb + 1 * BUFE * 2 + so, A1g + goA);
            cp16(sb + 2 * BUFE * 2 + so, B0g + goB);
            cp16(sb + 3 * BUFE * 2 + so, B1g + goB);
        }
    };

    const int nchunks = K >> 5;
    load_stage(0, 0);
    CP_COMMIT();

    for (int ch = 0; ch < nchunks; ch++) {
        if (ch + 1 < nchunks) load_stage((ch + 1) & 1, (ch + 1) << 5);
        CP_COMMIT();
        CP_WAIT1();
        __syncthreads();

        const uint32_t sb = sbase + (uint32_t)(ch & 1) * STGE * 2;
#pragma unroll
        for (int ks = 0; ks < 32; ks += 16) {
            uint32_t aH[4][4], aL[4][4], bH[4][2], bL[4][2];
#pragma unroll
            for (int im = 0; im < 4; im++) {
                const uint32_t ad = sb + (uint32_t)((a_row + im * 16) * SSTR + ks + a_col) * 2;
                ldm_x4(aH[im][0], aH[im][1], aH[im][2], aH[im][3], ad);
                ldm_x4(aL[im][0], aL[im][1], aL[im][2], aL[im][3], ad + BUFE * 2);
            }
#pragma unroll
            for (int jp = 0; jp < 2; jp++) {
                const uint32_t bd = sb + 2 * BUFE * 2
                                  + (uint32_t)((b_row + jp * 16) * SSTR + ks + b_col) * 2;
                ldm_x4(bH[2 * jp][0], bH[2 * jp][1], bH[2 * jp + 1][0], bH[2 * jp + 1][1], bd);
                ldm_x4(bL[2 * jp][0], bL[2 * jp][1], bL[2 * jp + 1][0], bL[2 * jp + 1][1], bd + BUFE * 2);
            }
#pragma unroll
            for (int im = 0; im < 4; im++)
#pragma unroll
                for (int jn = 0; jn < 4; jn++) {
                    float* a = acc[im][jn];
                    mma16816(a[0], a[1], a[2], a[3],
                             aH[im][0], aH[im][1], aH[im][2], aH[im][3],
                             bH[jn][0], bH[jn][1]);
                    mma16816(a[0], a[1], a[2], a[3],
                             aH[im][0], aH[im][1], aH[im][2], aH[im][3],
                             bL[jn][0], bL[jn][1]);
                    mma16816(a[0], a[1], a[2], a[3],
                             aL[im][0], aL[im][1], aL[im][2], aL[im][3],
                             bH[jn][0], bH[jn][1]);
                }
        }
        __syncthreads();
    }

#pragma unroll
    for (int im = 0; im < 4; im++) {
        const int row = tile_m + warp_m + im * 16 + g;
#pragma unroll
        for (int jn = 0; jn < 4; jn++) {
            const int col = tile_n + warp_n + jn * 8 + 2 * t;
            float2 v0; v0.x = acc[im][jn][0]; v0.y = acc[im][jn][1];
            float2 v1; v1.x = acc[im][jn][2]; v1.y = acc[im][jn][3];
            *(float2*)(C + (size_t)row * N + col)       = v0;
            *(float2*)(C + (size_t)(row + 8) * N + col) = v1;
        }
    }
}

// ================= MMA flash attention: band + global-col =================
// Block = (64-query tile, head). 4 warps x 16 query rows. Masked scores = -3e38,
// m init = -1e30 so all-invalid tiles degenerate to p=0 / c=1 branchlessly.
#define MASKV (-3.0e38f)

__device__ __forceinline__ void attn_tile(
    bool ph1, int kb, int h, int q0, int tid, int wid, int g, int t,
    const uint32_t qh[4][4], const uint32_t qlo[4][4],
    float o[8][4], float& m0, float& m1, float& l0, float& l1,
    __nv_bfloat16 (*Ksh)[72], __nv_bfloat16 (*Ksl)[72],
    __nv_bfloat16 (*Vth)[72], __nv_bfloat16 (*Vtl)[72])
{
    __syncthreads();
    // stage K [key][dim] and V transposed [dim][key], both split hi/lo
    for (int idx = tid; idx < 1024; idx += 128) {
        const int r  = idx >> 4;
        const int c4 = (idx & 15) << 2;
        const int krow = ph1 ? (kb + r) : ((r < 32 ? r : 0) * GSTRIDE);
        const float* kp = g_qkv + (size_t)krow * H3 + HID + h * HD + c4;
        const float4 kv = *(const float4*)kp;
        const float4 vv = *(const float4*)(kp + HID);
        bsplit(kv.x, Ksh[r][c4 + 0], Ksl[r][c4 + 0]);
        bsplit(kv.y, Ksh[r][c4 + 1], Ksl[r][c4 + 1]);
        bsplit(kv.z, Ksh[r][c4 + 2], Ksl[r][c4 + 2]);
        bsplit(kv.w, Ksh[r][c4 + 3], Ksl[r][c4 + 3]);
        bsplit(vv.x, Vth[c4 + 0][r], Vtl[c4 + 0][r]);
        bsplit(vv.y, Vth[c4 + 1][r], Vtl[c4 + 1][r]);
        bsplit(vv.z, Vth[c4 + 2][r], Vtl[c4 + 2][r]);
        bsplit(vv.w, Vth[c4 + 3][r], Vtl[c4 + 3][r]);
    }
    __syncthreads();

    // ---- S = Q K^T (3-term split MMA) ----
    float sc[8][4];
#pragma unroll
    for (int jn = 0; jn < 8; jn++) {
        const int kr = jn * 8 + g;
        uint32_t bh[4][2], bl[4][2];
#pragma unroll
        for (int c = 0; c < 4; c++) {
            bh[c][0] = *(const uint32_t*)&Ksh[kr][c * 16 + 2 * t];
            bh[c][1] = *(const uint32_t*)&Ksh[kr][c * 16 + 8 + 2 * t];
            bl[c][0] = *(const uint32_t*)&Ksl[kr][c * 16 + 2 * t];
            bl[c][1] = *(const uint32_t*)&Ksl[kr][c * 16 + 8 + 2 * t];
        }
        sc[jn][0] = sc[jn][1] = sc[jn][2] = sc[jn][3] = 0.f;
#pragma unroll
        for (int c = 0; c < 4; c++) {
            mma16816(sc[jn][0], sc[jn][1], sc[jn][2], sc[jn][3],
                     qh[c][0], qh[c][1], qh[c][2], qh[c][3], bh[c][0], bh[c][1]);
            mma16816(sc[jn][0], sc[jn][1], sc[jn][2], sc[jn][3],
                     qh[c][0], qh[c][1], qh[c][2], qh[c][3], bl[c][0], bl[c][1]);
            mma16816(sc[jn][0], sc[jn][1], sc[jn][2], sc[jn][3],
                     qlo[c][0], qlo[c][1], qlo[c][2], qlo[c][3], bh[c][0], bh[c][1]);
        }
    }

    // ---- mask + row max ----
    const int qr0 = q0 + wid * 16 + g;
    const int qr1 = qr0 + 8;
    float tm0 = MASKV, tm1 = MASKV;
#pragma unroll
    for (int jn = 0; jn < 8; jn++) {
        const int cc = jn * 8 + 2 * t;
#pragma unroll
        for (int e = 0; e < 2; e++) {
            const int ci  = cc + e;
            const int key = ph1 ? (kb + ci) : (ci * GSTRIDE);
            int d0 = qr0 - key; d0 = d0 < 0 ? -d0 : d0;
            int d1 = qr1 - key; d1 = d1 < 0 ? -d1 : d1;
            const bool in0 = ph1 ? (d0 <= WIN) : (ci < 32 && d0 > WIN);
            const bool in1 = ph1 ? (d1 <= WIN) : (ci < 32 && d1 > WIN);
            if (!in0) sc[jn][e]     = MASKV;
            if (!in1) sc[jn][2 + e] = MASKV;
            tm0 = fmaxf(tm0, sc[jn][e]);
            tm1 = fmaxf(tm1, sc[jn][2 + e]);
        }
    }
    tm0 = fmaxf(tm0, __shfl_xor_sync(0xffffffffu, tm0, 1));
    tm0 = fmaxf(tm0, __shfl_xor_sync(0xffffffffu, tm0, 2));
    tm1 = fmaxf(tm1, __shfl_xor_sync(0xffffffffu, tm1, 1));
    tm1 = fmaxf(tm1, __shfl_xor_sync(0xffffffffu, tm1, 2));

    const float mn0 = fmaxf(m0, tm0), mn1 = fmaxf(m1, tm1);
    const float e0 = __expf(m0 - mn0), e1 = __expf(m1 - mn1);
    m0 = mn0; m1 = mn1; l0 *= e0; l1 *= e1;
#pragma unroll
    for (int nb = 0; nb < 8; nb++) {
        o[nb][0] *= e0; o[nb][1] *= e0; o[nb][2] *= e1; o[nb][3] *= e1;
    }

    // ---- P = exp(S - m), split, and O += P V (3-term MMA) ----
    float s0 = 0.f, s1 = 0.f;
#pragma unroll
    for (int c = 0; c < 4; c++) {
        const float p00 = __expf(sc[2 * c][0] - m0);
        const float p01 = __expf(sc[2 * c][1] - m0);
        const float p02 = __expf(sc[2 * c][2] - m1);
        const float p03 = __expf(sc[2 * c][3] - m1);
        const float p10 = __expf(sc[2 * c + 1][0] - m0);
        const float p11 = __expf(sc[2 * c + 1][1] - m0);
        const float p12 = __expf(sc[2 * c + 1][2] - m1);
        const float p13 = __expf(sc[2 * c + 1][3] - m1);
        s0 += (p00 + p01) + (p10 + p11);
        s1 += (p02 + p03) + (p12 + p13);
        uint32_t ah[4], al[4];
        psplit2(p00, p01, ah[0], al[0]);
        psplit2(p02, p03, ah[1], al[1]);
        psplit2(p10, p11, ah[2], al[2]);
        psplit2(p12, p13, ah[3], al[3]);
#pragma unroll
        for (int nb = 0; nb < 8; nb++) {
            const int vr = nb * 8 + g;
            const uint32_t b0h = *(const uint32_t*)&Vth[vr][c * 16 + 2 * t];
            const uint32_t b1h = *(const uint32_t*)&Vth[vr][c * 16 + 8 + 2 * t];
            const uint32_t b0l = *(const uint32_t*)&Vtl[vr][c * 16 + 2 * t];
            const uint32_t b1l = *(const uint32_t*)&Vtl[vr][c * 16 + 8 + 2 * t];
            mma16816(o[nb][0], o[nb][1], o[nb][2], o[nb][3],
                     ah[0], ah[1], ah[2], ah[3], b0h, b1h);
            mma16816(o[nb][0], o[nb][1], o[nb][2], o[nb][3],
                     ah[0], ah[1], ah[2], ah[3], b0l, b1l);
            mma16816(o[nb][0], o[nb][1], o[nb][2], o[nb][3],
                     al[0], al[1], al[2], al[3], b0h, b1h);
        }
    }
    s0 += __shfl_xor_sync(0xffffffffu, s0, 1);
    s0 += __shfl_xor_sync(0xffffffffu, s0, 2);
    s1 += __shfl_xor_sync(0xffffffffu, s1, 1);
    s1 += __shfl_xor_sync(0xffffffffu, s1, 2);
    l0 += s0; l1 += s1;
}

__global__ __launch_bounds__(128) void attn_mma() {
    const int qt = blockIdx.x, h = blockIdx.y;
    const int q0 = qt * 64;
    const int tid = threadIdx.x;
    const int wid = tid >> 5, lane = tid & 31;
    const int g = lane >> 2, t = lane & 3;

    __shared__ __nv_bfloat16 Ksh[64][72], Ksl[64][72], Vth[64][72], Vtl[64][72];

    // ---- stage Q (pre-scaled by 1/8) and load A-fragments ----
    for (int idx = tid; idx < 1024; idx += 128) {
        const int r = idx >> 4, c4 = (idx & 15) << 2;
        const float4 v = *(const float4*)(g_qkv + (size_t)(q0 + r) * H3 + h * HD + c4);
        bsplit(v.x * 0.125f, Ksh[r][c4 + 0], Ksl[r][c4 + 0]);
        bsplit(v.y * 0.125f, Ksh[r][c4 + 1], Ksl[r][c4 + 1]);
        bsplit(v.z * 0.125f, Ksh[r][c4 + 2], Ksl[r][c4 + 2]);
        bsplit(v.w * 0.125f, Ksh[r][c4 + 3], Ksl[r][c4 + 3]);
    }
    __syncthreads();
    uint32_t qh[4][4], qlo[4][4];
    {
        const int r0 = wid * 16 + g, r1 = r0 + 8;
#pragma unroll
        for (int c = 0; c < 4; c++) {
            const int col = c * 16 + 2 * t;
            qh[c][0]  = *(const uint32_t*)&Ksh[r0][col];
            qh[c][1]  = *(const uint32_t*)&Ksh[r1][col];
            qh[c][2]  = *(const uint32_t*)&Ksh[r0][col + 8];
            qh[c][3]  = *(const uint32_t*)&Ksh[r1][col + 8];
            qlo[c][0] = *(const uint32_t*)&Ksl[r0][col];
            qlo[c][1] = *(const uint32_t*)&Ksl[r1][col];
            qlo[c][2] = *(const uint32_t*)&Ksl[r0][col + 8];
            qlo[c][3] = *(const uint32_t*)&Ksl[r1][col + 8];
        }
    }

    float o[8][4];
#pragma unroll
    for (int nb = 0; nb < 8; nb++)
#pragma unroll
        for (int c = 0; c < 4; c++) o[nb][c] = 0.f;
    float m0 = -1e30f, m1 = -1e30f, l0 = 0.f, l1 = 0.f;

    const int kb0 = q0 >= WIN ? q0 - WIN : 0;
    const int kb1 = (q0 + 64 + WIN) <= SEQ ? (q0 + 64 + WIN) : SEQ;
    for (int kb = kb0; kb < kb1; kb += 64)
        attn_tile(true, kb, h, q0, tid, wid, g, t, qh, qlo, o, m0, m1, l0, l1,
                  Ksh, Ksl, Vth, Vtl);
    attn_tile(false, 0, h, q0, tid, wid, g, t, qh, qlo, o, m0, m1, l0, l1,
              Ksh, Ksl, Vth, Vtl);

    // ---- epilogue ----
    const float i0 = 1.f / l0, i1 = 1.f / l1;
    const int row0 = q0 + wid * 16 + g;
#pragma unroll
    for (int nb = 0; nb < 8; nb++) {
        float2 w0; w0.x = o[nb][0] * i0; w0.y = o[nb][1] * i0;
        float2 w1; w1.x = o[nb][2] * i1; w1.y = o[nb][3] * i1;
        *(float2*)(g_attn + (size_t)row0 * HID + h * HD + nb * 8 + 2 * t)       = w0;
        *(float2*)(g_attn + (size_t)(row0 + 8) * HID + h * HD + nb * 8 + 2 * t) = w1;
    }
}

// ================= global rows (unchanged) =================
__global__ __launch_bounds__(256) void attn_global() {
    const int gq8 = blockIdx.x;
    const int h   = blockIdx.y;
    const int tid = threadIdx.x;
    const int ql    = tid >> 5;
    const int klane = (tid >> 2) & 7;
    const int part  = tid & 3;
    const int qi    = (gq8 * 8 + ql) * 64;
    const int db    = part * 16;

    __shared__ float Ks[32][68];
    __shared__ float Vs[32][68];
    __shared__ float sm[8][8];
    __shared__ float sl[8][8];
    __shared__ float red[8][8][64];

    u64 q2[8], o2[8];
    {
        const float* qrow = g_qkv + (size_t)qi * H3 + h * HD + db;
#pragma unroll
        for (int i = 0; i < 4; i++) {
            float4 v = *(const float4*)(qrow + i * 4);
            q2[2*i]   = pack2(v.x * 0.125f, v.y * 0.125f);
            q2[2*i+1] = pack2(v.z * 0.125f, v.w * 0.125f);
            o2[2*i] = 0ull; o2[2*i+1] = 0ull;
        }
    }
    float m = -1e30f, l = 0.f;

    for (int kt = 0; kt < SEQ; kt += 32) {
        __syncthreads();
        {
            int idx = tid;
#pragma unroll
            for (int rep = 0; rep < 2; rep++, idx += 256) {
                int r = idx >> 4, c = (idx & 15) << 2;
                const float* src = g_qkv + (size_t)(kt + r) * H3 + HID + h * HD + c;
                *(float4*)&Ks[r][c] = *(const float4*)src;
                *(float4*)&Vs[r][c] = *(const float4*)(src + HID);
            }
        }
        __syncthreads();

        float s[4];
#pragma unroll
        for (int w = 0; w < 4; w++) {
            const int j = klane + 8 * w;
            u64 s2 = 0ull;
#pragma unroll
            for (int i = 0; i < 4; i++) {
                float4 kv = *(const float4*)&Ks[j][db + i * 4];
                s2 = fma2(q2[2*i],   pack2(kv.x, kv.y), s2);
                s2 = fma2(q2[2*i+1], pack2(kv.z, kv.w), s2);
            }
            float slo, shi; unpack2(s2, slo, shi);
            float sv = slo + shi;
            sv += __shfl_xor_sync(0xffffffffu, sv, 1);
            sv += __shfl_xor_sync(0xffffffffu, sv, 2);
            s[w] = sv;
        }
        float tmax = fmaxf(fmaxf(s[0], s[1]), fmaxf(s[2], s[3]));
        const float mn = fmaxf(m, tmax);
        const float c = __expf(m - mn);
        m = mn; l *= c;
        const u64 c2 = dup2(c);
#pragma unroll
        for (int i = 0; i < 8; i++) o2[i] = mul2(o2[i], c2);
#pragma unroll
        for (int w = 0; w < 4; w++) {
            const int j = klane + 8 * w;
            const float p = __expf(s[w] - m);
            l += p;
            const u64 p2 = dup2(p);
#pragma unroll
            for (int i = 0; i < 4; i++) {
                float4 vv = *(const float4*)&Vs[j][db + i * 4];
                o2[2*i]   = fma2(p2, pack2(vv.x, vv.y), o2[2*i]);
                o2[2*i+1] = fma2(p2, pack2(vv.z, vv.w), o2[2*i+1]);
            }
        }
    }

    __syncthreads();
    if (part == 0) { sm[ql][klane] = m; sl[ql][klane] = l; }
    __syncthreads();

    float M = -1e30f;
#pragma unroll
    for (int t2 = 0; t2 < 8; t2++) M = fmaxf(M, sm[ql][t2]);
    const float w = __expf(m - M);
#pragma unroll
    for (int i = 0; i < 8; i++) {
        float a, b;
        unpack2(o2[i], a, b);
        red[ql][klane][db + 2*i]     = a * w;
        red[ql][klane][db + 2*i + 1] = b * w;
    }
    __syncthreads();

    for (int idx = tid; idx < 512; idx += 256) {
        const int ql2 = idx >> 6;
        const int d   = idx & 63;
        float M2 = -1e30f;
#pragma unroll
        for (int t2 = 0; t2 < 8; t2++) M2 = fmaxf(M2, sm[ql2][t2]);
        float L2 = 0.f;
#pragma unroll
        for (int t2 = 0; t2 < 8; t2++) L2 += sl[ql2][t2] * __expf(sm[ql2][t2] - M2);
        float sum = 0.f;
#pragma unroll
        for (int t2 = 0; t2 < 8; t2++) sum += red[ql2][t2][d];
        const int qi2 = (gq8 * 8 + ql2) * 64;
        g_attn[(size_t)qi2 * HID + h * HD + d] = sum / L2;
    }
}

// ---------------- launch ----------------
extern "C" void kernel_launch(void* const* d_in, const int* in_sizes, int n_in,
                              void* d_out, int out_size) {
    const float* x    = (const float*)d_in[0];
    const float* Wqkv = (const float*)d_in[1];
    const float* Wout = (const float*)d_in[2];
    float* out = (float*)d_out;

    float *qkv = nullptr, *attn = nullptr;
    cudaGetSymbolAddress((void**)&qkv,  g_qkv);
    cudaGetSymbolAddress((void**)&attn, g_attn);
    __nv_bfloat16 *x0, *x1, *wq0, *wq1, *a0, *a1, *wo0, *wo1;
    cudaGetSymbolAddress((void**)&x0,  g_x0);  cudaGetSymbolAddress((void**)&x1,  g_x1);
    cudaGetSymbolAddress((void**)&wq0, g_wq0); cudaGetSymbolAddress((void**)&wq1, g_wq1);
    cudaGetSymbolAddress((void**)&a0,  g_a0);  cudaGetSymbolAddress((void**)&a1,  g_a1);
    cudaGetSymbolAddress((void**)&wo0, g_wo0); cudaGetSymbolAddress((void**)&wo1, g_wo1);

    cudaFuncSetAttribute(gemm_mma, cudaFuncAttributeMaxDynamicSharedMemorySize, GT_SMEM);

    // 0) split inputs to bf16 hi/lo
    split_bf16<<<(SEQ * HID / 4 + 255) / 256, 256>>>(x, x0, x1, SEQ * HID / 4);
    split_bf16<<<(H3 * HID / 4 + 255) / 256, 256>>>(Wqkv, wq0, wq1, H3 * HID / 4);
    split_bf16<<<(HID * HID / 4 + 255) / 256, 256>>>(Wout, wo0, wo1, HID * HID / 4);

    // 1) qkv = x @ Wqkv^T  [2048, 3072]
    gemm_mma<<<dim3(H3 / 128, SEQ / 128), 256, GT_SMEM>>>(x0, x1, wq0, wq1, qkv, SEQ, H3, HID);

    // 2) sparse attention -> g_attn (MMA band/global-col, then global rows)
    attn_mma<<<dim3(SEQ / 64, NHEAD), 128>>>();
    attn_global<<<dim3(4, NHEAD), 256>>>();

    // 3) out = attn @ Wout^T  [2048, 1024]
    split_bf16<<<(SEQ * HID / 4 + 255) / 256, 256>>>(attn, a0, a1, SEQ * HID / 4);
    gemm_mma<<<dim3(HID / 128, SEQ / 128), 256, GT_SMEM>>>(a0, a1, wo0, wo1, out, SEQ, HID, HID);
}

// round 8
// speedup vs baseline: 3.7413x; 1.0778x over previous
#include <cuda_runtime.h>
#include <cuda_bf16.h>
#include <cstdint>

// ---------------- problem constants ----------------
#define SEQ   2048
#define HID   1024
#define H3    3072
#define NHEAD 16
#define HD    64
#define WIN   128
#define GSTRIDE 64

typedef unsigned long long u64;

// ---------------- packed f32x2 helpers ----------------
__device__ __forceinline__ u64 fma2(u64 a, u64 b, u64 c) {
    u64 d; asm("fma.rn.f32x2 %0, %1, %2, %3;" : "=l"(d) : "l"(a), "l"(b), "l"(c)); return d;
}
__device__ __forceinline__ u64 mul2(u64 a, u64 b) {
    u64 d; asm("mul.rn.f32x2 %0, %1, %2;" : "=l"(d) : "l"(a), "l"(b)); return d;
}
__device__ __forceinline__ u64 pack2(float lo, float hi) {
    u64 d; asm("mov.b64 %0, {%1, %2};" : "=l"(d) : "f"(lo), "f"(hi)); return d;
}
__device__ __forceinline__ u64 dup2(float x) { return pack2(x, x); }
__device__ __forceinline__ void unpack2(u64 v, float& lo, float& hi) {
    asm("mov.b64 {%0, %1}, %2;" : "=f"(lo), "=f"(hi) : "l"(v));
}

// ---------------- mma / ldmatrix / cp.async helpers ----------------
__device__ __forceinline__ void mma16816(float& c0, float& c1, float& c2, float& c3,
                                         uint32_t a0, uint32_t a1, uint32_t a2, uint32_t a3,
                                         uint32_t b0, uint32_t b1) {
    asm volatile(
        "mma.sync.aligned.m16n8k16.row.col.f32.bf16.bf16.f32 "
        "{%0,%1,%2,%3}, {%4,%5,%6,%7}, {%8,%9}, {%0,%1,%2,%3};"
        : "+f"(c0), "+f"(c1), "+f"(c2), "+f"(c3)
        : "r"(a0), "r"(a1), "r"(a2), "r"(a3), "r"(b0), "r"(b1));
}
__device__ __forceinline__ void ldm_x4(uint32_t& r0, uint32_t& r1, uint32_t& r2, uint32_t& r3,
                                       uint32_t addr) {
    asm volatile("ldmatrix.sync.aligned.m8n8.x4.shared.b16 {%0,%1,%2,%3}, [%4];"
                 : "=r"(r0), "=r"(r1), "=r"(r2), "=r"(r3) : "r"(addr));
}
__device__ __forceinline__ uint32_t smem_u32(const void* p) {
    uint32_t a;
    asm("{ .reg .u64 t; cvta.to.shared.u64 t, %1; cvt.u32.u64 %0, t; }" : "=r"(a) : "l"(p));
    return a;
}
__device__ __forceinline__ void cp16(uint32_t saddr, const void* gptr) {
    asm volatile("cp.async.cg.shared.global [%0], [%1], 16;" :: "r"(saddr), "l"(gptr));
}
#define CP_COMMIT() asm volatile("cp.async.commit_group;" ::: "memory")
#define CP_WAIT1()  asm volatile("cp.async.wait_group 1;" ::: "memory")
#define CP_WAIT0()  asm volatile("cp.async.wait_group 0;" ::: "memory")

// bf16 split helpers
__device__ __forceinline__ void bsplit(float x, __nv_bfloat16& hi, __nv_bfloat16& lo) {
    hi = __float2bfloat16(x);
    lo = __float2bfloat16(x - __bfloat162float(hi));
}
// pack (a,b) as bf16x2 (a low) + bf16x2 of residuals
__device__ __forceinline__ void psplit2(float a, float b, uint32_t& hi, uint32_t& lo) {
    uint32_t hp;
    asm("cvt.rn.bf16x2.f32 %0, %1, %2;" : "=r"(hp) : "f"(b), "f"(a));
    const float ha = __uint_as_float(hp << 16);
    const float hb = __uint_as_float(hp & 0xffff0000u);
    uint32_t lp;
    asm("cvt.rn.bf16x2.f32 %0, %1, %2;" : "=r"(lp) : "f"(b - hb), "f"(a - ha));
    hi = hp; lo = lp;
}

// ---------------- scratch (device globals) ----------------
__device__ float g_qkv[SEQ * H3];
__device__ __align__(16) __nv_bfloat16 g_x0[SEQ * HID],  g_x1[SEQ * HID];
__device__ __align__(16) __nv_bfloat16 g_wq0[H3 * HID],  g_wq1[H3 * HID];
__device__ __align__(16) __nv_bfloat16 g_a0[SEQ * HID],  g_a1[SEQ * HID];
__device__ __align__(16) __nv_bfloat16 g_wo0[HID * HID], g_wo1[HID * HID];
// per-head attention operands (bf16 hi/lo)
__device__ __align__(16) __nv_bfloat16 g_q0[NHEAD * SEQ * 64], g_q1[NHEAD * SEQ * 64];
__device__ __align__(16) __nv_bfloat16 g_k0[NHEAD * SEQ * 64], g_k1[NHEAD * SEQ * 64];
__device__ __align__(16) __nv_bfloat16 g_vt0[NHEAD * 64 * SEQ], g_vt1[NHEAD * 64 * SEQ];
__device__ __align__(16) __nv_bfloat16 g_kg0[NHEAD * 32 * 64], g_kg1[NHEAD * 32 * 64];
__device__ __align__(16) __nv_bfloat16 g_vtg0[NHEAD * 64 * 32], g_vtg1[NHEAD * 64 * 32];

// ---------------- fp32 -> (bf16 hi, bf16 lo) split ----------------
__global__ __launch_bounds__(256) void split_bf16(const float* __restrict__ in,
                                                  __nv_bfloat16* __restrict__ hi,
                                                  __nv_bfloat16* __restrict__ lo,
                                                  int n4) {
    int i = blockIdx.x * blockDim.x + threadIdx.x;
    if (i >= n4) return;
    float4 v = ((const float4*)in)[i];
    uint32_t h0, l0, h1, l1;
    psplit2(v.x, v.y, h0, l0);
    psplit2(v.z, v.w, h1, l1);
    uint32_t* hp = (uint32_t*)hi;
    uint32_t* lp = (uint32_t*)lo;
    hp[2 * i] = h0; hp[2 * i + 1] = h1;
    lp[2 * i] = l0; lp[2 * i + 1] = l1;
}

// ---------------- tensor-core GEMM (unchanged) ----------------
#define SSTR 40
#define BUFE (128 * SSTR)
#define STGE (4 * BUFE)
#define GT_SMEM (2 * STGE * 2)

__global__ __launch_bounds__(256) void gemm_mma(const __nv_bfloat16* __restrict__ A0g,
                                                const __nv_bfloat16* __restrict__ A1g,
                                                const __nv_bfloat16* __restrict__ B0g,
                                                const __nv_bfloat16* __restrict__ B1g,
                                                float* __restrict__ C,
                                                int M, int N, int K) {
    extern __shared__ __nv_bfloat16 smg[];
    const uint32_t sbase = smem_u32(smg);

    const int tid = threadIdx.x;
    const int wid = tid >> 5;
    const int lane = tid & 31;
    const int g = lane >> 2;
    const int t = lane & 3;
    const int warp_m = (wid & 1) * 64;
    const int warp_n = (wid >> 1) * 32;
    const int tile_m = blockIdx.y * 128;
    const int tile_n = blockIdx.x * 128;

    const int a_row = warp_m + ((lane >> 3) & 1) * 8 + (lane & 7);
    const int a_col = (lane >> 4) * 8;
    const int b_row = warp_n + (lane >> 4) * 8 + (lane & 7);
    const int b_col = ((lane >> 3) & 1) * 8;

    float acc[4][4][4];
#pragma unroll
    for (int im = 0; im < 4; im++)
#pragma unroll
        for (int jn = 0; jn < 4; jn++)
#pragma unroll
            for (int c = 0; c < 4; c++) acc[im][jn][c] = 0.f;

    const int srow = tid >> 2;
    const int sc16 = (tid & 3) * 8;

    auto load_stage = [&](int st, int k0) {
        const uint32_t sb = sbase + (uint32_t)st * STGE * 2;
#pragma unroll
        for (int rep = 0; rep < 2; rep++) {
            const int row = srow + rep * 64;
            const uint32_t so = (uint32_t)(row * SSTR + sc16) * 2;
            const size_t goA = (size_t)(tile_m + row) * K + k0 + sc16;
            const size_t goB = (size_t)(tile_n + row) * K + k0 + sc16;
            cp16(sb + 0 * BUFE * 2 + so, A0g + goA);
            cp16(sb + 1 * BUFE * 2 + so, A1g + goA);
            cp16(sb + 2 * BUFE * 2 + so, B0g + goB);
            cp16(sb + 3 * BUFE * 2 + so, B1g + goB);
        }
    };

    const int nchunks = K >> 5;
    load_stage(0, 0);
    CP_COMMIT();

    for (int ch = 0; ch < nchunks; ch++) {
        if (ch + 1 < nchunks) load_stage((ch + 1) & 1, (ch + 1) << 5);
        CP_COMMIT();
        CP_WAIT1();
        __syncthreads();

        const uint32_t sb = sbase + (uint32_t)(ch & 1) * STGE * 2;
#pragma unroll
        for (int ks = 0; ks < 32; ks += 16) {
            uint32_t aH[4][4], aL[4][4], bH[4][2], bL[4][2];
#pragma unroll
            for (int im = 0; im < 4; im++) {
                const uint32_t ad = sb + (uint32_t)((a_row + im * 16) * SSTR + ks + a_col) * 2;
                ldm_x4(aH[im][0], aH[im][1], aH[im][2], aH[im][3], ad);
                ldm_x4(aL[im][0], aL[im][1], aL[im][2], aL[im][3], ad + BUFE * 2);
            }
#pragma unroll
            for (int jp = 0; jp < 2; jp++) {
                const uint32_t bd = sb + 2 * BUFE * 2
                                  + (uint32_t)((b_row + jp * 16) * SSTR + ks + b_col) * 2;
                ldm_x4(bH[2 * jp][0], bH[2 * jp][1], bH[2 * jp + 1][0], bH[2 * jp + 1][1], bd);
                ldm_x4(bL[2 * jp][0], bL[2 * jp][1], bL[2 * jp + 1][0], bL[2 * jp + 1][1], bd + BUFE * 2);
            }
#pragma unroll
            for (int im = 0; im < 4; im++)
#pragma unroll
                for (int jn = 0; jn < 4; jn++) {
                    float* a = acc[im][jn];
                    mma16816(a[0], a[1], a[2], a[3],
                             aH[im][0], aH[im][1], aH[im][2], aH[im][3],
                             bH[jn][0], bH[jn][1]);
                    mma16816(a[0], a[1], a[2], a[3],
                             aH[im][0], aH[im][1], aH[im][2], aH[im][3],
                             bL[jn][0], bL[jn][1]);
                    mma16816(a[0], a[1], a[2], a[3],
                             aL[im][0], aL[im][1], aL[im][2], aL[im][3],
                             bH[jn][0], bH[jn][1]);
                }
        }
        __syncthreads();
    }

#pragma unroll
    for (int im = 0; im < 4; im++) {
        const int row = tile_m + warp_m + im * 16 + g;
#pragma unroll
        for (int jn = 0; jn < 4; jn++) {
            const int col = tile_n + warp_n + jn * 8 + 2 * t;
            float2 v0; v0.x = acc[im][jn][0]; v0.y = acc[im][jn][1];
            float2 v1; v1.x = acc[im][jn][2]; v1.y = acc[im][jn][3];
            *(float2*)(C + (size_t)row * N + col)       = v0;
            *(float2*)(C + (size_t)(row + 8) * N + col) = v1;
        }
    }
}

// ---------------- prep: build per-head bf16 split Q/K/Vt (+ compact globals) ----------------
__global__ __launch_bounds__(256) void prep_attn() {
    const int st = blockIdx.x;      // seq tile 0..31
    const int h  = blockIdx.y;      // head
    const int s0 = st * 64;
    const int tid = threadIdx.x;

    __shared__ __nv_bfloat16 vth[64][72], vtl[64][72];

    for (int idx = tid; idx < 1024; idx += 256) {
        const int r = idx >> 4, c4 = (idx & 15) << 2;
        const size_t base = (size_t)(s0 + r) * H3 + h * HD + c4;
        uint32_t h0, l0, h1, l1;
        // Q (scaled)
        float4 q = *(const float4*)(g_qkv + base);
        psplit2(q.x * 0.125f, q.y * 0.125f, h0, l0);
        psplit2(q.z * 0.125f, q.w * 0.125f, h1, l1);
        const size_t qo = (size_t)h * SEQ * 64 + (size_t)(s0 + r) * 64 + c4;
        *(uint32_t*)&g_q0[qo] = h0; *(uint32_t*)&g_q0[qo + 2] = h1;
        *(uint32_t*)&g_q1[qo] = l0; *(uint32_t*)&g_q1[qo + 2] = l1;
        // K
        float4 k = *(const float4*)(g_qkv + base + HID);
        psplit2(k.x, k.y, h0, l0);
        psplit2(k.z, k.w, h1, l1);
        *(uint32_t*)&g_k0[qo] = h0; *(uint32_t*)&g_k0[qo + 2] = h1;
        *(uint32_t*)&g_k1[qo] = l0; *(uint32_t*)&g_k1[qo + 2] = l1;
        // V -> transposed smem
        float4 v = *(const float4*)(g_qkv + base + 2 * HID);
        bsplit(v.x, vth[c4 + 0][r], vtl[c4 + 0][r]);
        bsplit(v.y, vth[c4 + 1][r], vtl[c4 + 1][r]);
        bsplit(v.z, vth[c4 + 2][r], vtl[c4 + 2][r]);
        bsplit(v.w, vth[c4 + 3][r], vtl[c4 + 3][r]);
    }
    __syncthreads();

    // write Vt rows (coalesced)
    for (int idx = tid; idx < 2048; idx += 256) {
        const int d = idx >> 5, cp = (idx & 31) << 1;
        const size_t vo = (size_t)h * 64 * SEQ + (size_t)d * SEQ + s0 + cp;
        *(uint32_t*)&g_vt0[vo] = *(const uint32_t*)&vth[d][cp];
        *(uint32_t*)&g_vt1[vo] = *(const uint32_t*)&vtl[d][cp];
    }
    // compact global-key copies (global key index = st, row s0)
    if (tid < 16) {
        const int c4 = tid * 4;
        float4 k = *(const float4*)(g_qkv + (size_t)s0 * H3 + HID + h * HD + c4);
        uint32_t h0, l0, h1, l1;
        psplit2(k.x, k.y, h0, l0);
        psplit2(k.z, k.w, h1, l1);
        const size_t ko = (size_t)h * 32 * 64 + (size_t)st * 64 + c4;
        *(uint32_t*)&g_kg0[ko] = h0; *(uint32_t*)&g_kg0[ko + 2] = h1;
        *(uint32_t*)&g_kg1[ko] = l0; *(uint32_t*)&g_kg1[ko + 2] = l1;
    }
    if (tid < 64) {
        const size_t go = (size_t)h * 64 * 32 + (size_t)tid * 32 + st;
        g_vtg0[go] = vth[tid][0];
        g_vtg1[go] = vtl[tid][0];
    }
}

// ================= MMA flash attention v2 =================
#define MASKV (-3.0e38f)
#define ATS   72
#define ATILE (64 * ATS)                      // elems per tile buffer
#define AT_SMEM ((2 + 8) * ATILE * 2)         // Q(hi/lo) + 2 stages x 4 tiles

template<int NKT>
__device__ __forceinline__ void attn_compute(
    uint32_t sKh, uint32_t sVh, int kb, bool isGlob,
    int q0, int wid, int g, int t, int brow, int bcol,
    const uint32_t qh[4][4], const uint32_t qlo[4][4],
    float o[8][4], float& m0, float& m1, float& l0, float& l1)
{
    constexpr int NJ = NKT / 8;
    float sc[NJ][4];

    // ---- S = Q K^T ----
#pragma unroll
    for (int jp = 0; jp < NKT / 16; jp++) {
#pragma unroll
        for (int e = 0; e < 4; e++) { sc[2 * jp][e] = 0.f; sc[2 * jp + 1][e] = 0.f; }
#pragma unroll
        for (int c = 0; c < 4; c++) {
            uint32_t b0, b1, b2, b3, d0, d1, d2, d3;
            const uint32_t ka = sKh + (uint32_t)((jp * 16 + brow) * ATS + c * 16 + bcol) * 2;
            ldm_x4(b0, b1, b2, b3, ka);
            ldm_x4(d0, d1, d2, d3, ka + ATILE * 2);
            float* s0p = sc[2 * jp];
            float* s1p = sc[2 * jp + 1];
            mma16816(s0p[0], s0p[1], s0p[2], s0p[3],
                     qh[c][0], qh[c][1], qh[c][2], qh[c][3], b0, b1);
            mma16816(s0p[0], s0p[1], s0p[2], s0p[3],
                     qh[c][0], qh[c][1], qh[c][2], qh[c][3], d0, d1);
            mma16816(s0p[0], s0p[1], s0p[2], s0p[3],
                     qlo[c][0], qlo[c][1], qlo[c][2], qlo[c][3], b0, b1);
            mma16816(s1p[0], s1p[1], s1p[2], s1p[3],
                     qh[c][0], qh[c][1], qh[c][2], qh[c][3], b2, b3);
            mma16816(s1p[0], s1p[1], s1p[2], s1p[3],
                     qh[c][0], qh[c][1], qh[c][2], qh[c][3], d2, d3);
            mma16816(s1p[0], s1p[1], s1p[2], s1p[3],
                     qlo[c][0], qlo[c][1], qlo[c][2], qlo[c][3], b2, b3);
        }
    }

    // ---- mask + row max ----
    const int qr0 = q0 + wid * 16 + g;
    const int qr1 = qr0 + 8;
    float tm0 = MASKV, tm1 = MASKV;
#pragma unroll
    for (int jn = 0; jn < NJ; jn++) {
#pragma unroll
        for (int e = 0; e < 2; e++) {
            const int ci  = jn * 8 + 2 * t + e;
            const int key = isGlob ? (ci * GSTRIDE) : (kb + ci);
            int d0 = qr0 - key; d0 = d0 < 0 ? -d0 : d0;
            int d1 = qr1 - key; d1 = d1 < 0 ? -d1 : d1;
            const bool in0 = isGlob ? (d0 > WIN) : (d0 <= WIN);
            const bool in1 = isGlob ? (d1 > WIN) : (d1 <= WIN);
            if (!in0) sc[jn][e]     = MASKV;
            if (!in1) sc[jn][2 + e] = MASKV;
            tm0 = fmaxf(tm0, sc[jn][e]);
            tm1 = fmaxf(tm1, sc[jn][2 + e]);
        }
    }
    tm0 = fmaxf(tm0, __shfl_xor_sync(0xffffffffu, tm0, 1));
    tm0 = fmaxf(tm0, __shfl_xor_sync(0xffffffffu, tm0, 2));
    tm1 = fmaxf(tm1, __shfl_xor_sync(0xffffffffu, tm1, 1));
    tm1 = fmaxf(tm1, __shfl_xor_sync(0xffffffffu, tm1, 2));

    const float mn0 = fmaxf(m0, tm0), mn1 = fmaxf(m1, tm1);
    const float e0 = __expf(m0 - mn0), e1 = __expf(m1 - mn1);
    m0 = mn0; m1 = mn1; l0 *= e0; l1 *= e1;
#pragma unroll
    for (int nb = 0; nb < 8; nb++) {
        o[nb][0] *= e0; o[nb][1] *= e0; o[nb][2] *= e1; o[nb][3] *= e1;
    }

    // ---- P = exp(S - m); O += P V ----
    float s0 = 0.f, s1 = 0.f;
#pragma unroll
    for (int c = 0; c < NKT / 16; c++) {
        const float p00 = __expf(sc[2 * c][0] - m0);
        const float p01 = __expf(sc[2 * c][1] - m0);
        const float p02 = __expf(sc[2 * c][2] - m1);
        const float p03 = __expf(sc[2 * c][3] - m1);
        const float p10 = __expf(sc[2 * c + 1][0] - m0);
        const float p11 = __expf(sc[2 * c + 1][1] - m0);
        const float p12 = __expf(sc[2 * c + 1][2] - m1);
        const float p13 = __expf(sc[2 * c + 1][3] - m1);
        s0 += (p00 + p01) + (p10 + p11);
        s1 += (p02 + p03) + (p12 + p13);
        uint32_t ah[4], al[4];
        psplit2(p00, p01, ah[0], al[0]);
        psplit2(p02, p03, ah[1], al[1]);
        psplit2(p10, p11, ah[2], al[2]);
        psplit2(p12, p13, ah[3], al[3]);
#pragma unroll
        for (int np = 0; np < 4; np++) {
            uint32_t v0, v1, v2, v3, w0, w1, w2, w3;
            const uint32_t va = sVh + (uint32_t)((np * 16 + brow) * ATS + c * 16 + bcol) * 2;
            ldm_x4(v0, v1, v2, v3, va);
            ldm_x4(w0, w1, w2, w3, va + ATILE * 2);
            float* oa = o[2 * np];
            float* ob = o[2 * np + 1];
            mma16816(oa[0], oa[1], oa[2], oa[3], ah[0], ah[1], ah[2], ah[3], v0, v1);
            mma16816(oa[0], oa[1], oa[2], oa[3], ah[0], ah[1], ah[2], ah[3], w0, w1);
            mma16816(oa[0], oa[1], oa[2], oa[3], al[0], al[1], al[2], al[3], v0, v1);
            mma16816(ob[0], ob[1], ob[2], ob[3], ah[0], ah[1], ah[2], ah[3], v2, v3);
            mma16816(ob[0], ob[1], ob[2], ob[3], ah[0], ah[1], ah[2], ah[3], w2, w3);
            mma16816(ob[0], ob[1], ob[2], ob[3], al[0], al[1], al[2], al[3], v2, v3);
        }
    }
    s0 += __shfl_xor_sync(0xffffffffu, s0, 1);
    s0 += __shfl_xor_sync(0xffffffffu, s0, 2);
    s1 += __shfl_xor_sync(0xffffffffu, s1, 1);
    s1 += __shfl_xor_sync(0xffffffffu, s1, 2);
    l0 += s0; l1 += s1;
}

__global__ __launch_bounds__(128) void attn_mma() {
    extern __shared__ __nv_bfloat16 sm_[];
    const uint32_t sb = smem_u32(sm_);
    const uint32_t sQh = sb, sQl = sb + ATILE * 2;

    const int qt = blockIdx.x, h = blockIdx.y, q0 = qt * 64;
    const int tid = threadIdx.x, wid = tid >> 5, lane = tid & 31;
    const int g = lane >> 2, t = lane & 3;
    const int brow = ((lane >> 4) << 3) + (lane & 7);
    const int bcol = ((lane >> 3) & 1) * 8;

    // ---- stage Q (group 0) ----
    {
        const __nv_bfloat16* q0p = g_q0 + (size_t)h * SEQ * 64 + (size_t)q0 * 64;
        const __nv_bfloat16* q1p = g_q1 + (size_t)h * SEQ * 64 + (size_t)q0 * 64;
        for (int idx = tid; idx < 512; idx += 128) {
            const int r = idx >> 3, c = idx & 7;
            const uint32_t so = (uint32_t)(r * ATS + c * 8) * 2;
            cp16(sQh + so, q0p + r * 64 + c * 8);
            cp16(sQl + so, q1p + r * 64 + c * 8);
        }
    }
    CP_COMMIT();

    const int kb0 = q0 >= WIN ? q0 - WIN : 0;
    const int kb1 = (q0 + 64 + WIN) <= SEQ ? (q0 + 64 + WIN) : SEQ;
    const int nband = (kb1 - kb0) >> 6;
    const int T = nband + 1;

    auto stage_base = [&](int s) { return sb + (uint32_t)(2 + 4 * s) * ATILE * 2; };
    auto stage_band = [&](int s, int kb) {
        const uint32_t b = stage_base(s);
        const __nv_bfloat16* k0p = g_k0 + (size_t)h * SEQ * 64 + (size_t)kb * 64;
        const __nv_bfloat16* k1p = g_k1 + (size_t)h * SEQ * 64 + (size_t)kb * 64;
        const __nv_bfloat16* v0p = g_vt0 + (size_t)h * 64 * SEQ + kb;
        const __nv_bfloat16* v1p = g_vt1 + (size_t)h * 64 * SEQ + kb;
        for (int idx = tid; idx < 512; idx += 128) {
            const int r = idx >> 3, c = idx & 7;
            const uint32_t so = (uint32_t)(r * ATS + c * 8) * 2;
            cp16(b + so,                 k0p + r * 64 + c * 8);
            cp16(b + ATILE * 2 + so,     k1p + r * 64 + c * 8);
            cp16(b + 2 * ATILE * 2 + so, v0p + (size_t)r * SEQ + c * 8);
            cp16(b + 3 * ATILE * 2 + so, v1p + (size_t)r * SEQ + c * 8);
        }
    };
    auto stage_glob = [&](int s) {
        const uint32_t b = stage_base(s);
        const __nv_bfloat16* k0p = g_kg0 + (size_t)h * 32 * 64;
        const __nv_bfloat16* k1p = g_kg1 + (size_t)h * 32 * 64;
        const __nv_bfloat16* v0p = g_vtg0 + (size_t)h * 64 * 32;
        const __nv_bfloat16* v1p = g_vtg1 + (size_t)h * 64 * 32;
        for (int idx = tid; idx < 256; idx += 128) {
            const int r = idx >> 3, c = idx & 7;
            const uint32_t so = (uint32_t)(r * ATS + c * 8) * 2;
            cp16(b + so,             k0p + r * 64 + c * 8);
            cp16(b + ATILE * 2 + so, k1p + r * 64 + c * 8);
        }
        for (int idx = tid; idx < 256; idx += 128) {
            const int r = idx >> 2, c = idx & 3;
            const uint32_t so = (uint32_t)(r * ATS + c * 8) * 2;
            cp16(b + 2 * ATILE * 2 + so, v0p + r * 32 + c * 8);
            cp16(b + 3 * ATILE * 2 + so, v1p + r * 32 + c * 8);
        }
    };

    stage_band(0, kb0);
    CP_COMMIT();
    CP_WAIT1();          // Q group done
    __syncthreads();

    // ---- Q fragments ----
    uint32_t qh[4][4], qlo[4][4];
    {
        const int ar = wid * 16 + ((lane >> 3) & 1) * 8 + (lane & 7);
        const int ac = (lane >> 4) * 8;
#pragma unroll
        for (int c = 0; c < 4; c++) {
            const uint32_t ad = sQh + (uint32_t)(ar * ATS + c * 16 + ac) * 2;
            ldm_x4(qh[c][0], qh[c][1], qh[c][2], qh[c][3], ad);
            ldm_x4(qlo[c][0], qlo[c][1], qlo[c][2], qlo[c][3], ad + ATILE * 2);
        }
    }

    float o[8][4];
#pragma unroll
    for (int nb = 0; nb < 8; nb++)
#pragma unroll
        for (int c = 0; c < 4; c++) o[nb][c] = 0.f;
    float m0 = -1e30f, m1 = -1e30f, l0 = 0.f, l1 = 0.f;

    for (int i = 0; i < T; i++) {
        if (i + 1 < T) {
            if (i + 1 < nband) stage_band((i + 1) & 1, kb0 + (i + 1) * 64);
            else stage_glob((i + 1) & 1);
            CP_COMMIT();
            CP_WAIT1();
        } else {
            CP_WAIT0();
        }
        __syncthreads();
        const uint32_t b = stage_base(i & 1);
        if (i < nband)
            attn_compute<64>(b, b + 2 * ATILE * 2, kb0 + i * 64, false,
                             q0, wid, g, t, brow, bcol, qh, qlo, o, m0, m1, l0, l1);
        else
            attn_compute<32>(b, b + 2 * ATILE * 2, 0, true,
                             q0, wid, g, t, brow, bcol, qh, qlo, o, m0, m1, l0, l1);
        __syncthreads();
    }

    // ---- epilogue: split-write directly to a0/a1 ----
    const float i0 = 1.f / l0, i1 = 1.f / l1;
    const int row0 = q0 + wid * 16 + g;
#pragma unroll
    for (int nb = 0; nb < 8; nb++) {
        uint32_t h0, lo0, h1, lo1;
        psplit2(o[nb][0] * i0, o[nb][1] * i0, h0, lo0);
        psplit2(o[nb][2] * i1, o[nb][3] * i1, h1, lo1);
        const size_t ofs0 = (size_t)row0 * HID + h * HD + nb * 8 + 2 * t;
        const size_t ofs1 = ofs0 + (size_t)8 * HID;
        *(uint32_t*)&g_a0[ofs0] = h0; *(uint32_t*)&g_a1[ofs0] = lo0;
        *(uint32_t*)&g_a0[ofs1] = h1; *(uint32_t*)&g_a1[ofs1] = lo1;
    }
}

// ================= global rows (scalar; writes split output) =================
__global__ __launch_bounds__(256) void attn_global() {
    const int gq8 = blockIdx.x;
    const int h   = blockIdx.y;
    const int tid = threadIdx.x;
    const int ql    = tid >> 5;
    const int klane = (tid >> 2) & 7;
    const int part  = tid & 3;
    const int qi    = (gq8 * 8 + ql) * 64;
    const int db    = part * 16;

    __shared__ float Ks[32][68];
    __shared__ float Vs[32][68];
    __shared__ float sm[8][8];
    __shared__ float sl[8][8];
    __shared__ float red[8][8][64];

    u64 q2[8], o2[8];
    {
        const float* qrow = g_qkv + (size_t)qi * H3 + h * HD + db;
#pragma unroll
        for (int i = 0; i < 4; i++) {
            float4 v = *(const float4*)(qrow + i * 4);
            q2[2*i]   = pack2(v.x * 0.125f, v.y * 0.125f);
            q2[2*i+1] = pack2(v.z * 0.125f, v.w * 0.125f);
            o2[2*i] = 0ull; o2[2*i+1] = 0ull;
        }
    }
    float m = -1e30f, l = 0.f;

    for (int kt = 0; kt < SEQ; kt += 32) {
        __syncthreads();
        {
            int idx = tid;
#pragma unroll
            for (int rep = 0; rep < 2; rep++, idx += 256) {
                int r = idx >> 4, c = (idx & 15) << 2;
                const float* src = g_qkv + (size_t)(kt + r) * H3 + HID + h * HD + c;
                *(float4*)&Ks[r][c] = *(const float4*)src;
                *(float4*)&Vs[r][c] = *(const float4*)(src + HID);
            }
        }
        __syncthreads();

        float s[4];
#pragma unroll
        for (int w = 0; w < 4; w++) {
            const int j = klane + 8 * w;
            u64 s2 = 0ull;
#pragma unroll
            for (int i = 0; i < 4; i++) {
                float4 kv = *(const float4*)&Ks[j][db + i * 4];
                s2 = fma2(q2[2*i],   pack2(kv.x, kv.y), s2);
                s2 = fma2(q2[2*i+1], pack2(kv.z, kv.w), s2);
            }
            float slo, shi; unpack2(s2, slo, shi);
            float sv = slo + shi;
            sv += __shfl_xor_sync(0xffffffffu, sv, 1);
            sv += __shfl_xor_sync(0xffffffffu, sv, 2);
            s[w] = sv;
        }
        float tmax = fmaxf(fmaxf(s[0], s[1]), fmaxf(s[2], s[3]));
        const float mn = fmaxf(m, tmax);
        const float c = __expf(m - mn);
        m = mn; l *= c;
        const u64 c2 = dup2(c);
#pragma unroll
        for (int i = 0; i < 8; i++) o2[i] = mul2(o2[i], c2);
#pragma unroll
        for (int w = 0; w < 4; w++) {
            const int j = klane + 8 * w;
            const float p = __expf(s[w] - m);
            l += p;
            const u64 p2 = dup2(p);
#pragma unroll
            for (int i = 0; i < 4; i++) {
                float4 vv = *(const float4*)&Vs[j][db + i * 4];
                o2[2*i]   = fma2(p2, pack2(vv.x, vv.y), o2[2*i]);
                o2[2*i+1] = fma2(p2, pack2(vv.z, vv.w), o2[2*i+1]);
            }
        }
    }

    __syncthreads();
    if (part == 0) { sm[ql][klane] = m; sl[ql][klane] = l; }
    __syncthreads();

    float M = -1e30f;
#pragma unroll
    for (int t2 = 0; t2 < 8; t2++) M = fmaxf(M, sm[ql][t2]);
    const float w = __expf(m - M);
#pragma unroll
    for (int i = 0; i < 8; i++) {
        float a, b;
        unpack2(o2[i], a, b);
        red[ql][klane][db + 2*i]     = a * w;
        red[ql][klane][db + 2*i + 1] = b * w;
    }
    __syncthreads();

    for (int idx = tid; idx < 512; idx += 256) {
        const int ql2 = idx >> 6;
        const int d   = idx & 63;
        float M2 = -1e30f;
#pragma unroll
        for (int t2 = 0; t2 < 8; t2++) M2 = fmaxf(M2, sm[ql2][t2]);
        float L2 = 0.f;
#pragma unroll
        for (int t2 = 0; t2 < 8; t2++) L2 += sl[ql2][t2] * __expf(sm[ql2][t2] - M2);
        float sum = 0.f;
#pragma unroll
        for (int t2 = 0; t2 < 8; t2++) sum += red[ql2][t2][d];
        const int qi2 = (gq8 * 8 + ql2) * 64;
        const float val = sum / L2;
        const size_t ofs = (size_t)qi2 * HID + h * HD + d;
        __nv_bfloat16 hi, lo;
        bsplit(val, hi, lo);
        g_a0[ofs] = hi;
        g_a1[ofs] = lo;
    }
}

// ---------------- launch ----------------
extern "C" void kernel_launch(void* const* d_in, const int* in_sizes, int n_in,
                              void* d_out, int out_size) {
    const float* x    = (const float*)d_in[0];
    const float* Wqkv = (const float*)d_in[1];
    const float* Wout = (const float*)d_in[2];
    float* out = (float*)d_out;

    float* qkv = nullptr;
    cudaGetSymbolAddress((void**)&qkv, g_qkv);
    __nv_bfloat16 *x0, *x1, *wq0, *wq1, *a0, *a1, *wo0, *wo1;
    cudaGetSymbolAddress((void**)&x0,  g_x0);  cudaGetSymbolAddress((void**)&x1,  g_x1);
    cudaGetSymbolAddress((void**)&wq0, g_wq0); cudaGetSymbolAddress((void**)&wq1, g_wq1);
    cudaGetSymbolAddress((void**)&a0,  g_a0);  cudaGetSymbolAddress((void**)&a1,  g_a1);
    cudaGetSymbolAddress((void**)&wo0, g_wo0); cudaGetSymbolAddress((void**)&wo1, g_wo1);

    cudaFuncSetAttribute(gemm_mma, cudaFuncAttributeMaxDynamicSharedMemorySize, GT_SMEM);
    cudaFuncSetAttribute(attn_mma, cudaFuncAttributeMaxDynamicSharedMemorySize, AT_SMEM);

    // 0) split inputs to bf16 hi/lo
    split_bf16<<<(SEQ * HID / 4 + 255) / 256, 256>>>(x, x0, x1, SEQ * HID / 4);
    split_bf16<<<(H3 * HID / 4 + 255) / 256, 256>>>(Wqkv, wq0, wq1, H3 * HID / 4);
    split_bf16<<<(HID * HID / 4 + 255) / 256, 256>>>(Wout, wo0, wo1, HID * HID / 4);

    // 1) qkv = x @ Wqkv^T
    gemm_mma<<<dim3(H3 / 128, SEQ / 128), 256, GT_SMEM>>>(x0, x1, wq0, wq1, qkv, SEQ, H3, HID);

    // 2) prep per-head bf16 split operands
    prep_attn<<<dim3(SEQ / 64, NHEAD), 256>>>();

    // 3) sparse attention -> g_a0/g_a1 (bf16 split, fused)
    attn_mma<<<dim3(SEQ / 64, NHEAD), 128, AT_SMEM>>>();
    attn_global<<<dim3(4, NHEAD), 256>>>();

    // 4) out = attn @ Wout^T
    gemm_mma<<<dim3(HID / 128, SEQ / 128), 256, GT_SMEM>>>(a0, a1, wo0, wo1, out, SEQ, HID, HID);
}

// round 9
// speedup vs baseline: 4.1767x; 1.1164x over previous
#include <cuda_runtime.h>
#include <cuda_bf16.h>
#include <cstdint>

// ---------------- problem constants ----------------
#define SEQ   2048
#define HID   1024
#define H3    3072
#define NHEAD 16
#define HD    64
#define WIN   128
#define GSTRIDE 64

typedef unsigned long long u64;

// ---------------- mma / ldmatrix / cp.async helpers ----------------
__device__ __forceinline__ void mma16816(float& c0, float& c1, float& c2, float& c3,
                                         uint32_t a0, uint32_t a1, uint32_t a2, uint32_t a3,
                                         uint32_t b0, uint32_t b1) {
    asm volatile(
        "mma.sync.aligned.m16n8k16.row.col.f32.bf16.bf16.f32 "
        "{%0,%1,%2,%3}, {%4,%5,%6,%7}, {%8,%9}, {%0,%1,%2,%3};"
        : "+f"(c0), "+f"(c1), "+f"(c2), "+f"(c3)
        : "r"(a0), "r"(a1), "r"(a2), "r"(a3), "r"(b0), "r"(b1));
}
__device__ __forceinline__ void ldm_x4(uint32_t& r0, uint32_t& r1, uint32_t& r2, uint32_t& r3,
                                       uint32_t addr) {
    asm volatile("ldmatrix.sync.aligned.m8n8.x4.shared.b16 {%0,%1,%2,%3}, [%4];"
                 : "=r"(r0), "=r"(r1), "=r"(r2), "=r"(r3) : "r"(addr));
}
__device__ __forceinline__ uint32_t smem_u32(const void* p) {
    uint32_t a;
    asm("{ .reg .u64 t; cvta.to.shared.u64 t, %1; cvt.u32.u64 %0, t; }" : "=r"(a) : "l"(p));
    return a;
}
__device__ __forceinline__ void cp16(uint32_t saddr, const void* gptr) {
    asm volatile("cp.async.cg.shared.global [%0], [%1], 16;" :: "r"(saddr), "l"(gptr));
}
#define CP_COMMIT() asm volatile("cp.async.commit_group;" ::: "memory")
#define CP_WAIT1()  asm volatile("cp.async.wait_group 1;" ::: "memory")
#define CP_WAIT0()  asm volatile("cp.async.wait_group 0;" ::: "memory")

// bf16 split helpers
__device__ __forceinline__ void bsplit(float x, __nv_bfloat16& hi, __nv_bfloat16& lo) {
    hi = __float2bfloat16(x);
    lo = __float2bfloat16(x - __bfloat162float(hi));
}
__device__ __forceinline__ void psplit2(float a, float b, uint32_t& hi, uint32_t& lo) {
    uint32_t hp;
    asm("cvt.rn.bf16x2.f32 %0, %1, %2;" : "=r"(hp) : "f"(b), "f"(a));
    const float ha = __uint_as_float(hp << 16);
    const float hb = __uint_as_float(hp & 0xffff0000u);
    uint32_t lp;
    asm("cvt.rn.bf16x2.f32 %0, %1, %2;" : "=r"(lp) : "f"(b - hb), "f"(a - ha));
    hi = hp; lo = lp;
}

// ---------------- scratch (device globals) ----------------
__device__ float g_qkv[SEQ * H3];
__device__ __align__(16) __nv_bfloat16 g_x0[SEQ * HID],  g_x1[SEQ * HID];
__device__ __align__(16) __nv_bfloat16 g_wq0[H3 * HID],  g_wq1[H3 * HID];
__device__ __align__(16) __nv_bfloat16 g_a0[SEQ * HID],  g_a1[SEQ * HID];
__device__ __align__(16) __nv_bfloat16 g_wo0[HID * HID], g_wo1[HID * HID];
__device__ __align__(16) __nv_bfloat16 g_q0[NHEAD * SEQ * 64], g_q1[NHEAD * SEQ * 64];
__device__ __align__(16) __nv_bfloat16 g_k0[NHEAD * SEQ * 64], g_k1[NHEAD * SEQ * 64];
__device__ __align__(16) __nv_bfloat16 g_vt0[NHEAD * 64 * SEQ], g_vt1[NHEAD * 64 * SEQ];
__device__ __align__(16) __nv_bfloat16 g_kg0[NHEAD * 32 * 64], g_kg1[NHEAD * 32 * 64];
__device__ __align__(16) __nv_bfloat16 g_vtg0[NHEAD * 64 * 32], g_vtg1[NHEAD * 64 * 32];

// ---------------- fp32 -> (bf16 hi, bf16 lo) split ----------------
__global__ __launch_bounds__(256) void split_bf16(const float* __restrict__ in,
                                                  __nv_bfloat16* __restrict__ hi,
                                                  __nv_bfloat16* __restrict__ lo,
                                                  int n4) {
    int i = blockIdx.x * blockDim.x + threadIdx.x;
    if (i >= n4) return;
    float4 v = ((const float4*)in)[i];
    uint32_t h0, l0, h1, l1;
    psplit2(v.x, v.y, h0, l0);
    psplit2(v.z, v.w, h1, l1);
    uint32_t* hp = (uint32_t*)hi;
    uint32_t* lp = (uint32_t*)lo;
    hp[2 * i] = h0; hp[2 * i + 1] = h1;
    lp[2 * i] = l0; lp[2 * i + 1] = l1;
}

// ---------------- tensor-core GEMM v4: 64x64 warp tiles ----------------
// C[M,N] = A[M,K] @ B[N,K]^T, 2-way bf16 split, 3 MMA terms.
// 128x128 CTA tile, 4 warps (2x2), warp tile 64x64, BK=32, 2 smem stages.
#define SSTR 40
#define BUFE (128 * SSTR)
#define STGE (4 * BUFE)
#define GT_SMEM (2 * STGE * 2)

__global__ __launch_bounds__(128) void gemm_mma(const __nv_bfloat16* __restrict__ A0g,
                                                const __nv_bfloat16* __restrict__ A1g,
                                                const __nv_bfloat16* __restrict__ B0g,
                                                const __nv_bfloat16* __restrict__ B1g,
                                                float* __restrict__ C,
                                                int M, int N, int K) {
    extern __shared__ __nv_bfloat16 smg[];
    const uint32_t sbase = smem_u32(smg);

    const int tid = threadIdx.x;
    const int wid = tid >> 5;
    const int lane = tid & 31;
    const int g = lane >> 2;
    const int t = lane & 3;
    const int warp_m = (wid & 1) * 64;
    const int warp_n = (wid >> 1) * 64;
    const int tile_m = blockIdx.y * 128;
    const int tile_n = blockIdx.x * 128;

    const int a_row = warp_m + ((lane >> 3) & 1) * 8 + (lane & 7);
    const int a_col = (lane >> 4) * 8;
    const int b_row = warp_n + (lane >> 4) * 8 + (lane & 7);
    const int b_col = ((lane >> 3) & 1) * 8;

    float acc[4][8][4];
#pragma unroll
    for (int im = 0; im < 4; im++)
#pragma unroll
        for (int jn = 0; jn < 8; jn++)
#pragma unroll
            for (int c = 0; c < 4; c++) acc[im][jn][c] = 0.f;

    auto load_stage = [&](int st, int k0) {
        const uint32_t sb = sbase + (uint32_t)st * STGE * 2;
#pragma unroll
        for (int rep = 0; rep < 4; rep++) {
            const int idx = tid + 128 * rep;     // 0..511
            const int row = idx >> 2;
            const int c8  = (idx & 3) * 8;
            const uint32_t so = (uint32_t)(row * SSTR + c8) * 2;
            const size_t goA = (size_t)(tile_m + row) * K + k0 + c8;
            const size_t goB = (size_t)(tile_n + row) * K + k0 + c8;
            cp16(sb + 0 * BUFE * 2 + so, A0g + goA);
            cp16(sb + 1 * BUFE * 2 + so, A1g + goA);
            cp16(sb + 2 * BUFE * 2 + so, B0g + goB);
            cp16(sb + 3 * BUFE * 2 + so, B1g + goB);
        }
    };

    const int nchunks = K >> 5;
    load_stage(0, 0);
    CP_COMMIT();

    for (int ch = 0; ch < nchunks; ch++) {
        if (ch + 1 < nchunks) load_stage((ch + 1) & 1, (ch + 1) << 5);
        CP_COMMIT();
        CP_WAIT1();
        __syncthreads();

        const uint32_t sb = sbase + (uint32_t)(ch & 1) * STGE * 2;
#pragma unroll
        for (int ks = 0; ks < 32; ks += 16) {
            uint32_t aH[4][4], aL[4][4];
#pragma unroll
            for (int im = 0; im < 4; im++) {
                const uint32_t ad = sb + (uint32_t)((a_row + im * 16) * SSTR + ks + a_col) * 2;
                ldm_x4(aH[im][0], aH[im][1], aH[im][2], aH[im][3], ad);
                ldm_x4(aL[im][0], aL[im][1], aL[im][2], aL[im][3], ad + BUFE * 2);
            }
#pragma unroll
            for (int jp = 0; jp < 4; jp++) {
                uint32_t bh0, bh1, bh2, bh3, bl0, bl1, bl2, bl3;
                const uint32_t bd = sb + 2 * BUFE * 2
                                  + (uint32_t)((b_row + jp * 16) * SSTR + ks + b_col) * 2;
                ldm_x4(bh0, bh1, bh2, bh3, bd);
                ldm_x4(bl0, bl1, bl2, bl3, bd + BUFE * 2);
#pragma unroll
                for (int im = 0; im < 4; im++) {
                    float* a0p = acc[im][2 * jp];
                    float* a1p = acc[im][2 * jp + 1];
                    mma16816(a0p[0], a0p[1], a0p[2], a0p[3],
                             aH[im][0], aH[im][1], aH[im][2], aH[im][3], bh0, bh1);
                    mma16816(a0p[0], a0p[1], a0p[2], a0p[3],
                             aH[im][0], aH[im][1], aH[im][2], aH[im][3], bl0, bl1);
                    mma16816(a0p[0], a0p[1], a0p[2], a0p[3],
                             aL[im][0], aL[im][1], aL[im][2], aL[im][3], bh0, bh1);
                    mma16816(a1p[0], a1p[1], a1p[2], a1p[3],
                             aH[im][0], aH[im][1], aH[im][2], aH[im][3], bh2, bh3);
                    mma16816(a1p[0], a1p[1], a1p[2], a1p[3],
                             aH[im][0], aH[im][1], aH[im][2], aH[im][3], bl2, bl3);
                    mma16816(a1p[0], a1p[1], a1p[2], a1p[3],
                             aL[im][0], aL[im][1], aL[im][2], aL[im][3], bh2, bh3);
                }
            }
        }
        __syncthreads();
    }

#pragma unroll
    for (int im = 0; im < 4; im++) {
        const int row = tile_m + warp_m + im * 16 + g;
#pragma unroll
        for (int jn = 0; jn < 8; jn++) {
            const int col = tile_n + warp_n + jn * 8 + 2 * t;
            float2 v0; v0.x = acc[im][jn][0]; v0.y = acc[im][jn][1];
            float2 v1; v1.x = acc[im][jn][2]; v1.y = acc[im][jn][3];
            *(float2*)(C + (size_t)row * N + col)       = v0;
            *(float2*)(C + (size_t)(row + 8) * N + col) = v1;
        }
    }
}

// ---------------- prep: per-head bf16 split Q/K/Vt (+ compact globals) ----------------
#define PVS 66
__global__ __launch_bounds__(256) void prep_attn() {
    const int st = blockIdx.x;
    const int h  = blockIdx.y;
    const int s0 = st * 64;
    const int tid = threadIdx.x;

    __shared__ __nv_bfloat16 vth[64][PVS], vtl[64][PVS];

    for (int idx = tid; idx < 1024; idx += 256) {
        const int r = idx >> 4, c4 = (idx & 15) << 2;
        const size_t base = (size_t)(s0 + r) * H3 + h * HD + c4;
        uint32_t h0, l0, h1, l1;
        float4 q = *(const float4*)(g_qkv + base);
        psplit2(q.x * 0.125f, q.y * 0.125f, h0, l0);
        psplit2(q.z * 0.125f, q.w * 0.125f, h1, l1);
        const size_t qo = (size_t)h * SEQ * 64 + (size_t)(s0 + r) * 64 + c4;
        *(uint32_t*)&g_q0[qo] = h0; *(uint32_t*)&g_q0[qo + 2] = h1;
        *(uint32_t*)&g_q1[qo] = l0; *(uint32_t*)&g_q1[qo + 2] = l1;
        float4 k = *(const float4*)(g_qkv + base + HID);
        psplit2(k.x, k.y, h0, l0);
        psplit2(k.z, k.w, h1, l1);
        *(uint32_t*)&g_k0[qo] = h0; *(uint32_t*)&g_k0[qo + 2] = h1;
        *(uint32_t*)&g_k1[qo] = l0; *(uint32_t*)&g_k1[qo + 2] = l1;
        float4 v = *(const float4*)(g_qkv + base + 2 * HID);
        bsplit(v.x, vth[c4 + 0][r], vtl[c4 + 0][r]);
        bsplit(v.y, vth[c4 + 1][r], vtl[c4 + 1][r]);
        bsplit(v.z, vth[c4 + 2][r], vtl[c4 + 2][r]);
        bsplit(v.w, vth[c4 + 3][r], vtl[c4 + 3][r]);
    }
    __syncthreads();

    for (int idx = tid; idx < 2048; idx += 256) {
        const int d = idx >> 5, cp = (idx & 31) << 1;
        const size_t vo = (size_t)h * 64 * SEQ + (size_t)d * SEQ + s0 + cp;
        *(uint32_t*)&g_vt0[vo] = *(const uint32_t*)&vth[d][cp];
        *(uint32_t*)&g_vt1[vo] = *(const uint32_t*)&vtl[d][cp];
    }
    if (tid < 16) {
        const int c4 = tid * 4;
        float4 k = *(const float4*)(g_qkv + (size_t)s0 * H3 + HID + h * HD + c4);
        uint32_t h0, l0, h1, l1;
        psplit2(k.x, k.y, h0, l0);
        psplit2(k.z, k.w, h1, l1);
        const size_t ko = (size_t)h * 32 * 64 + (size_t)st * 64 + c4;
        *(uint32_t*)&g_kg0[ko] = h0; *(uint32_t*)&g_kg0[ko + 2] = h1;
        *(uint32_t*)&g_kg1[ko] = l0; *(uint32_t*)&g_kg1[ko + 2] = l1;
    }
    if (tid < 64) {
        const size_t go = (size_t)h * 64 * 32 + (size_t)tid * 32 + st;
        g_vtg0[go] = vth[tid][0];
        g_vtg1[go] = vtl[tid][0];
    }
}

// ================= MMA attention core =================
// MODE: 0 = band mask |q-k|<=WIN, 1 = global cols (|q-k|>WIN), 2 = no mask
#define MASKV (-3.0e38f)
#define ATS   72
#define ATILE (64 * ATS)
#define AT_SMEM ((2 + 8) * ATILE * 2)

template<int NKT, int MODE>
__device__ __forceinline__ void attn_compute(
    uint32_t sKh, uint32_t sVh, int kb, int qr0,
    int t, int brow, int bcol,
    const uint32_t qh[4][4], const uint32_t qlo[4][4],
    float o[8][4], float& m0, float& m1, float& l0, float& l1)
{
    constexpr int NJ = NKT / 8;
    float sc[NJ][4];

#pragma unroll
    for (int jp = 0; jp < NKT / 16; jp++) {
#pragma unroll
        for (int e = 0; e < 4; e++) { sc[2 * jp][e] = 0.f; sc[2 * jp + 1][e] = 0.f; }
#pragma unroll
        for (int c = 0; c < 4; c++) {
            uint32_t b0, b1, b2, b3, d0, d1, d2, d3;
            const uint32_t ka = sKh + (uint32_t)((jp * 16 + brow) * ATS + c * 16 + bcol) * 2;
            ldm_x4(b0, b1, b2, b3, ka);
            ldm_x4(d0, d1, d2, d3, ka + ATILE * 2);
            float* s0p = sc[2 * jp];
            float* s1p = sc[2 * jp + 1];
            mma16816(s0p[0], s0p[1], s0p[2], s0p[3],
                     qh[c][0], qh[c][1], qh[c][2], qh[c][3], b0, b1);
            mma16816(s0p[0], s0p[1], s0p[2], s0p[3],
                     qh[c][0], qh[c][1], qh[c][2], qh[c][3], d0, d1);
            mma16816(s0p[0], s0p[1], s0p[2], s0p[3],
                     qlo[c][0], qlo[c][1], qlo[c][2], qlo[c][3], b0, b1);
            mma16816(s1p[0], s1p[1], s1p[2], s1p[3],
                     qh[c][0], qh[c][1], qh[c][2], qh[c][3], b2, b3);
            mma16816(s1p[0], s1p[1], s1p[2], s1p[3],
                     qh[c][0], qh[c][1], qh[c][2], qh[c][3], d2, d3);
            mma16816(s1p[0], s1p[1], s1p[2], s1p[3],
                     qlo[c][0], qlo[c][1], qlo[c][2], qlo[c][3], b2, b3);
        }
    }

    float tm0 = MASKV, tm1 = MASKV;
#pragma unroll
    for (int jn = 0; jn < NJ; jn++) {
#pragma unroll
        for (int e = 0; e < 2; e++) {
            if (MODE < 2) {
                const int ci  = jn * 8 + 2 * t + e;
                const int key = (MODE == 1) ? (ci * GSTRIDE) : (kb + ci);
                int d0 = qr0 - key; d0 = d0 < 0 ? -d0 : d0;
                int d1 = qr0 + 8 - key; d1 = d1 < 0 ? -d1 : d1;
                const bool in0 = (MODE == 1) ? (d0 > WIN) : (d0 <= WIN);
                const bool in1 = (MODE == 1) ? (d1 > WIN) : (d1 <= WIN);
                if (!in0) sc[jn][e]     = MASKV;
                if (!in1) sc[jn][2 + e] = MASKV;
            }
            tm0 = fmaxf(tm0, sc[jn][e]);
            tm1 = fmaxf(tm1, sc[jn][2 + e]);
        }
    }
    tm0 = fmaxf(tm0, __shfl_xor_sync(0xffffffffu, tm0, 1));
    tm0 = fmaxf(tm0, __shfl_xor_sync(0xffffffffu, tm0, 2));
    tm1 = fmaxf(tm1, __shfl_xor_sync(0xffffffffu, tm1, 1));
    tm1 = fmaxf(tm1, __shfl_xor_sync(0xffffffffu, tm1, 2));

    const float mn0 = fmaxf(m0, tm0), mn1 = fmaxf(m1, tm1);
    const float e0 = __expf(m0 - mn0), e1 = __expf(m1 - mn1);
    m0 = mn0; m1 = mn1; l0 *= e0; l1 *= e1;
#pragma unroll
    for (int nb = 0; nb < 8; nb++) {
        o[nb][0] *= e0; o[nb][1] *= e0; o[nb][2] *= e1; o[nb][3] *= e1;
    }

    float s0 = 0.f, s1 = 0.f;
#pragma unroll
    for (int c = 0; c < NKT / 16; c++) {
        const float p00 = __expf(sc[2 * c][0] - m0);
        const float p01 = __expf(sc[2 * c][1] - m0);
        const float p02 = __expf(sc[2 * c][2] - m1);
        const float p03 = __expf(sc[2 * c][3] - m1);
        const float p10 = __expf(sc[2 * c + 1][0] - m0);
        const float p11 = __expf(sc[2 * c + 1][1] - m0);
        const float p12 = __expf(sc[2 * c + 1][2] - m1);
        const float p13 = __expf(sc[2 * c + 1][3] - m1);
        s0 += (p00 + p01) + (p10 + p11);
        s1 += (p02 + p03) + (p12 + p13);
        uint32_t ah[4], al[4];
        psplit2(p00, p01, ah[0], al[0]);
        psplit2(p02, p03, ah[1], al[1]);
        psplit2(p10, p11, ah[2], al[2]);
        psplit2(p12, p13, ah[3], al[3]);
#pragma unroll
        for (int np = 0; np < 4; np++) {
            uint32_t v0, v1, v2, v3, w0, w1, w2, w3;
            const uint32_t va = sVh + (uint32_t)((np * 16 + brow) * ATS + c * 16 + bcol) * 2;
            ldm_x4(v0, v1, v2, v3, va);
            ldm_x4(w0, w1, w2, w3, va + ATILE * 2);
            float* oa = o[2 * np];
            float* ob = o[2 * np + 1];
            mma16816(oa[0], oa[1], oa[2], oa[3], ah[0], ah[1], ah[2], ah[3], v0, v1);
            mma16816(oa[0], oa[1], oa[2], oa[3], ah[0], ah[1], ah[2], ah[3], w0, w1);
            mma16816(oa[0], oa[1], oa[2], oa[3], al[0], al[1], al[2], al[3], v0, v1);
            mma16816(ob[0], ob[1], ob[2], ob[3], ah[0], ah[1], ah[2], ah[3], v2, v3);
            mma16816(ob[0], ob[1], ob[2], ob[3], ah[0], ah[1], ah[2], ah[3], w2, w3);
            mma16816(ob[0], ob[1], ob[2], ob[3], al[0], al[1], al[2], al[3], v2, v3);
        }
    }
    s0 += __shfl_xor_sync(0xffffffffu, s0, 1);
    s0 += __shfl_xor_sync(0xffffffffu, s0, 2);
    s1 += __shfl_xor_sync(0xffffffffu, s1, 1);
    s1 += __shfl_xor_sync(0xffffffffu, s1, 2);
    l0 += s0; l1 += s1;
}

// ================= band + global-col attention =================
__global__ __launch_bounds__(128) void attn_mma() {
    extern __shared__ __nv_bfloat16 sm_[];
    const uint32_t sb = smem_u32(sm_);
    const uint32_t sQh = sb, sQl = sb + ATILE * 2;

    const int qt = blockIdx.x, h = blockIdx.y, q0 = qt * 64;
    const int tid = threadIdx.x, wid = tid >> 5, lane = tid & 31;
    const int g = lane >> 2, t = lane & 3;
    const int brow = ((lane >> 4) << 3) + (lane & 7);
    const int bcol = ((lane >> 3) & 1) * 8;

    {
        const __nv_bfloat16* q0p = g_q0 + (size_t)h * SEQ * 64 + (size_t)q0 * 64;
        const __nv_bfloat16* q1p = g_q1 + (size_t)h * SEQ * 64 + (size_t)q0 * 64;
        for (int idx = tid; idx < 512; idx += 128) {
            const int r = idx >> 3, c = idx & 7;
            const uint32_t so = (uint32_t)(r * ATS + c * 8) * 2;
            cp16(sQh + so, q0p + r * 64 + c * 8);
            cp16(sQl + so, q1p + r * 64 + c * 8);
        }
    }
    CP_COMMIT();

    const int kb0 = q0 >= WIN ? q0 - WIN : 0;
    const int kb1 = (q0 + 64 + WIN) <= SEQ ? (q0 + 64 + WIN) : SEQ;
    const int nband = (kb1 - kb0) >> 6;
    const int T = nband + 1;

    auto stage_base = [&](int s) { return sb + (uint32_t)(2 + 4 * s) * ATILE * 2; };
    auto stage_band = [&](int s, int kb) {
        const uint32_t b = stage_base(s);
        const __nv_bfloat16* k0p = g_k0 + (size_t)h * SEQ * 64 + (size_t)kb * 64;
        const __nv_bfloat16* k1p = g_k1 + (size_t)h * SEQ * 64 + (size_t)kb * 64;
        const __nv_bfloat16* v0p = g_vt0 + (size_t)h * 64 * SEQ + kb;
        const __nv_bfloat16* v1p = g_vt1 + (size_t)h * 64 * SEQ + kb;
        for (int idx = tid; idx < 512; idx += 128) {
            const int r = idx >> 3, c = idx & 7;
            const uint32_t so = (uint32_t)(r * ATS + c * 8) * 2;
            cp16(b + so,                 k0p + r * 64 + c * 8);
            cp16(b + ATILE * 2 + so,     k1p + r * 64 + c * 8);
            cp16(b + 2 * ATILE * 2 + so, v0p + (size_t)r * SEQ + c * 8);
            cp16(b + 3 * ATILE * 2 + so, v1p + (size_t)r * SEQ + c * 8);
        }
    };
    auto stage_glob = [&](int s) {
        const uint32_t b = stage_base(s);
        const __nv_bfloat16* k0p = g_kg0 + (size_t)h * 32 * 64;
        const __nv_bfloat16* k1p = g_kg1 + (size_t)h * 32 * 64;
        const __nv_bfloat16* v0p = g_vtg0 + (size_t)h * 64 * 32;
        const __nv_bfloat16* v1p = g_vtg1 + (size_t)h * 64 * 32;
        for (int idx = tid; idx < 256; idx += 128) {
            const int r = idx >> 3, c = idx & 7;
            const uint32_t so = (uint32_t)(r * ATS + c * 8) * 2;
            cp16(b + so,             k0p + r * 64 + c * 8);
            cp16(b + ATILE * 2 + so, k1p + r * 64 + c * 8);
        }
        for (int idx = tid; idx < 256; idx += 128) {
            const int r = idx >> 2, c = idx & 3;
            const uint32_t so = (uint32_t)(r * ATS + c * 8) * 2;
            cp16(b + 2 * ATILE * 2 + so, v0p + r * 32 + c * 8);
            cp16(b + 3 * ATILE * 2 + so, v1p + r * 32 + c * 8);
        }
    };

    stage_band(0, kb0);
    CP_COMMIT();
    CP_WAIT1();
    __syncthreads();

    uint32_t qh[4][4], qlo[4][4];
    {
        const int ar = wid * 16 + ((lane >> 3) & 1) * 8 + (lane & 7);
        const int ac = (lane >> 4) * 8;
#pragma unroll
        for (int c = 0; c < 4; c++) {
            const uint32_t ad = sQh + (uint32_t)(ar * ATS + c * 16 + ac) * 2;
            ldm_x4(qh[c][0], qh[c][1], qh[c][2], qh[c][3], ad);
            ldm_x4(qlo[c][0], qlo[c][1], qlo[c][2], qlo[c][3], ad + ATILE * 2);
        }
    }

    float o[8][4];
#pragma unroll
    for (int nb = 0; nb < 8; nb++)
#pragma unroll
        for (int c = 0; c < 4; c++) o[nb][c] = 0.f;
    float m0 = -1e30f, m1 = -1e30f, l0 = 0.f, l1 = 0.f;
    const int qr0 = q0 + wid * 16 + g;

    for (int i = 0; i < T; i++) {
        if (i + 1 < T) {
            if (i + 1 < nband) stage_band((i + 1) & 1, kb0 + (i + 1) * 64);
            else stage_glob((i + 1) & 1);
            CP_COMMIT();
            CP_WAIT1();
        } else {
            CP_WAIT0();
        }
        __syncthreads();
        const uint32_t b = stage_base(i & 1);
        if (i < nband)
            attn_compute<64, 0>(b, b + 2 * ATILE * 2, kb0 + i * 64, qr0,
                                t, brow, bcol, qh, qlo, o, m0, m1, l0, l1);
        else
            attn_compute<32, 1>(b, b + 2 * ATILE * 2, 0, qr0,
                                t, brow, bcol, qh, qlo, o, m0, m1, l0, l1);
        __syncthreads();
    }

    const float i0 = 1.f / l0, i1 = 1.f / l1;
    const int row0 = q0 + wid * 16 + g;
#pragma unroll
    for (int nb = 0; nb < 8; nb++) {
        uint32_t h0, lo0, h1, lo1;
        psplit2(o[nb][0] * i0, o[nb][1] * i0, h0, lo0);
        psplit2(o[nb][2] * i1, o[nb][3] * i1, h1, lo1);
        const size_t ofs0 = (size_t)row0 * HID + h * HD + nb * 8 + 2 * t;
        const size_t ofs1 = ofs0 + (size_t)8 * HID;
        *(uint32_t*)&g_a0[ofs0] = h0; *(uint32_t*)&g_a1[ofs0] = lo0;
        *(uint32_t*)&g_a0[ofs1] = h1; *(uint32_t*)&g_a1[ofs1] = lo1;
    }
}

// ================= global rows: MMA over all 2048 keys =================
// Block = head. 4 warps: (row-half rh = wid&1) x (key-parity kp = wid>>1).
// M=32 gathered global queries (row r -> query 64r). Split-softmax merge across kp.
#define GA_QSZ   (32 * ATS * 2)                 // bytes per Q split
#define GA_TILES (2 * 2 * 4 * ATILE * 2)        // 2 stages x 2 kp x 4 bufs
#define GA_OBUF  (2 * 16 * 64 * 4)
#define GA_SMEM  (2 * GA_QSZ + GA_TILES + GA_OBUF + 256)

__global__ __launch_bounds__(128) void attn_global_mma() {
    extern __shared__ __nv_bfloat16 smg2[];
    const uint32_t sb = smem_u32(smg2);
    const int h = blockIdx.x;
    const int tid = threadIdx.x, wid = tid >> 5, lane = tid & 31;
    const int g = lane >> 2, t = lane & 3;
    const int rh = wid & 1, kp = wid >> 1;
    const int brow = ((lane >> 4) << 3) + (lane & 7);
    const int bcol = ((lane >> 3) & 1) * 8;

    const uint32_t sQ = sb;
    const uint32_t tiles0 = sb + 2 * GA_QSZ;
    float* obuf = (float*)(smg2 + (2 * 32 * ATS + 16 * ATILE));
    float* slm  = obuf + 2 * 16 * 64;
    float* sll  = slm + 32;

    // stage Q (gathered rows: query 64r)
    {
        const __nv_bfloat16* q0p = g_q0 + (size_t)h * SEQ * 64;
        const __nv_bfloat16* q1p = g_q1 + (size_t)h * SEQ * 64;
        for (int idx = tid; idx < 256; idx += 128) {
            const int r = idx >> 3, c = idx & 7;
            const uint32_t so = (uint32_t)(r * ATS + c * 8) * 2;
            cp16(sQ + so,          q0p + (size_t)r * 64 * 64 + c * 8);
            cp16(sQ + GA_QSZ + so, q1p + (size_t)r * 64 * 64 + c * 8);
        }
    }
    CP_COMMIT();

    auto stage_tiles = [&](int st, int it) {
#pragma unroll
        for (int kpi = 0; kpi < 2; kpi++) {
            const int kt = (it * 2 + kpi) * 64;
            const uint32_t b = tiles0 + (uint32_t)((st * 2 + kpi) * 4) * ATILE * 2;
            const __nv_bfloat16* k0p = g_k0 + (size_t)h * SEQ * 64 + (size_t)kt * 64;
            const __nv_bfloat16* k1p = g_k1 + (size_t)h * SEQ * 64 + (size_t)kt * 64;
            const __nv_bfloat16* v0p = g_vt0 + (size_t)h * 64 * SEQ + kt;
            const __nv_bfloat16* v1p = g_vt1 + (size_t)h * 64 * SEQ + kt;
            for (int idx = tid; idx < 512; idx += 128) {
                const int r = idx >> 3, c = idx & 7;
                const uint32_t so = (uint32_t)(r * ATS + c * 8) * 2;
                cp16(b + so,                 k0p + r * 64 + c * 8);
                cp16(b + ATILE * 2 + so,     k1p + r * 64 + c * 8);
                cp16(b + 2 * ATILE * 2 + so, v0p + (size_t)r * SEQ + c * 8);
                cp16(b + 3 * ATILE * 2 + so, v1p + (size_t)r * SEQ + c * 8);
            }
        }
    };

    stage_tiles(0, 0);
    CP_COMMIT();
    CP_WAIT1();          // Q done
    __syncthreads();

    uint32_t qh[4][4], qlo[4][4];
    {
        const int ar = rh * 16 + ((lane >> 3) & 1) * 8 + (lane & 7);
        const int ac = (lane >> 4) * 8;
#pragma unroll
        for (int c = 0; c < 4; c++) {
            const uint32_t ad = sQ + (uint32_t)(ar * ATS + c * 16 + ac) * 2;
            ldm_x4(qh[c][0], qh[c][1], qh[c][2], qh[c][3], ad);
            ldm_x4(qlo[c][0], qlo[c][1], qlo[c][2], qlo[c][3], ad + GA_QSZ);
        }
    }

    float o[8][4];
#pragma unroll
    for (int nb = 0; nb < 8; nb++)
#pragma unroll
        for (int c = 0; c < 4; c++) o[nb][c] = 0.f;
    float m0 = -1e30f, m1 = -1e30f, l0 = 0.f, l1 = 0.f;

    for (int it = 0; it < 16; it++) {
        if (it + 1 < 16) {
            stage_tiles((it + 1) & 1, it + 1);
            CP_COMMIT();
            CP_WAIT1();
        } else {
            CP_WAIT0();
        }
        __syncthreads();
        const uint32_t b = tiles0 + (uint32_t)(((it & 1) * 2 + kp) * 4) * ATILE * 2;
        attn_compute<64, 2>(b, b + 2 * ATILE * 2, 0, 0,
                            t, brow, bcol, qh, qlo, o, m0, m1, l0, l1);
        __syncthreads();
    }

    // ---- merge kp=1 into kp=0 ----
    __syncthreads();
    if (kp == 1) {
        float* ob = obuf + rh * 16 * 64;
#pragma unroll
        for (int nb = 0; nb < 8; nb++) {
            ob[g * 64 + nb * 8 + 2 * t]           = o[nb][0];
            ob[g * 64 + nb * 8 + 2 * t + 1]       = o[nb][1];
            ob[(g + 8) * 64 + nb * 8 + 2 * t]     = o[nb][2];
            ob[(g + 8) * 64 + nb * 8 + 2 * t + 1] = o[nb][3];
        }
        if (t == 0) {
            slm[rh * 16 + g] = m0; slm[rh * 16 + g + 8] = m1;
            sll[rh * 16 + g] = l0; sll[rh * 16 + g + 8] = l1;
        }
    }
    __syncthreads();
    if (kp == 0) {
        const float pm0 = slm[rh * 16 + g], pm1 = slm[rh * 16 + g + 8];
        const float pl0 = sll[rh * 16 + g], pl1 = sll[rh * 16 + g + 8];
        const float M0 = fmaxf(m0, pm0), M1 = fmaxf(m1, pm1);
        const float e0 = __expf(m0 - M0), f0 = __expf(pm0 - M0);
        const float e1 = __expf(m1 - M1), f1 = __expf(pm1 - M1);
        const float L0 = l0 * e0 + pl0 * f0;
        const float L1 = l1 * e1 + pl1 * f1;
        const float i0 = 1.f / L0, i1 = 1.f / L1;
        float* ob = obuf + rh * 16 * 64;
        const int qi0 = (rh * 16 + g) * 64;
        const int qi1 = (rh * 16 + g + 8) * 64;
#pragma unroll
        for (int nb = 0; nb < 8; nb++) {
            const int cc = nb * 8 + 2 * t;
            const float r00 = (o[nb][0] * e0 + ob[g * 64 + cc] * f0) * i0;
            const float r01 = (o[nb][1] * e0 + ob[g * 64 + cc + 1] * f0) * i0;
            const float r10 = (o[nb][2] * e1 + ob[(g + 8) * 64 + cc] * f1) * i1;
            const float r11 = (o[nb][3] * e1 + ob[(g + 8) * 64 + cc + 1] * f1) * i1;
            uint32_t h0, lo0, h1, lo1;
            psplit2(r00, r01, h0, lo0);
            psplit2(r10, r11, h1, lo1);
            const size_t ofs0 = (size_t)qi0 * HID + h * HD + cc;
            const size_t ofs1 = (size_t)qi1 * HID + h * HD + cc;
            *(uint32_t*)&g_a0[ofs0] = h0; *(uint32_t*)&g_a1[ofs0] = lo0;
            *(uint32_t*)&g_a0[ofs1] = h1; *(uint32_t*)&g_a1[ofs1] = lo1;
        }
    }
}

// ---------------- launch ----------------
extern "C" void kernel_launch(void* const* d_in, const int* in_sizes, int n_in,
                              void* d_out, int out_size) {
    const float* x    = (const float*)d_in[0];
    const float* Wqkv = (const float*)d_in[1];
    const float* Wout = (const float*)d_in[2];
    float* out = (float*)d_out;

    float* qkv = nullptr;
    cudaGetSymbolAddress((void**)&qkv, g_qkv);
    __nv_bfloat16 *x0, *x1, *wq0, *wq1, *a0, *a1, *wo0, *wo1;
    cudaGetSymbolAddress((void**)&x0,  g_x0);  cudaGetSymbolAddress((void**)&x1,  g_x1);
    cudaGetSymbolAddress((void**)&wq0, g_wq0); cudaGetSymbolAddress((void**)&wq1, g_wq1);
    cudaGetSymbolAddress((void**)&a0,  g_a0);  cudaGetSymbolAddress((void**)&a1,  g_a1);
    cudaGetSymbolAddress((void**)&wo0, g_wo0); cudaGetSymbolAddress((void**)&wo1, g_wo1);

    cudaFuncSetAttribute(gemm_mma, cudaFuncAttributeMaxDynamicSharedMemorySize, GT_SMEM);
    cudaFuncSetAttribute(attn_mma, cudaFuncAttributeMaxDynamicSharedMemorySize, AT_SMEM);
    cudaFuncSetAttribute(attn_global_mma, cudaFuncAttributeMaxDynamicSharedMemorySize, GA_SMEM);

    // 0) split inputs
    split_bf16<<<(SEQ * HID / 4 + 255) / 256, 256>>>(x, x0, x1, SEQ * HID / 4);
    split_bf16<<<(H3 * HID / 4 + 255) / 256, 256>>>(Wqkv, wq0, wq1, H3 * HID / 4);
    split_bf16<<<(HID * HID / 4 + 255) / 256, 256>>>(Wout, wo0, wo1, HID * HID / 4);

    // 1) qkv = x @ Wqkv^T
    gemm_mma<<<dim3(H3 / 128, SEQ / 128), 128, GT_SMEM>>>(x0, x1, wq0, wq1, qkv, SEQ, H3, HID);

    // 2) per-head split operands
    prep_attn<<<dim3(SEQ / 64, NHEAD), 256>>>();

    // 3) sparse attention -> g_a0/g_a1
    attn_mma<<<dim3(SEQ / 64, NHEAD), 128, AT_SMEM>>>();
    attn_global_mma<<<NHEAD, 128, GA_SMEM>>>();

    // 4) out = attn @ Wout^T
    gemm_mma<<<dim3(HID / 128, SEQ / 128), 128, GT_SMEM>>>(a0, a1, wo0, wo1, out, SEQ, HID, HID);
}

// round 10
// speedup vs baseline: 5.4843x; 1.3131x over previous
#include <cuda_runtime.h>
#include <cuda_bf16.h>
#include <cuda_fp16.h>
#include <cstdint>

// ---------------- problem constants ----------------
#define SEQ   2048
#define HID   1024
#define H3    3072
#define NHEAD 16
#define HD    64
#define WIN   128
#define GSTRIDE 64

typedef unsigned long long u64;

// ---------------- mma / ldmatrix / cp.async helpers ----------------
__device__ __forceinline__ void mma16816(float& c0, float& c1, float& c2, float& c3,
                                         uint32_t a0, uint32_t a1, uint32_t a2, uint32_t a3,
                                         uint32_t b0, uint32_t b1) {
    asm volatile(
        "mma.sync.aligned.m16n8k16.row.col.f32.bf16.bf16.f32 "
        "{%0,%1,%2,%3}, {%4,%5,%6,%7}, {%8,%9}, {%0,%1,%2,%3};"
        : "+f"(c0), "+f"(c1), "+f"(c2), "+f"(c3)
        : "r"(a0), "r"(a1), "r"(a2), "r"(a3), "r"(b0), "r"(b1));
}
__device__ __forceinline__ void mma16816h(float& c0, float& c1, float& c2, float& c3,
                                          uint32_t a0, uint32_t a1, uint32_t a2, uint32_t a3,
                                          uint32_t b0, uint32_t b1) {
    asm volatile(
        "mma.sync.aligned.m16n8k16.row.col.f32.f16.f16.f32 "
        "{%0,%1,%2,%3}, {%4,%5,%6,%7}, {%8,%9}, {%0,%1,%2,%3};"
        : "+f"(c0), "+f"(c1), "+f"(c2), "+f"(c3)
        : "r"(a0), "r"(a1), "r"(a2), "r"(a3), "r"(b0), "r"(b1));
}
__device__ __forceinline__ void ldm_x4(uint32_t& r0, uint32_t& r1, uint32_t& r2, uint32_t& r3,
                                       uint32_t addr) {
    asm volatile("ldmatrix.sync.aligned.m8n8.x4.shared.b16 {%0,%1,%2,%3}, [%4];"
                 : "=r"(r0), "=r"(r1), "=r"(r2), "=r"(r3) : "r"(addr));
}
__device__ __forceinline__ uint32_t smem_u32(const void* p) {
    uint32_t a;
    asm("{ .reg .u64 t; cvta.to.shared.u64 t, %1; cvt.u32.u64 %0, t; }" : "=r"(a) : "l"(p));
    return a;
}
__device__ __forceinline__ void cp16(uint32_t saddr, const void* gptr) {
    asm volatile("cp.async.cg.shared.global [%0], [%1], 16;" :: "r"(saddr), "l"(gptr));
}
#define CP_COMMIT() asm volatile("cp.async.commit_group;" ::: "memory")
#define CP_WAIT1()  asm volatile("cp.async.wait_group 1;" ::: "memory")
#define CP_WAIT0()  asm volatile("cp.async.wait_group 0;" ::: "memory")

// bf16 split helpers
__device__ __forceinline__ void bsplit(float x, __nv_bfloat16& hi, __nv_bfloat16& lo) {
    hi = __float2bfloat16(x);
    lo = __float2bfloat16(x - __bfloat162float(hi));
}
__device__ __forceinline__ void psplit2(float a, float b, uint32_t& hi, uint32_t& lo) {
    uint32_t hp;
    asm("cvt.rn.bf16x2.f32 %0, %1, %2;" : "=r"(hp) : "f"(b), "f"(a));
    const float ha = __uint_as_float(hp << 16);
    const float hb = __uint_as_float(hp & 0xffff0000u);
    uint32_t lp;
    asm("cvt.rn.bf16x2.f32 %0, %1, %2;" : "=r"(lp) : "f"(b - hb), "f"(a - ha));
    hi = hp; lo = lp;
}
// fp16 pair pack (a in low half)
__device__ __forceinline__ uint32_t packh2(float a, float b) {
    __half2 h = __floats2half2_rn(a, b);
    uint32_t r;
    *(__half2*)&r = h;
    return r;
}

// ---------------- scratch (device globals) ----------------
__device__ float g_qkv[SEQ * H3];
__device__ __align__(16) __half g_xh[SEQ * HID];
__device__ __align__(16) __half g_wqh[H3 * HID], g_wql[H3 * HID];
__device__ __align__(16) __nv_bfloat16 g_a0[SEQ * HID],  g_a1[SEQ * HID];
__device__ __align__(16) __nv_bfloat16 g_wo0[HID * HID], g_wo1[HID * HID];
__device__ __align__(16) __nv_bfloat16 g_q0[NHEAD * SEQ * 64], g_q1[NHEAD * SEQ * 64];
__device__ __align__(16) __nv_bfloat16 g_k0[NHEAD * SEQ * 64], g_k1[NHEAD * SEQ * 64];
__device__ __align__(16) __nv_bfloat16 g_vt0[NHEAD * 64 * SEQ], g_vt1[NHEAD * 64 * SEQ];
__device__ __align__(16) __nv_bfloat16 g_kg0[NHEAD * 32 * 64], g_kg1[NHEAD * 32 * 64];
__device__ __align__(16) __nv_bfloat16 g_vtg0[NHEAD * 64 * 32], g_vtg1[NHEAD * 64 * 32];

// ---------------- conversions ----------------
__global__ __launch_bounds__(256) void split_bf16(const float* __restrict__ in,
                                                  __nv_bfloat16* __restrict__ hi,
                                                  __nv_bfloat16* __restrict__ lo,
                                                  int n4) {
    int i = blockIdx.x * blockDim.x + threadIdx.x;
    if (i >= n4) return;
    float4 v = ((const float4*)in)[i];
    uint32_t h0, l0, h1, l1;
    psplit2(v.x, v.y, h0, l0);
    psplit2(v.z, v.w, h1, l1);
    uint32_t* hp = (uint32_t*)hi;
    uint32_t* lp = (uint32_t*)lo;
    hp[2 * i] = h0; hp[2 * i + 1] = h1;
    lp[2 * i] = l0; lp[2 * i + 1] = l1;
}
__global__ __launch_bounds__(256) void conv_half(const float* __restrict__ in,
                                                 __half* __restrict__ out, int n4) {
    int i = blockIdx.x * blockDim.x + threadIdx.x;
    if (i >= n4) return;
    float4 v = ((const float4*)in)[i];
    uint32_t* op = (uint32_t*)out;
    op[2 * i]     = packh2(v.x, v.y);
    op[2 * i + 1] = packh2(v.z, v.w);
}
__global__ __launch_bounds__(256) void split_half(const float* __restrict__ in,
                                                  __half* __restrict__ hi,
                                                  __half* __restrict__ lo, int n4) {
    int i = blockIdx.x * blockDim.x + threadIdx.x;
    if (i >= n4) return;
    float4 v = ((const float4*)in)[i];
    __half h0 = __float2half_rn(v.x), h1 = __float2half_rn(v.y);
    __half h2 = __float2half_rn(v.z), h3 = __float2half_rn(v.w);
    float r0 = v.x - __half2float(h0), r1 = v.y - __half2float(h1);
    float r2 = v.z - __half2float(h2), r3 = v.w - __half2float(h3);
    uint32_t* hp = (uint32_t*)hi;
    uint32_t* lp = (uint32_t*)lo;
    uint32_t ph0; *(__half2*)&ph0 = __halves2half2(h0, h1);
    uint32_t ph1; *(__half2*)&ph1 = __halves2half2(h2, h3);
    hp[2 * i] = ph0; hp[2 * i + 1] = ph1;
    lp[2 * i]     = packh2(r0, r1);
    lp[2 * i + 1] = packh2(r2, r3);
}

// ---------------- shared tile geometry ----------------
#define SSTR 40
#define BUFE (128 * SSTR)

// ---------------- fp16 2-term GEMM: C = A @ (Bh+Bl)^T ----------------
// 256 thr, 8 warps 2(M)x4(N), warp tile 64x32, BK=32, 2 stages x 3 buffers.
#define FSTGE (3 * BUFE)
#define GF_SMEM (2 * FSTGE * 2)

__global__ __launch_bounds__(256) void gemm_f16(const __half* __restrict__ Ag,
                                                const __half* __restrict__ Bhg,
                                                const __half* __restrict__ Blg,
                                                float* __restrict__ C,
                                                int M, int N, int K) {
    extern __shared__ __half smf[];
    const uint32_t sbase = smem_u32(smf);

    const int tid = threadIdx.x;
    const int wid = tid >> 5;
    const int lane = tid & 31;
    const int g = lane >> 2;
    const int t = lane & 3;
    const int warp_m = (wid & 1) * 64;
    const int warp_n = (wid >> 1) * 32;
    const int tile_m = blockIdx.y * 128;
    const int tile_n = blockIdx.x * 128;

    const int a_row = warp_m + ((lane >> 3) & 1) * 8 + (lane & 7);
    const int a_col = (lane >> 4) * 8;
    const int b_row = warp_n + (lane >> 4) * 8 + (lane & 7);
    const int b_col = ((lane >> 3) & 1) * 8;

    float acc[4][4][4];
#pragma unroll
    for (int im = 0; im < 4; im++)
#pragma unroll
        for (int jn = 0; jn < 4; jn++)
#pragma unroll
            for (int c = 0; c < 4; c++) acc[im][jn][c] = 0.f;

    auto load_stage = [&](int st, int k0) {
        const uint32_t sb = sbase + (uint32_t)st * FSTGE * 2;
#pragma unroll
        for (int rep = 0; rep < 2; rep++) {
            const int idx = tid + 256 * rep;
            const int row = idx >> 2;
            const int c8  = (idx & 3) * 8;
            const uint32_t so = (uint32_t)(row * SSTR + c8) * 2;
            const size_t goA = (size_t)(tile_m + row) * K + k0 + c8;
            const size_t goB = (size_t)(tile_n + row) * K + k0 + c8;
            cp16(sb + 0 * BUFE * 2 + so, Ag + goA);
            cp16(sb + 1 * BUFE * 2 + so, Bhg + goB);
            cp16(sb + 2 * BUFE * 2 + so, Blg + goB);
        }
    };

    const int nchunks = K >> 5;
    load_stage(0, 0);
    CP_COMMIT();

    for (int ch = 0; ch < nchunks; ch++) {
        if (ch + 1 < nchunks) load_stage((ch + 1) & 1, (ch + 1) << 5);
        CP_COMMIT();
        CP_WAIT1();
        __syncthreads();

        const uint32_t sb = sbase + (uint32_t)(ch & 1) * FSTGE * 2;
#pragma unroll
        for (int ks = 0; ks < 32; ks += 16) {
            uint32_t aH[4][4];
#pragma unroll
            for (int im = 0; im < 4; im++) {
                const uint32_t ad = sb + (uint32_t)((a_row + im * 16) * SSTR + ks + a_col) * 2;
                ldm_x4(aH[im][0], aH[im][1], aH[im][2], aH[im][3], ad);
            }
#pragma unroll
            for (int jp = 0; jp < 2; jp++) {
                uint32_t bh0, bh1, bh2, bh3, bl0, bl1, bl2, bl3;
                const uint32_t bd = sb + 1 * BUFE * 2
                                  + (uint32_t)((b_row + jp * 16) * SSTR + ks + b_col) * 2;
                ldm_x4(bh0, bh1, bh2, bh3, bd);
                ldm_x4(bl0, bl1, bl2, bl3, bd + BUFE * 2);
#pragma unroll
                for (int im = 0; im < 4; im++) {
                    float* a0p = acc[im][2 * jp];
                    float* a1p = acc[im][2 * jp + 1];
                    mma16816h(a0p[0], a0p[1], a0p[2], a0p[3],
                              aH[im][0], aH[im][1], aH[im][2], aH[im][3], bh0, bh1);
                    mma16816h(a0p[0], a0p[1], a0p[2], a0p[3],
                              aH[im][0], aH[im][1], aH[im][2], aH[im][3], bl0, bl1);
                    mma16816h(a1p[0], a1p[1], a1p[2], a1p[3],
                              aH[im][0], aH[im][1], aH[im][2], aH[im][3], bh2, bh3);
                    mma16816h(a1p[0], a1p[1], a1p[2], a1p[3],
                              aH[im][0], aH[im][1], aH[im][2], aH[im][3], bl2, bl3);
                }
            }
        }
        __syncthreads();
    }

#pragma unroll
    for (int im = 0; im < 4; im++) {
        const int row = tile_m + warp_m + im * 16 + g;
#pragma unroll
        for (int jn = 0; jn < 4; jn++) {
            const int col = tile_n + warp_n + jn * 8 + 2 * t;
            float2 v0; v0.x = acc[im][jn][0]; v0.y = acc[im][jn][1];
            float2 v1; v1.x = acc[im][jn][2]; v1.y = acc[im][jn][3];
            *(float2*)(C + (size_t)row * N + col)       = v0;
            *(float2*)(C + (size_t)(row + 8) * N + col) = v1;
        }
    }
}

// ---------------- bf16 3-term GEMM (R6 256-thread config) ----------------
#define STGE (4 * BUFE)
#define GT_SMEM (2 * STGE * 2)

__global__ __launch_bounds__(256) void gemm_mma(const __nv_bfloat16* __restrict__ A0g,
                                                const __nv_bfloat16* __restrict__ A1g,
                                                const __nv_bfloat16* __restrict__ B0g,
                                                const __nv_bfloat16* __restrict__ B1g,
                                                float* __restrict__ C,
                                                int M, int N, int K) {
    extern __shared__ __nv_bfloat16 smg[];
    const uint32_t sbase = smem_u32(smg);

    const int tid = threadIdx.x;
    const int wid = tid >> 5;
    const int lane = tid & 31;
    const int g = lane >> 2;
    const int t = lane & 3;
    const int warp_m = (wid & 1) * 64;
    const int warp_n = (wid >> 1) * 32;
    const int tile_m = blockIdx.y * 128;
    const int tile_n = blockIdx.x * 128;

    const int a_row = warp_m + ((lane >> 3) & 1) * 8 + (lane & 7);
    const int a_col = (lane >> 4) * 8;
    const int b_row = warp_n + (lane >> 4) * 8 + (lane & 7);
    const int b_col = ((lane >> 3) & 1) * 8;

    float acc[4][4][4];
#pragma unroll
    for (int im = 0; im < 4; im++)
#pragma unroll
        for (int jn = 0; jn < 4; jn++)
#pragma unroll
            for (int c = 0; c < 4; c++) acc[im][jn][c] = 0.f;

    const int srow = tid >> 2;
    const int sc16 = (tid & 3) * 8;

    auto load_stage = [&](int st, int k0) {
        const uint32_t sb = sbase + (uint32_t)st * STGE * 2;
#pragma unroll
        for (int rep = 0; rep < 2; rep++) {
            const int row = srow + rep * 64;
            const uint32_t so = (uint32_t)(row * SSTR + sc16) * 2;
            const size_t goA = (size_t)(tile_m + row) * K + k0 + sc16;
            const size_t goB = (size_t)(tile_n + row) * K + k0 + sc16;
            cp16(sb + 0 * BUFE * 2 + so, A0g + goA);
            cp16(sb + 1 * BUFE * 2 + so, A1g + goA);
            cp16(sb + 2 * BUFE * 2 + so, B0g + goB);
            cp16(sb + 3 * BUFE * 2 + so, B1g + goB);
        }
    };

    const int nchunks = K >> 5;
    load_stage(0, 0);
    CP_COMMIT();

    for (int ch = 0; ch < nchunks; ch++) {
        if (ch + 1 < nchunks) load_stage((ch + 1) & 1, (ch + 1) << 5);
        CP_COMMIT();
        CP_WAIT1();
        __syncthreads();

        const uint32_t sb = sbase + (uint32_t)(ch & 1) * STGE * 2;
#pragma unroll
        for (int ks = 0; ks < 32; ks += 16) {
            uint32_t aH[4][4], aL[4][4], bH[4][2], bL[4][2];
#pragma unroll
            for (int im = 0; im < 4; im++) {
                const uint32_t ad = sb + (uint32_t)((a_row + im * 16) * SSTR + ks + a_col) * 2;
                ldm_x4(aH[im][0], aH[im][1], aH[im][2], aH[im][3], ad);
                ldm_x4(aL[im][0], aL[im][1], aL[im][2], aL[im][3], ad + BUFE * 2);
            }
#pragma unroll
            for (int jp = 0; jp < 2; jp++) {
                const uint32_t bd = sb + 2 * BUFE * 2
                                  + (uint32_t)((b_row + jp * 16) * SSTR + ks + b_col) * 2;
                ldm_x4(bH[2 * jp][0], bH[2 * jp][1], bH[2 * jp + 1][0], bH[2 * jp + 1][1], bd);
                ldm_x4(bL[2 * jp][0], bL[2 * jp][1], bL[2 * jp + 1][0], bL[2 * jp + 1][1], bd + BUFE * 2);
            }
#pragma unroll
            for (int im = 0; im < 4; im++)
#pragma unroll
                for (int jn = 0; jn < 4; jn++) {
                    float* a = acc[im][jn];
                    mma16816(a[0], a[1], a[2], a[3],
                             aH[im][0], aH[im][1], aH[im][2], aH[im][3],
                             bH[jn][0], bH[jn][1]);
                    mma16816(a[0], a[1], a[2], a[3],
                             aH[im][0], aH[im][1], aH[im][2], aH[im][3],
                             bL[jn][0], bL[jn][1]);
                    mma16816(a[0], a[1], a[2], a[3],
                             aL[im][0], aL[im][1], aL[im][2], aL[im][3],
                             bH[jn][0], bH[jn][1]);
                }
        }
        __syncthreads();
    }

#pragma unroll
    for (int im = 0; im < 4; im++) {
        const int row = tile_m + warp_m + im * 16 + g;
#pragma unroll
        for (int jn = 0; jn < 4; jn++) {
            const int col = tile_n + warp_n + jn * 8 + 2 * t;
            float2 v0; v0.x = acc[im][jn][0]; v0.y = acc[im][jn][1];
            float2 v1; v1.x = acc[im][jn][2]; v1.y = acc[im][jn][3];
            *(float2*)(C + (size_t)row * N + col)       = v0;
            *(float2*)(C + (size_t)(row + 8) * N + col) = v1;
        }
    }
}

// ---------------- prep: per-head bf16 split Q/K/Vt (+ compact globals) ----------------
#define PVS 66
__global__ __launch_bounds__(256) void prep_attn() {
    const int st = blockIdx.x;
    const int h  = blockIdx.y;
    const int s0 = st * 64;
    const int tid = threadIdx.x;

    __shared__ __nv_bfloat16 vth[64][PVS], vtl[64][PVS];

    for (int idx = tid; idx < 1024; idx += 256) {
        const int r = idx >> 4, c4 = (idx & 15) << 2;
        const size_t base = (size_t)(s0 + r) * H3 + h * HD + c4;
        uint32_t h0, l0, h1, l1;
        float4 q = *(const float4*)(g_qkv + base);
        psplit2(q.x * 0.125f, q.y * 0.125f, h0, l0);
        psplit2(q.z * 0.125f, q.w * 0.125f, h1, l1);
        const size_t qo = (size_t)h * SEQ * 64 + (size_t)(s0 + r) * 64 + c4;
        *(uint32_t*)&g_q0[qo] = h0; *(uint32_t*)&g_q0[qo + 2] = h1;
        *(uint32_t*)&g_q1[qo] = l0; *(uint32_t*)&g_q1[qo + 2] = l1;
        float4 k = *(const float4*)(g_qkv + base + HID);
        psplit2(k.x, k.y, h0, l0);
        psplit2(k.z, k.w, h1, l1);
        *(uint32_t*)&g_k0[qo] = h0; *(uint32_t*)&g_k0[qo + 2] = h1;
        *(uint32_t*)&g_k1[qo] = l0; *(uint32_t*)&g_k1[qo + 2] = l1;
        float4 v = *(const float4*)(g_qkv + base + 2 * HID);
        bsplit(v.x, vth[c4 + 0][r], vtl[c4 + 0][r]);
        bsplit(v.y, vth[c4 + 1][r], vtl[c4 + 1][r]);
        bsplit(v.z, vth[c4 + 2][r], vtl[c4 + 2][r]);
        bsplit(v.w, vth[c4 + 3][r], vtl[c4 + 3][r]);
    }
    __syncthreads();

    for (int idx = tid; idx < 2048; idx += 256) {
        const int d = idx >> 5, cp = (idx & 31) << 1;
        const size_t vo = (size_t)h * 64 * SEQ + (size_t)d * SEQ + s0 + cp;
        *(uint32_t*)&g_vt0[vo] = *(const uint32_t*)&vth[d][cp];
        *(uint32_t*)&g_vt1[vo] = *(const uint32_t*)&vtl[d][cp];
    }
    if (tid < 16) {
        const int c4 = tid * 4;
        float4 k = *(const float4*)(g_qkv + (size_t)s0 * H3 + HID + h * HD + c4);
        uint32_t h0, l0, h1, l1;
        psplit2(k.x, k.y, h0, l0);
        psplit2(k.z, k.w, h1, l1);
        const size_t ko = (size_t)h * 32 * 64 + (size_t)st * 64 + c4;
        *(uint32_t*)&g_kg0[ko] = h0; *(uint32_t*)&g_kg0[ko + 2] = h1;
        *(uint32_t*)&g_kg1[ko] = l0; *(uint32_t*)&g_kg1[ko + 2] = l1;
    }
    if (tid < 64) {
        const size_t go = (size_t)h * 64 * 32 + (size_t)tid * 32 + st;
        g_vtg0[go] = vth[tid][0];
        g_vtg1[go] = vtl[tid][0];
    }
}

// ================= MMA attention core =================
#define MASKV (-3.0e38f)
#define ATS   72
#define ATILE (64 * ATS)
#define AT_SMEM ((2 + 8) * ATILE * 2)

template<int NKT, int MODE>
__device__ __forceinline__ void attn_compute(
    uint32_t sKh, uint32_t sVh, int kb, int qr0,
    int t, int brow, int bcol,
    const uint32_t qh[4][4], const uint32_t qlo[4][4],
    float o[8][4], float& m0, float& m1, float& l0, float& l1)
{
    constexpr int NJ = NKT / 8;
    float sc[NJ][4];

#pragma unroll
    for (int jp = 0; jp < NKT / 16; jp++) {
#pragma unroll
        for (int e = 0; e < 4; e++) { sc[2 * jp][e] = 0.f; sc[2 * jp + 1][e] = 0.f; }
#pragma unroll
        for (int c = 0; c < 4; c++) {
            uint32_t b0, b1, b2, b3, d0, d1, d2, d3;
            const uint32_t ka = sKh + (uint32_t)((jp * 16 + brow) * ATS + c * 16 + bcol) * 2;
            ldm_x4(b0, b1, b2, b3, ka);
            ldm_x4(d0, d1, d2, d3, ka + ATILE * 2);
            float* s0p = sc[2 * jp];
            float* s1p = sc[2 * jp + 1];
            mma16816(s0p[0], s0p[1], s0p[2], s0p[3],
                     qh[c][0], qh[c][1], qh[c][2], qh[c][3], b0, b1);
            mma16816(s0p[0], s0p[1], s0p[2], s0p[3],
                     qh[c][0], qh[c][1], qh[c][2], qh[c][3], d0, d1);
            mma16816(s0p[0], s0p[1], s0p[2], s0p[3],
                     qlo[c][0], qlo[c][1], qlo[c][2], qlo[c][3], b0, b1);
            mma16816(s1p[0], s1p[1], s1p[2], s1p[3],
                     qh[c][0], qh[c][1], qh[c][2], qh[c][3], b2, b3);
            mma16816(s1p[0], s1p[1], s1p[2], s1p[3],
                     qh[c][0], qh[c][1], qh[c][2], qh[c][3], d2, d3);
            mma16816(s1p[0], s1p[1], s1p[2], s1p[3],
                     qlo[c][0], qlo[c][1], qlo[c][2], qlo[c][3], b2, b3);
        }
    }

    float tm0 = MASKV, tm1 = MASKV;
#pragma unroll
    for (int jn = 0; jn < NJ; jn++) {
#pragma unroll
        for (int e = 0; e < 2; e++) {
            if (MODE < 2) {
                const int ci  = jn * 8 + 2 * t + e;
                const int key = (MODE == 1) ? (ci * GSTRIDE) : (kb + ci);
                int d0 = qr0 - key; d0 = d0 < 0 ? -d0 : d0;
                int d1 = qr0 + 8 - key; d1 = d1 < 0 ? -d1 : d1;
                const bool in0 = (MODE == 1) ? (d0 > WIN) : (d0 <= WIN);
                const bool in1 = (MODE == 1) ? (d1 > WIN) : (d1 <= WIN);
                if (!in0) sc[jn][e]     = MASKV;
                if (!in1) sc[jn][2 + e] = MASKV;
            }
            tm0 = fmaxf(tm0, sc[jn][e]);
            tm1 = fmaxf(tm1, sc[jn][2 + e]);
        }
    }
    tm0 = fmaxf(tm0, __shfl_xor_sync(0xffffffffu, tm0, 1));
    tm0 = fmaxf(tm0, __shfl_xor_sync(0xffffffffu, tm0, 2));
    tm1 = fmaxf(tm1, __shfl_xor_sync(0xffffffffu, tm1, 1));
    tm1 = fmaxf(tm1, __shfl_xor_sync(0xffffffffu, tm1, 2));

    const float mn0 = fmaxf(m0, tm0), mn1 = fmaxf(m1, tm1);
    const float e0 = __expf(m0 - mn0), e1 = __expf(m1 - mn1);
    m0 = mn0; m1 = mn1; l0 *= e0; l1 *= e1;
#pragma unroll
    for (int nb = 0; nb < 8; nb++) {
        o[nb][0] *= e0; o[nb][1] *= e0; o[nb][2] *= e1; o[nb][3] *= e1;
    }

    float s0 = 0.f, s1 = 0.f;
#pragma unroll
    for (int c = 0; c < NKT / 16; c++) {
        const float p00 = __expf(sc[2 * c][0] - m0);
        const float p01 = __expf(sc[2 * c][1] - m0);
        const float p02 = __expf(sc[2 * c][2] - m1);
        const float p03 = __expf(sc[2 * c][3] - m1);
        const float p10 = __expf(sc[2 * c + 1][0] - m0);
        const float p11 = __expf(sc[2 * c + 1][1] - m0);
        const float p12 = __expf(sc[2 * c + 1][2] - m1);
        const float p13 = __expf(sc[2 * c + 1][3] - m1);
        s0 += (p00 + p01) + (p10 + p11);
        s1 += (p02 + p03) + (p12 + p13);
        uint32_t ah[4], al[4];
        psplit2(p00, p01, ah[0], al[0]);
        psplit2(p02, p03, ah[1], al[1]);
        psplit2(p10, p11, ah[2], al[2]);
        psplit2(p12, p13, ah[3], al[3]);
#pragma unroll
        for (int np = 0; np < 4; np++) {
            uint32_t v0, v1, v2, v3, w0, w1, w2, w3;
            const uint32_t va = sVh + (uint32_t)((np * 16 + brow) * ATS + c * 16 + bcol) * 2;
            ldm_x4(v0, v1, v2, v3, va);
            ldm_x4(w0, w1, w2, w3, va + ATILE * 2);
            float* oa = o[2 * np];
            float* ob = o[2 * np + 1];
            mma16816(oa[0], oa[1], oa[2], oa[3], ah[0], ah[1], ah[2], ah[3], v0, v1);
            mma16816(oa[0], oa[1], oa[2], oa[3], ah[0], ah[1], ah[2], ah[3], w0, w1);
            mma16816(oa[0], oa[1], oa[2], oa[3], al[0], al[1], al[2], al[3], v0, v1);
            mma16816(ob[0], ob[1], ob[2], ob[3], ah[0], ah[1], ah[2], ah[3], v2, v3);
            mma16816(ob[0], ob[1], ob[2], ob[3], ah[0], ah[1], ah[2], ah[3], w2, w3);
            mma16816(ob[0], ob[1], ob[2], ob[3], al[0], al[1], al[2], al[3], v2, v3);
        }
    }
    s0 += __shfl_xor_sync(0xffffffffu, s0, 1);
    s0 += __shfl_xor_sync(0xffffffffu, s0, 2);
    s1 += __shfl_xor_sync(0xffffffffu, s1, 1);
    s1 += __shfl_xor_sync(0xffffffffu, s1, 2);
    l0 += s0; l1 += s1;
}

// ================= band + global-col attention =================
__global__ __launch_bounds__(128) void attn_mma() {
    extern __shared__ __nv_bfloat16 sm_[];
    const uint32_t sb = smem_u32(sm_);
    const uint32_t sQh = sb, sQl = sb + ATILE * 2;

    const int qt = blockIdx.x, h = blockIdx.y, q0 = qt * 64;
    const int tid = threadIdx.x, wid = tid >> 5, lane = tid & 31;
    const int g = lane >> 2, t = lane & 3;
    const int brow = ((lane >> 4) << 3) + (lane & 7);
    const int bcol = ((lane >> 3) & 1) * 8;

    {
        const __nv_bfloat16* q0p = g_q0 + (size_t)h * SEQ * 64 + (size_t)q0 * 64;
        const __nv_bfloat16* q1p = g_q1 + (size_t)h * SEQ * 64 + (size_t)q0 * 64;
        for (int idx = tid; idx < 512; idx += 128) {
            const int r = idx >> 3, c = idx & 7;
            const uint32_t so = (uint32_t)(r * ATS + c * 8) * 2;
            cp16(sQh + so, q0p + r * 64 + c * 8);
            cp16(sQl + so, q1p + r * 64 + c * 8);
        }
    }
    CP_COMMIT();

    const int kb0 = q0 >= WIN ? q0 - WIN : 0;
    const int kb1 = (q0 + 64 + WIN) <= SEQ ? (q0 + 64 + WIN) : SEQ;
    const int nband = (kb1 - kb0) >> 6;
    const int T = nband + 1;

    auto stage_base = [&](int s) { return sb + (uint32_t)(2 + 4 * s) * ATILE * 2; };
    auto stage_band = [&](int s, int kb) {
        const uint32_t b = stage_base(s);
        const __nv_bfloat16* k0p = g_k0 + (size_t)h * SEQ * 64 + (size_t)kb * 64;
        const __nv_bfloat16* k1p = g_k1 + (size_t)h * SEQ * 64 + (size_t)kb * 64;
        const __nv_bfloat16* v0p = g_vt0 + (size_t)h * 64 * SEQ + kb;
        const __nv_bfloat16* v1p = g_vt1 + (size_t)h * 64 * SEQ + kb;
        for (int idx = tid; idx < 512; idx += 128) {
            const int r = idx >> 3, c = idx & 7;
            const uint32_t so = (uint32_t)(r * ATS + c * 8) * 2;
            cp16(b + so,                 k0p + r * 64 + c * 8);
            cp16(b + ATILE * 2 + so,     k1p + r * 64 + c * 8);
            cp16(b + 2 * ATILE * 2 + so, v0p + (size_t)r * SEQ + c * 8);
            cp16(b + 3 * ATILE * 2 + so, v1p + (size_t)r * SEQ + c * 8);
        }
    };
    auto stage_glob = [&](int s) {
        const uint32_t b = stage_base(s);
        const __nv_bfloat16* k0p = g_kg0 + (size_t)h * 32 * 64;
        const __nv_bfloat16* k1p = g_kg1 + (size_t)h * 32 * 64;
        const __nv_bfloat16* v0p = g_vtg0 + (size_t)h * 64 * 32;
        const __nv_bfloat16* v1p = g_vtg1 + (size_t)h * 64 * 32;
        for (int idx = tid; idx < 256; idx += 128) {
            const int r = idx >> 3, c = idx & 7;
            const uint32_t so = (uint32_t)(r * ATS + c * 8) * 2;
            cp16(b + so,             k0p + r * 64 + c * 8);
            cp16(b + ATILE * 2 + so, k1p + r * 64 + c * 8);
        }
        for (int idx = tid; idx < 256; idx += 128) {
            const int r = idx >> 2, c = idx & 3;
            const uint32_t so = (uint32_t)(r * ATS + c * 8) * 2;
            cp16(b + 2 * ATILE * 2 + so, v0p + r * 32 + c * 8);
            cp16(b + 3 * ATILE * 2 + so, v1p + r * 32 + c * 8);
        }
    };

    stage_band(0, kb0);
    CP_COMMIT();
    CP_WAIT1();
    __syncthreads();

    uint32_t qh[4][4], qlo[4][4];
    {
        const int ar = wid * 16 + ((lane >> 3) & 1) * 8 + (lane & 7);
        const int ac = (lane >> 4) * 8;
#pragma unroll
        for (int c = 0; c < 4; c++) {
            const uint32_t ad = sQh + (uint32_t)(ar * ATS + c * 16 + ac) * 2;
            ldm_x4(qh[c][0], qh[c][1], qh[c][2], qh[c][3], ad);
            ldm_x4(qlo[c][0], qlo[c][1], qlo[c][2], qlo[c][3], ad + ATILE * 2);
        }
    }

    float o[8][4];
#pragma unroll
    for (int nb = 0; nb < 8; nb++)
#pragma unroll
        for (int c = 0; c < 4; c++) o[nb][c] = 0.f;
    float m0 = -1e30f, m1 = -1e30f, l0 = 0.f, l1 = 0.f;
    const int qr0 = q0 + wid * 16 + g;

    for (int i = 0; i < T; i++) {
        if (i + 1 < T) {
            if (i + 1 < nband) stage_band((i + 1) & 1, kb0 + (i + 1) * 64);
            else stage_glob((i + 1) & 1);
            CP_COMMIT();
            CP_WAIT1();
        } else {
            CP_WAIT0();
        }
        __syncthreads();
        const uint32_t b = stage_base(i & 1);
        if (i < nband)
            attn_compute<64, 0>(b, b + 2 * ATILE * 2, kb0 + i * 64, qr0,
                                t, brow, bcol, qh, qlo, o, m0, m1, l0, l1);
        else
            attn_compute<32, 1>(b, b + 2 * ATILE * 2, 0, qr0,
                                t, brow, bcol, qh, qlo, o, m0, m1, l0, l1);
        __syncthreads();
    }

    const float i0 = 1.f / l0, i1 = 1.f / l1;
    const int row0 = q0 + wid * 16 + g;
#pragma unroll
    for (int nb = 0; nb < 8; nb++) {
        uint32_t h0, lo0, h1, lo1;
        psplit2(o[nb][0] * i0, o[nb][1] * i0, h0, lo0);
        psplit2(o[nb][2] * i1, o[nb][3] * i1, h1, lo1);
        const size_t ofs0 = (size_t)row0 * HID + h * HD + nb * 8 + 2 * t;
        const size_t ofs1 = ofs0 + (size_t)8 * HID;
        *(uint32_t*)&g_a0[ofs0] = h0; *(uint32_t*)&g_a1[ofs0] = lo0;
        *(uint32_t*)&g_a0[ofs1] = h1; *(uint32_t*)&g_a1[ofs1] = lo1;
    }
}

// ================= global rows: MMA over all 2048 keys =================
#define GA_QSZ   (32 * ATS * 2)
#define GA_TILES (2 * 2 * 4 * ATILE * 2)
#define GA_OBUF  (2 * 16 * 64 * 4)
#define GA_SMEM  (2 * GA_QSZ + GA_TILES + GA_OBUF + 256)

__global__ __launch_bounds__(128) void attn_global_mma() {
    extern __shared__ __nv_bfloat16 smg2[];
    const uint32_t sb = smem_u32(smg2);
    const int h = blockIdx.x;
    const int tid = threadIdx.x, wid = tid >> 5, lane = tid & 31;
    const int g = lane >> 2, t = lane & 3;
    const int rh = wid & 1, kp = wid >> 1;
    const int brow = ((lane >> 4) << 3) + (lane & 7);
    const int bcol = ((lane >> 3) & 1) * 8;

    const uint32_t sQ = sb;
    const uint32_t tiles0 = sb + 2 * GA_QSZ;
    float* obuf = (float*)(smg2 + (2 * 32 * ATS + 16 * ATILE));
    float* slm  = obuf + 2 * 16 * 64;
    float* sll  = slm + 32;

    {
        const __nv_bfloat16* q0p = g_q0 + (size_t)h * SEQ * 64;
        const __nv_bfloat16* q1p = g_q1 + (size_t)h * SEQ * 64;
        for (int idx = tid; idx < 256; idx += 128) {
            const int r = idx >> 3, c = idx & 7;
            const uint32_t so = (uint32_t)(r * ATS + c * 8) * 2;
            cp16(sQ + so,          q0p + (size_t)r * 64 * 64 + c * 8);
            cp16(sQ + GA_QSZ + so, q1p + (size_t)r * 64 * 64 + c * 8);
        }
    }
    CP_COMMIT();

    auto stage_tiles = [&](int st, int it) {
#pragma unroll
        for (int kpi = 0; kpi < 2; kpi++) {
            const int kt = (it * 2 + kpi) * 64;
            const uint32_t b = tiles0 + (uint32_t)((st * 2 + kpi) * 4) * ATILE * 2;
            const __nv_bfloat16* k0p = g_k0 + (size_t)h * SEQ * 64 + (size_t)kt * 64;
            const __nv_bfloat16* k1p = g_k1 + (size_t)h * SEQ * 64 + (size_t)kt * 64;
            const __nv_bfloat16* v0p = g_vt0 + (size_t)h * 64 * SEQ + kt;
            const __nv_bfloat16* v1p = g_vt1 + (size_t)h * 64 * SEQ + kt;
            for (int idx = tid; idx < 512; idx += 128) {
                const int r = idx >> 3, c = idx & 7;
                const uint32_t so = (uint32_t)(r * ATS + c * 8) * 2;
                cp16(b + so,                 k0p + r * 64 + c * 8);
                cp16(b + ATILE * 2 + so,     k1p + r * 64 + c * 8);
                cp16(b + 2 * ATILE * 2 + so, v0p + (size_t)r * SEQ + c * 8);
                cp16(b + 3 * ATILE * 2 + so, v1p + (size_t)r * SEQ + c * 8);
            }
        }
    };

    stage_tiles(0, 0);
    CP_COMMIT();
    CP_WAIT1();
    __syncthreads();

    uint32_t qh[4][4], qlo[4][4];
    {
        const int ar = rh * 16 + ((lane >> 3) & 1) * 8 + (lane & 7);
        const int ac = (lane >> 4) * 8;
#pragma unroll
        for (int c = 0; c < 4; c++) {
            const uint32_t ad = sQ + (uint32_t)(ar * ATS + c * 16 + ac) * 2;
            ldm_x4(qh[c][0], qh[c][1], qh[c][2], qh[c][3], ad);
            ldm_x4(qlo[c][0], qlo[c][1], qlo[c][2], qlo[c][3], ad + GA_QSZ);
        }
    }

    float o[8][4];
#pragma unroll
    for (int nb = 0; nb < 8; nb++)
#pragma unroll
        for (int c = 0; c < 4; c++) o[nb][c] = 0.f;
    float m0 = -1e30f, m1 = -1e30f, l0 = 0.f, l1 = 0.f;

    for (int it = 0; it < 16; it++) {
        if (it + 1 < 16) {
            stage_tiles((it + 1) & 1, it + 1);
            CP_COMMIT();
            CP_WAIT1();
        } else {
            CP_WAIT0();
        }
        __syncthreads();
        const uint32_t b = tiles0 + (uint32_t)(((it & 1) * 2 + kp) * 4) * ATILE * 2;
        attn_compute<64, 2>(b, b + 2 * ATILE * 2, 0, 0,
                            t, brow, bcol, qh, qlo, o, m0, m1, l0, l1);
        __syncthreads();
    }

    __syncthreads();
    if (kp == 1) {
        float* ob = obuf + rh * 16 * 64;
#pragma unroll
        for (int nb = 0; nb < 8; nb++) {
            ob[g * 64 + nb * 8 + 2 * t]           = o[nb][0];
            ob[g * 64 + nb * 8 + 2 * t + 1]       = o[nb][1];
            ob[(g + 8) * 64 + nb * 8 + 2 * t]     = o[nb][2];
            ob[(g + 8) * 64 + nb * 8 + 2 * t + 1] = o[nb][3];
        }
        if (t == 0) {
            slm[rh * 16 + g] = m0; slm[rh * 16 + g + 8] = m1;
            sll[rh * 16 + g] = l0; sll[rh * 16 + g + 8] = l1;
        }
    }
    __syncthreads();
    if (kp == 0) {
        const float pm0 = slm[rh * 16 + g], pm1 = slm[rh * 16 + g + 8];
        const float pl0 = sll[rh * 16 + g], pl1 = sll[rh * 16 + g + 8];
        const float M0 = fmaxf(m0, pm0), M1 = fmaxf(m1, pm1);
        const float e0 = __expf(m0 - M0), f0 = __expf(pm0 - M0);
        const float e1 = __expf(m1 - M1), f1 = __expf(pm1 - M1);
        const float L0 = l0 * e0 + pl0 * f0;
        const float L1 = l1 * e1 + pl1 * f1;
        const float i0 = 1.f / L0, i1 = 1.f / L1;
        float* ob = obuf + rh * 16 * 64;
        const int qi0 = (rh * 16 + g) * 64;
        const int qi1 = (rh * 16 + g + 8) * 64;
#pragma unroll
        for (int nb = 0; nb < 8; nb++) {
            const int cc = nb * 8 + 2 * t;
            const float r00 = (o[nb][0] * e0 + ob[g * 64 + cc] * f0) * i0;
            const float r01 = (o[nb][1] * e0 + ob[g * 64 + cc + 1] * f0) * i0;
            const float r10 = (o[nb][2] * e1 + ob[(g + 8) * 64 + cc] * f1) * i1;
            const float r11 = (o[nb][3] * e1 + ob[(g + 8) * 64 + cc + 1] * f1) * i1;
            uint32_t h0, lo0, h1, lo1;
            psplit2(r00, r01, h0, lo0);
            psplit2(r10, r11, h1, lo1);
            const size_t ofs0 = (size_t)qi0 * HID + h * HD + cc;
            const size_t ofs1 = (size_t)qi1 * HID + h * HD + cc;
            *(uint32_t*)&g_a0[ofs0] = h0; *(uint32_t*)&g_a1[ofs0] = lo0;
            *(uint32_t*)&g_a0[ofs1] = h1; *(uint32_t*)&g_a1[ofs1] = lo1;
        }
    }
}

// ---------------- launch ----------------
extern "C" void kernel_launch(void* const* d_in, const int* in_sizes, int n_in,
                              void* d_out, int out_size) {
    const float* x    = (const float*)d_in[0];
    const float* Wqkv = (const float*)d_in[1];
    const float* Wout = (const float*)d_in[2];
    float* out = (float*)d_out;

    float* qkv = nullptr;
    cudaGetSymbolAddress((void**)&qkv, g_qkv);
    __half *xh, *wqh, *wql;
    __nv_bfloat16 *a0, *a1, *wo0, *wo1;
    cudaGetSymbolAddress((void**)&xh,  g_xh);
    cudaGetSymbolAddress((void**)&wqh, g_wqh); cudaGetSymbolAddress((void**)&wql, g_wql);
    cudaGetSymbolAddress((void**)&a0,  g_a0);  cudaGetSymbolAddress((void**)&a1,  g_a1);
    cudaGetSymbolAddress((void**)&wo0, g_wo0); cudaGetSymbolAddress((void**)&wo1, g_wo1);

    cudaFuncSetAttribute(gemm_f16, cudaFuncAttributeMaxDynamicSharedMemorySize, GF_SMEM);
    cudaFuncSetAttribute(gemm_mma, cudaFuncAttributeMaxDynamicSharedMemorySize, GT_SMEM);
    cudaFuncSetAttribute(attn_mma, cudaFuncAttributeMaxDynamicSharedMemorySize, AT_SMEM);
    cudaFuncSetAttribute(attn_global_mma, cudaFuncAttributeMaxDynamicSharedMemorySize, GA_SMEM);

    // 0) conversions
    conv_half<<<(SEQ * HID / 4 + 255) / 256, 256>>>(x, xh, SEQ * HID / 4);
    split_half<<<(H3 * HID / 4 + 255) / 256, 256>>>(Wqkv, wqh, wql, H3 * HID / 4);
    split_bf16<<<(HID * HID / 4 + 255) / 256, 256>>>(Wout, wo0, wo1, HID * HID / 4);

    // 1) qkv = x @ Wqkv^T  (fp16 2-term)
    gemm_f16<<<dim3(H3 / 128, SEQ / 128), 256, GF_SMEM>>>(xh, wqh, wql, qkv, SEQ, H3, HID);

    // 2) per-head split operands
    prep_attn<<<dim3(SEQ / 64, NHEAD), 256>>>();

    // 3) sparse attention -> g_a0/g_a1
    attn_mma<<<dim3(SEQ / 64, NHEAD), 128, AT_SMEM>>>();
    attn_global_mma<<<NHEAD, 128, GA_SMEM>>>();

    // 4) out = attn @ Wout^T  (bf16 3-term)
    gemm_mma<<<dim3(HID / 128, SEQ / 128), 256, GT_SMEM>>>(a0, a1, wo0, wo1, out, SEQ, HID, HID);
}

// round 11
// speedup vs baseline: 6.0334x; 1.1001x over previous
#include <cuda_runtime.h>
#include <cuda_fp16.h>
#include <cstdint>

// ---------------- problem constants ----------------
#define SEQ   2048
#define HID   1024
#define H3    3072
#define NHEAD 16
#define HD    64
#define WIN   128
#define GSTRIDE 64

// ---------------- mma / ldmatrix / cp.async helpers ----------------
__device__ __forceinline__ void mma16816h(float& c0, float& c1, float& c2, float& c3,
                                          uint32_t a0, uint32_t a1, uint32_t a2, uint32_t a3,
                                          uint32_t b0, uint32_t b1) {
    asm volatile(
        "mma.sync.aligned.m16n8k16.row.col.f32.f16.f16.f32 "
        "{%0,%1,%2,%3}, {%4,%5,%6,%7}, {%8,%9}, {%0,%1,%2,%3};"
        : "+f"(c0), "+f"(c1), "+f"(c2), "+f"(c3)
        : "r"(a0), "r"(a1), "r"(a2), "r"(a3), "r"(b0), "r"(b1));
}
__device__ __forceinline__ void ldm_x4(uint32_t& r0, uint32_t& r1, uint32_t& r2, uint32_t& r3,
                                       uint32_t addr) {
    asm volatile("ldmatrix.sync.aligned.m8n8.x4.shared.b16 {%0,%1,%2,%3}, [%4];"
                 : "=r"(r0), "=r"(r1), "=r"(r2), "=r"(r3) : "r"(addr));
}
__device__ __forceinline__ uint32_t smem_u32(const void* p) {
    uint32_t a;
    asm("{ .reg .u64 t; cvta.to.shared.u64 t, %1; cvt.u32.u64 %0, t; }" : "=r"(a) : "l"(p));
    return a;
}
__device__ __forceinline__ void cp16(uint32_t saddr, const void* gptr) {
    asm volatile("cp.async.cg.shared.global [%0], [%1], 16;" :: "r"(saddr), "l"(gptr));
}
#define CP_COMMIT() asm volatile("cp.async.commit_group;" ::: "memory")
#define CP_WAIT1()  asm volatile("cp.async.wait_group 1;" ::: "memory")
#define CP_WAIT0()  asm volatile("cp.async.wait_group 0;" ::: "memory")

// fp16 helpers
__device__ __forceinline__ uint32_t packh2(float a, float b) {
    __half2 h = __floats2half2_rn(a, b);
    uint32_t r; *(__half2*)&r = h; return r;
}
__device__ __forceinline__ void hsplit(float x, __half& hi, __half& lo) {
    hi = __float2half_rn(x);
    lo = __float2half_rn(x - __half2float(hi));
}
__device__ __forceinline__ void hsplit2(float a, float b, uint32_t& hi, uint32_t& lo) {
    __half ha = __float2half_rn(a), hb = __float2half_rn(b);
    float ra = a - __half2float(ha), rb = b - __half2float(hb);
    *(__half2*)&hi = __halves2half2(ha, hb);
    lo = packh2(ra, rb);
}

// ---------------- scratch (device globals) ----------------
__device__ float g_qkv[SEQ * H3];
__device__ __align__(16) __half g_xh[SEQ * HID];
__device__ __align__(16) __half g_wqh[H3 * HID], g_wql[H3 * HID];
__device__ __align__(16) __half g_woh[HID * HID], g_wol[HID * HID];
__device__ __align__(16) __half g_ah[SEQ * HID];
__device__ __align__(16) __half g_qh[NHEAD * SEQ * 64];
__device__ __align__(16) __half g_kh[NHEAD * SEQ * 64], g_kl[NHEAD * SEQ * 64];
__device__ __align__(16) __half g_vth[NHEAD * 64 * SEQ], g_vtl[NHEAD * 64 * SEQ];
__device__ __align__(16) __half g_kgh[NHEAD * 32 * 64], g_kgl[NHEAD * 32 * 64];
__device__ __align__(16) __half g_vtgh[NHEAD * 64 * 32], g_vtgl[NHEAD * 64 * 32];

// ---------------- conversions ----------------
__global__ __launch_bounds__(256) void conv_half(const float* __restrict__ in,
                                                 __half* __restrict__ out, int n4) {
    int i = blockIdx.x * blockDim.x + threadIdx.x;
    if (i >= n4) return;
    float4 v = ((const float4*)in)[i];
    uint32_t* op = (uint32_t*)out;
    op[2 * i]     = packh2(v.x, v.y);
    op[2 * i + 1] = packh2(v.z, v.w);
}
__global__ __launch_bounds__(256) void split_half(const float* __restrict__ in,
                                                  __half* __restrict__ hi,
                                                  __half* __restrict__ lo, int n4) {
    int i = blockIdx.x * blockDim.x + threadIdx.x;
    if (i >= n4) return;
    float4 v = ((const float4*)in)[i];
    uint32_t h0, l0, h1, l1;
    hsplit2(v.x, v.y, h0, l0);
    hsplit2(v.z, v.w, h1, l1);
    uint32_t* hp = (uint32_t*)hi;
    uint32_t* lp = (uint32_t*)lo;
    hp[2 * i] = h0; hp[2 * i + 1] = h1;
    lp[2 * i] = l0; lp[2 * i + 1] = l1;
}

// ---------------- fp16 2-term GEMM: C = A @ (Bh+Bl)^T ----------------
// 256 thr, 8 warps 2(M)x4(N), warp tile 64x32, BK=32, 2 stages x 3 buffers.
#define SSTR 40
#define BUFE (128 * SSTR)
#define FSTGE (3 * BUFE)
#define GF_SMEM (2 * FSTGE * 2)

__global__ __launch_bounds__(256) void gemm_f16(const __half* __restrict__ Ag,
                                                const __half* __restrict__ Bhg,
                                                const __half* __restrict__ Blg,
                                                float* __restrict__ C,
                                                int M, int N, int K) {
    extern __shared__ __half smf[];
    const uint32_t sbase = smem_u32(smf);

    const int tid = threadIdx.x;
    const int wid = tid >> 5;
    const int lane = tid & 31;
    const int g = lane >> 2;
    const int t = lane & 3;
    const int warp_m = (wid & 1) * 64;
    const int warp_n = (wid >> 1) * 32;
    const int tile_m = blockIdx.y * 128;
    const int tile_n = blockIdx.x * 128;

    const int a_row = warp_m + ((lane >> 3) & 1) * 8 + (lane & 7);
    const int a_col = (lane >> 4) * 8;
    const int b_row = warp_n + (lane >> 4) * 8 + (lane & 7);
    const int b_col = ((lane >> 3) & 1) * 8;

    float acc[4][4][4];
#pragma unroll
    for (int im = 0; im < 4; im++)
#pragma unroll
        for (int jn = 0; jn < 4; jn++)
#pragma unroll
            for (int c = 0; c < 4; c++) acc[im][jn][c] = 0.f;

    auto load_stage = [&](int st, int k0) {
        const uint32_t sb = sbase + (uint32_t)st * FSTGE * 2;
#pragma unroll
        for (int rep = 0; rep < 2; rep++) {
            const int idx = tid + 256 * rep;
            const int row = idx >> 2;
            const int c8  = (idx & 3) * 8;
            const uint32_t so = (uint32_t)(row * SSTR + c8) * 2;
            const size_t goA = (size_t)(tile_m + row) * K + k0 + c8;
            const size_t goB = (size_t)(tile_n + row) * K + k0 + c8;
            cp16(sb + 0 * BUFE * 2 + so, Ag + goA);
            cp16(sb + 1 * BUFE * 2 + so, Bhg + goB);
            cp16(sb + 2 * BUFE * 2 + so, Blg + goB);
        }
    };

    const int nchunks = K >> 5;
    load_stage(0, 0);
    CP_COMMIT();

    for (int ch = 0; ch < nchunks; ch++) {
        if (ch + 1 < nchunks) load_stage((ch + 1) & 1, (ch + 1) << 5);
        CP_COMMIT();
        CP_WAIT1();
        __syncthreads();

        const uint32_t sb = sbase + (uint32_t)(ch & 1) * FSTGE * 2;
#pragma unroll
        for (int ks = 0; ks < 32; ks += 16) {
            uint32_t aH[4][4];
#pragma unroll
            for (int im = 0; im < 4; im++) {
                const uint32_t ad = sb + (uint32_t)((a_row + im * 16) * SSTR + ks + a_col) * 2;
                ldm_x4(aH[im][0], aH[im][1], aH[im][2], aH[im][3], ad);
            }
#pragma unroll
            for (int jp = 0; jp < 2; jp++) {
                uint32_t bh0, bh1, bh2, bh3, bl0, bl1, bl2, bl3;
                const uint32_t bd = sb + 1 * BUFE * 2
                                  + (uint32_t)((b_row + jp * 16) * SSTR + ks + b_col) * 2;
                ldm_x4(bh0, bh1, bh2, bh3, bd);
                ldm_x4(bl0, bl1, bl2, bl3, bd + BUFE * 2);
#pragma unroll
                for (int im = 0; im < 4; im++) {
                    float* a0p = acc[im][2 * jp];
                    float* a1p = acc[im][2 * jp + 1];
                    mma16816h(a0p[0], a0p[1], a0p[2], a0p[3],
                              aH[im][0], aH[im][1], aH[im][2], aH[im][3], bh0, bh1);
                    mma16816h(a0p[0], a0p[1], a0p[2], a0p[3],
                              aH[im][0], aH[im][1], aH[im][2], aH[im][3], bl0, bl1);
                    mma16816h(a1p[0], a1p[1], a1p[2], a1p[3],
                              aH[im][0], aH[im][1], aH[im][2], aH[im][3], bh2, bh3);
                    mma16816h(a1p[0], a1p[1], a1p[2], a1p[3],
                              aH[im][0], aH[im][1], aH[im][2], aH[im][3], bl2, bl3);
                }
            }
        }
        __syncthreads();
    }

#pragma unroll
    for (int im = 0; im < 4; im++) {
        const int row = tile_m + warp_m + im * 16 + g;
#pragma unroll
        for (int jn = 0; jn < 4; jn++) {
            const int col = tile_n + warp_n + jn * 8 + 2 * t;
            float2 v0; v0.x = acc[im][jn][0]; v0.y = acc[im][jn][1];
            float2 v1; v1.x = acc[im][jn][2]; v1.y = acc[im][jn][3];
            *(float2*)(C + (size_t)row * N + col)       = v0;
            *(float2*)(C + (size_t)(row + 8) * N + col) = v1;
        }
    }
}

// ---------------- prep: per-head fp16 Q (plain) / K,Vt (hi+lo) ----------------
#define PVS 66
__global__ __launch_bounds__(256) void prep_attn() {
    const int st = blockIdx.x;
    const int h  = blockIdx.y;
    const int s0 = st * 64;
    const int tid = threadIdx.x;

    __shared__ __half vth[64][PVS], vtl[64][PVS];

    for (int idx = tid; idx < 1024; idx += 256) {
        const int r = idx >> 4, c4 = (idx & 15) << 2;
        const size_t base = (size_t)(s0 + r) * H3 + h * HD + c4;
        const size_t qo = (size_t)h * SEQ * 64 + (size_t)(s0 + r) * 64 + c4;
        // Q plain fp16 (scaled)
        float4 q = *(const float4*)(g_qkv + base);
        *(uint32_t*)&g_qh[qo]     = packh2(q.x * 0.125f, q.y * 0.125f);
        *(uint32_t*)&g_qh[qo + 2] = packh2(q.z * 0.125f, q.w * 0.125f);
        // K fp16 hi/lo
        float4 k = *(const float4*)(g_qkv + base + HID);
        uint32_t h0, l0, h1, l1;
        hsplit2(k.x, k.y, h0, l0);
        hsplit2(k.z, k.w, h1, l1);
        *(uint32_t*)&g_kh[qo] = h0; *(uint32_t*)&g_kh[qo + 2] = h1;
        *(uint32_t*)&g_kl[qo] = l0; *(uint32_t*)&g_kl[qo + 2] = l1;
        // V -> transposed smem (fp16 hi/lo)
        float4 v = *(const float4*)(g_qkv + base + 2 * HID);
        hsplit(v.x, vth[c4 + 0][r], vtl[c4 + 0][r]);
        hsplit(v.y, vth[c4 + 1][r], vtl[c4 + 1][r]);
        hsplit(v.z, vth[c4 + 2][r], vtl[c4 + 2][r]);
        hsplit(v.w, vth[c4 + 3][r], vtl[c4 + 3][r]);
    }
    __syncthreads();

    for (int idx = tid; idx < 2048; idx += 256) {
        const int d = idx >> 5, cp = (idx & 31) << 1;
        const size_t vo = (size_t)h * 64 * SEQ + (size_t)d * SEQ + s0 + cp;
        *(uint32_t*)&g_vth[vo] = *(const uint32_t*)&vth[d][cp];
        *(uint32_t*)&g_vtl[vo] = *(const uint32_t*)&vtl[d][cp];
    }
    if (tid < 16) {
        const int c4 = tid * 4;
        float4 k = *(const float4*)(g_qkv + (size_t)s0 * H3 + HID + h * HD + c4);
        uint32_t h0, l0, h1, l1;
        hsplit2(k.x, k.y, h0, l0);
        hsplit2(k.z, k.w, h1, l1);
        const size_t ko = (size_t)h * 32 * 64 + (size_t)st * 64 + c4;
        *(uint32_t*)&g_kgh[ko] = h0; *(uint32_t*)&g_kgh[ko + 2] = h1;
        *(uint32_t*)&g_kgl[ko] = l0; *(uint32_t*)&g_kgl[ko + 2] = l1;
    }
    if (tid < 64) {
        const size_t go = (size_t)h * 64 * 32 + (size_t)tid * 32 + st;
        g_vtgh[go] = vth[tid][0];
        g_vtgl[go] = vtl[tid][0];
    }
}

// ================= MMA attention core (fp16 2-term) =================
#define MASKV (-3.0e38f)
#define ATS   72
#define ATILE (64 * ATS)
#define AT_SMEM ((1 + 8) * ATILE * 2)

template<int NKT, int MODE>
__device__ __forceinline__ void attn_compute(
    uint32_t sKh, uint32_t sVh, int kb, int qr0,
    int t, int brow, int bcol,
    const uint32_t qh[4][4],
    float o[8][4], float& m0, float& m1, float& l0, float& l1)
{
    constexpr int NJ = NKT / 8;
    float sc[NJ][4];

    // ---- S = Q (Kh + Kl)^T ----
#pragma unroll
    for (int jp = 0; jp < NKT / 16; jp++) {
#pragma unroll
        for (int e = 0; e < 4; e++) { sc[2 * jp][e] = 0.f; sc[2 * jp + 1][e] = 0.f; }
#pragma unroll
        for (int c = 0; c < 4; c++) {
            uint32_t b0, b1, b2, b3, d0, d1, d2, d3;
            const uint32_t ka = sKh + (uint32_t)((jp * 16 + brow) * ATS + c * 16 + bcol) * 2;
            ldm_x4(b0, b1, b2, b3, ka);
            ldm_x4(d0, d1, d2, d3, ka + ATILE * 2);
            float* s0p = sc[2 * jp];
            float* s1p = sc[2 * jp + 1];
            mma16816h(s0p[0], s0p[1], s0p[2], s0p[3],
                      qh[c][0], qh[c][1], qh[c][2], qh[c][3], b0, b1);
            mma16816h(s0p[0], s0p[1], s0p[2], s0p[3],
                      qh[c][0], qh[c][1], qh[c][2], qh[c][3], d0, d1);
            mma16816h(s1p[0], s1p[1], s1p[2], s1p[3],
                      qh[c][0], qh[c][1], qh[c][2], qh[c][3], b2, b3);
            mma16816h(s1p[0], s1p[1], s1p[2], s1p[3],
                      qh[c][0], qh[c][1], qh[c][2], qh[c][3], d2, d3);
        }
    }

    // ---- mask + row max ----
    float tm0 = MASKV, tm1 = MASKV;
#pragma unroll
    for (int jn = 0; jn < NJ; jn++) {
#pragma unroll
        for (int e = 0; e < 2; e++) {
            if (MODE < 2) {
                const int ci  = jn * 8 + 2 * t + e;
                const int key = (MODE == 1) ? (ci * GSTRIDE) : (kb + ci);
                int d0 = qr0 - key; d0 = d0 < 0 ? -d0 : d0;
                int d1 = qr0 + 8 - key; d1 = d1 < 0 ? -d1 : d1;
                const bool in0 = (MODE == 1) ? (d0 > WIN) : (d0 <= WIN);
                const bool in1 = (MODE == 1) ? (d1 > WIN) : (d1 <= WIN);
                if (!in0) sc[jn][e]     = MASKV;
                if (!in1) sc[jn][2 + e] = MASKV;
            }
            tm0 = fmaxf(tm0, sc[jn][e]);
            tm1 = fmaxf(tm1, sc[jn][2 + e]);
        }
    }
    tm0 = fmaxf(tm0, __shfl_xor_sync(0xffffffffu, tm0, 1));
    tm0 = fmaxf(tm0, __shfl_xor_sync(0xffffffffu, tm0, 2));
    tm1 = fmaxf(tm1, __shfl_xor_sync(0xffffffffu, tm1, 1));
    tm1 = fmaxf(tm1, __shfl_xor_sync(0xffffffffu, tm1, 2));

    const float mn0 = fmaxf(m0, tm0), mn1 = fmaxf(m1, tm1);
    const float e0 = __expf(m0 - mn0), e1 = __expf(m1 - mn1);
    m0 = mn0; m1 = mn1; l0 *= e0; l1 *= e1;
#pragma unroll
    for (int nb = 0; nb < 8; nb++) {
        o[nb][0] *= e0; o[nb][1] *= e0; o[nb][2] *= e1; o[nb][3] *= e1;
    }

    // ---- P = exp(S - m) (plain fp16); O += P (Vh + Vl) ----
    float s0 = 0.f, s1 = 0.f;
#pragma unroll
    for (int c = 0; c < NKT / 16; c++) {
        const float p00 = __expf(sc[2 * c][0] - m0);
        const float p01 = __expf(sc[2 * c][1] - m0);
        const float p02 = __expf(sc[2 * c][2] - m1);
        const float p03 = __expf(sc[2 * c][3] - m1);
        const float p10 = __expf(sc[2 * c + 1][0] - m0);
        const float p11 = __expf(sc[2 * c + 1][1] - m0);
        const float p12 = __expf(sc[2 * c + 1][2] - m1);
        const float p13 = __expf(sc[2 * c + 1][3] - m1);
        s0 += (p00 + p01) + (p10 + p11);
        s1 += (p02 + p03) + (p12 + p13);
        uint32_t ah[4];
        ah[0] = packh2(p00, p01);
        ah[1] = packh2(p02, p03);
        ah[2] = packh2(p10, p11);
        ah[3] = packh2(p12, p13);
#pragma unroll
        for (int np = 0; np < 4; np++) {
            uint32_t v0, v1, v2, v3, w0, w1, w2, w3;
            const uint32_t va = sVh + (uint32_t)((np * 16 + brow) * ATS + c * 16 + bcol) * 2;
            ldm_x4(v0, v1, v2, v3, va);
            ldm_x4(w0, w1, w2, w3, va + ATILE * 2);
            float* oa = o[2 * np];
            float* ob = o[2 * np + 1];
            mma16816h(oa[0], oa[1], oa[2], oa[3], ah[0], ah[1], ah[2], ah[3], v0, v1);
            mma16816h(oa[0], oa[1], oa[2], oa[3], ah[0], ah[1], ah[2], ah[3], w0, w1);
            mma16816h(ob[0], ob[1], ob[2], ob[3], ah[0], ah[1], ah[2], ah[3], v2, v3);
            mma16816h(ob[0], ob[1], ob[2], ob[3], ah[0], ah[1], ah[2], ah[3], w2, w3);
        }
    }
    s0 += __shfl_xor_sync(0xffffffffu, s0, 1);
    s0 += __shfl_xor_sync(0xffffffffu, s0, 2);
    s1 += __shfl_xor_sync(0xffffffffu, s1, 1);
    s1 += __shfl_xor_sync(0xffffffffu, s1, 2);
    l0 += s0; l1 += s1;
}

// ================= band + global-col attention =================
__global__ __launch_bounds__(128) void attn_mma() {
    extern __shared__ __half sm_[];
    const uint32_t sb = smem_u32(sm_);
    const uint32_t sQ = sb;

    const int qt = blockIdx.x, h = blockIdx.y, q0 = qt * 64;
    const int tid = threadIdx.x, wid = tid >> 5, lane = tid & 31;
    const int g = lane >> 2, t = lane & 3;
    const int brow = ((lane >> 4) << 3) + (lane & 7);
    const int bcol = ((lane >> 3) & 1) * 8;

    {
        const __half* qp = g_qh + (size_t)h * SEQ * 64 + (size_t)q0 * 64;
        for (int idx = tid; idx < 512; idx += 128) {
            const int r = idx >> 3, c = idx & 7;
            cp16(sQ + (uint32_t)(r * ATS + c * 8) * 2, qp + r * 64 + c * 8);
        }
    }
    CP_COMMIT();

    const int kb0 = q0 >= WIN ? q0 - WIN : 0;
    const int kb1 = (q0 + 64 + WIN) <= SEQ ? (q0 + 64 + WIN) : SEQ;
    const int nband = (kb1 - kb0) >> 6;
    const int T = nband + 1;

    auto stage_base = [&](int s) { return sb + (uint32_t)(1 + 4 * s) * ATILE * 2; };
    auto stage_band = [&](int s, int kb) {
        const uint32_t b = stage_base(s);
        const __half* khp = g_kh + (size_t)h * SEQ * 64 + (size_t)kb * 64;
        const __half* klp = g_kl + (size_t)h * SEQ * 64 + (size_t)kb * 64;
        const __half* vhp = g_vth + (size_t)h * 64 * SEQ + kb;
        const __half* vlp = g_vtl + (size_t)h * 64 * SEQ + kb;
        for (int idx = tid; idx < 512; idx += 128) {
            const int r = idx >> 3, c = idx & 7;
            const uint32_t so = (uint32_t)(r * ATS + c * 8) * 2;
            cp16(b + so,                 khp + r * 64 + c * 8);
            cp16(b + ATILE * 2 + so,     klp + r * 64 + c * 8);
            cp16(b + 2 * ATILE * 2 + so, vhp + (size_t)r * SEQ + c * 8);
            cp16(b + 3 * ATILE * 2 + so, vlp + (size_t)r * SEQ + c * 8);
        }
    };
    auto stage_glob = [&](int s) {
        const uint32_t b = stage_base(s);
        const __half* khp = g_kgh + (size_t)h * 32 * 64;
        const __half* klp = g_kgl + (size_t)h * 32 * 64;
        const __half* vhp = g_vtgh + (size_t)h * 64 * 32;
        const __half* vlp = g_vtgl + (size_t)h * 64 * 32;
        for (int idx = tid; idx < 256; idx += 128) {
            const int r = idx >> 3, c = idx & 7;
            const uint32_t so = (uint32_t)(r * ATS + c * 8) * 2;
            cp16(b + so,             khp + r * 64 + c * 8);
            cp16(b + ATILE * 2 + so, klp + r * 64 + c * 8);
        }
        for (int idx = tid; idx < 256; idx += 128) {
            const int r = idx >> 2, c = idx & 3;
            const uint32_t so = (uint32_t)(r * ATS + c * 8) * 2;
            cp16(b + 2 * ATILE * 2 + so, vhp + r * 32 + c * 8);
            cp16(b + 3 * ATILE * 2 + so, vlp + r * 32 + c * 8);
        }
    };

    stage_band(0, kb0);
    CP_COMMIT();
    CP_WAIT1();
    __syncthreads();

    uint32_t qh[4][4];
    {
        const int ar = wid * 16 + ((lane >> 3) & 1) * 8 + (lane & 7);
        const int ac = (lane >> 4) * 8;
#pragma unroll
        for (int c = 0; c < 4; c++) {
            const uint32_t ad = sQ + (uint32_t)(ar * ATS + c * 16 + ac) * 2;
            ldm_x4(qh[c][0], qh[c][1], qh[c][2], qh[c][3], ad);
        }
    }

    float o[8][4];
#pragma unroll
    for (int nb = 0; nb < 8; nb++)
#pragma unroll
        for (int c = 0; c < 4; c++) o[nb][c] = 0.f;
    float m0 = -1e30f, m1 = -1e30f, l0 = 0.f, l1 = 0.f;
    const int qr0 = q0 + wid * 16 + g;

    for (int i = 0; i < T; i++) {
        if (i + 1 < T) {
            if (i + 1 < nband) stage_band((i + 1) & 1, kb0 + (i + 1) * 64);
            else stage_glob((i + 1) & 1);
            CP_COMMIT();
            CP_WAIT1();
        } else {
            CP_WAIT0();
        }
        __syncthreads();
        const uint32_t b = stage_base(i & 1);
        if (i < nband)
            attn_compute<64, 0>(b, b + 2 * ATILE * 2, kb0 + i * 64, qr0,
                                t, brow, bcol, qh, o, m0, m1, l0, l1);
        else
            attn_compute<32, 1>(b, b + 2 * ATILE * 2, 0, qr0,
                                t, brow, bcol, qh, o, m0, m1, l0, l1);
        __syncthreads();
    }

    // ---- epilogue: write plain fp16 attention output ----
    const float i0 = 1.f / l0, i1 = 1.f / l1;
    const int row0 = q0 + wid * 16 + g;
#pragma unroll
    for (int nb = 0; nb < 8; nb++) {
        const size_t ofs0 = (size_t)row0 * HID + h * HD + nb * 8 + 2 * t;
        const size_t ofs1 = ofs0 + (size_t)8 * HID;
        *(uint32_t*)&g_ah[ofs0] = packh2(o[nb][0] * i0, o[nb][1] * i0);
        *(uint32_t*)&g_ah[ofs1] = packh2(o[nb][2] * i1, o[nb][3] * i1);
    }
}

// ================= global rows: MMA over all 2048 keys =================
#define GA_QSZ   (32 * ATS * 2)
#define GA_TILES (2 * 2 * 4 * ATILE * 2)
#define GA_OBUF  (2 * 16 * 64 * 4)
#define GA_SMEM  (GA_QSZ + GA_TILES + GA_OBUF + 256)

__global__ __launch_bounds__(128) void attn_global_mma() {
    extern __shared__ __half smg2[];
    const uint32_t sb = smem_u32(smg2);
    const int h = blockIdx.x;
    const int tid = threadIdx.x, wid = tid >> 5, lane = tid & 31;
    const int g = lane >> 2, t = lane & 3;
    const int rh = wid & 1, kp = wid >> 1;
    const int brow = ((lane >> 4) << 3) + (lane & 7);
    const int bcol = ((lane >> 3) & 1) * 8;

    const uint32_t sQ = sb;
    const uint32_t tiles0 = sb + GA_QSZ;
    float* obuf = (float*)(smg2 + (32 * ATS + 16 * ATILE));
    float* slm  = obuf + 2 * 16 * 64;
    float* sll  = slm + 32;

    {
        const __half* qp = g_qh + (size_t)h * SEQ * 64;
        for (int idx = tid; idx < 256; idx += 128) {
            const int r = idx >> 3, c = idx & 7;
            cp16(sQ + (uint32_t)(r * ATS + c * 8) * 2, qp + (size_t)r * 64 * 64 + c * 8);
        }
    }
    CP_COMMIT();

    auto stage_tiles = [&](int st, int it) {
#pragma unroll
        for (int kpi = 0; kpi < 2; kpi++) {
            const int kt = (it * 2 + kpi) * 64;
            const uint32_t b = tiles0 + (uint32_t)((st * 2 + kpi) * 4) * ATILE * 2;
            const __half* khp = g_kh + (size_t)h * SEQ * 64 + (size_t)kt * 64;
            const __half* klp = g_kl + (size_t)h * SEQ * 64 + (size_t)kt * 64;
            const __half* vhp = g_vth + (size_t)h * 64 * SEQ + kt;
            const __half* vlp = g_vtl + (size_t)h * 64 * SEQ + kt;
            for (int idx = tid; idx < 512; idx += 128) {
                const int r = idx >> 3, c = idx & 7;
                const uint32_t so = (uint32_t)(r * ATS + c * 8) * 2;
                cp16(b + so,                 khp + r * 64 + c * 8);
                cp16(b + ATILE * 2 + so,     klp + r * 64 + c * 8);
                cp16(b + 2 * ATILE * 2 + so, vhp + (size_t)r * SEQ + c * 8);
                cp16(b + 3 * ATILE * 2 + so, vlp + (size_t)r * SEQ + c * 8);
            }
        }
    };

    stage_tiles(0, 0);
    CP_COMMIT();
    CP_WAIT1();
    __syncthreads();

    uint32_t qh[4][4];
    {
        const int ar = rh * 16 + ((lane >> 3) & 1) * 8 + (lane & 7);
        const int ac = (lane >> 4) * 8;
#pragma unroll
        for (int c = 0; c < 4; c++) {
            const uint32_t ad = sQ + (uint32_t)(ar * ATS + c * 16 + ac) * 2;
            ldm_x4(qh[c][0], qh[c][1], qh[c][2], qh[c][3], ad);
        }
    }

    float o[8][4];
#pragma unroll
    for (int nb = 0; nb < 8; nb++)
#pragma unroll
        for (int c = 0; c < 4; c++) o[nb][c] = 0.f;
    float m0 = -1e30f, m1 = -1e30f, l0 = 0.f, l1 = 0.f;

    for (int it = 0; it < 16; it++) {
        if (it + 1 < 16) {
            stage_tiles((it + 1) & 1, it + 1);
            CP_COMMIT();
            CP_WAIT1();
        } else {
            CP_WAIT0();
        }
        __syncthreads();
        const uint32_t b = tiles0 + (uint32_t)(((it & 1) * 2 + kp) * 4) * ATILE * 2;
        attn_compute<64, 2>(b, b + 2 * ATILE * 2, 0, 0,
                            t, brow, bcol, qh, o, m0, m1, l0, l1);
        __syncthreads();
    }

    // ---- merge kp=1 into kp=0 ----
    __syncthreads();
    if (kp == 1) {
        float* ob = obuf + rh * 16 * 64;
#pragma unroll
        for (int nb = 0; nb < 8; nb++) {
            ob[g * 64 + nb * 8 + 2 * t]           = o[nb][0];
            ob[g * 64 + nb * 8 + 2 * t + 1]       = o[nb][1];
            ob[(g + 8) * 64 + nb * 8 + 2 * t]     = o[nb][2];
            ob[(g + 8) * 64 + nb * 8 + 2 * t + 1] = o[nb][3];
        }
        if (t == 0) {
            slm[rh * 16 + g] = m0; slm[rh * 16 + g + 8] = m1;
            sll[rh * 16 + g] = l0; sll[rh * 16 + g + 8] = l1;
        }
    }
    __syncthreads();
    if (kp == 0) {
        const float pm0 = slm[rh * 16 + g], pm1 = slm[rh * 16 + g + 8];
        const float pl0 = sll[rh * 16 + g], pl1 = sll[rh * 16 + g + 8];
        const float M0 = fmaxf(m0, pm0), M1 = fmaxf(m1, pm1);
        const float e0 = __expf(m0 - M0), f0 = __expf(pm0 - M0);
        const float e1 = __expf(m1 - M1), f1 = __expf(pm1 - M1);
        const float L0 = l0 * e0 + pl0 * f0;
        const float L1 = l1 * e1 + pl1 * f1;
        const float i0 = 1.f / L0, i1 = 1.f / L1;
        float* ob = obuf + rh * 16 * 64;
        const int qi0 = (rh * 16 + g) * 64;
        const int qi1 = (rh * 16 + g + 8) * 64;
#pragma unroll
        for (int nb = 0; nb < 8; nb++) {
            const int cc = nb * 8 + 2 * t;
            const float r00 = (o[nb][0] * e0 + ob[g * 64 + cc] * f0) * i0;
            const float r01 = (o[nb][1] * e0 + ob[g * 64 + cc + 1] * f0) * i0;
            const float r10 = (o[nb][2] * e1 + ob[(g + 8) * 64 + cc] * f1) * i1;
            const float r11 = (o[nb][3] * e1 + ob[(g + 8) * 64 + cc + 1] * f1) * i1;
            const size_t ofs0 = (size_t)qi0 * HID + h * HD + cc;
            const size_t ofs1 = (size_t)qi1 * HID + h * HD + cc;
            *(uint32_t*)&g_ah[ofs0] = packh2(r00, r01);
            *(uint32_t*)&g_ah[ofs1] = packh2(r10, r11);
        }
    }
}

// ---------------- launch ----------------
extern "C" void kernel_launch(void* const* d_in, const int* in_sizes, int n_in,
                              void* d_out, int out_size) {
    const float* x    = (const float*)d_in[0];
    const float* Wqkv = (const float*)d_in[1];
    const float* Wout = (const float*)d_in[2];
    float* out = (float*)d_out;

    float* qkv = nullptr;
    cudaGetSymbolAddress((void**)&qkv, g_qkv);
    __half *xh, *wqh, *wql, *woh, *wol, *ah;
    cudaGetSymbolAddress((void**)&xh,  g_xh);
    cudaGetSymbolAddress((void**)&wqh, g_wqh); cudaGetSymbolAddress((void**)&wql, g_wql);
    cudaGetSymbolAddress((void**)&woh, g_woh); cudaGetSymbolAddress((void**)&wol, g_wol);
    cudaGetSymbolAddress((void**)&ah,  g_ah);

    cudaFuncSetAttribute(gemm_f16, cudaFuncAttributeMaxDynamicSharedMemorySize, GF_SMEM);
    cudaFuncSetAttribute(attn_mma, cudaFuncAttributeMaxDynamicSharedMemorySize, AT_SMEM);
    cudaFuncSetAttribute(attn_global_mma, cudaFuncAttributeMaxDynamicSharedMemorySize, GA_SMEM);

    // 0) conversions
    conv_half<<<(SEQ * HID / 4 + 255) / 256, 256>>>(x, xh, SEQ * HID / 4);
    split_half<<<(H3 * HID / 4 + 255) / 256, 256>>>(Wqkv, wqh, wql, H3 * HID / 4);
    split_half<<<(HID * HID / 4 + 255) / 256, 256>>>(Wout, woh, wol, HID * HID / 4);

    // 1) qkv = x @ Wqkv^T  (fp16 2-term)
    gemm_f16<<<dim3(H3 / 128, SEQ / 128), 256, GF_SMEM>>>(xh, wqh, wql, qkv, SEQ, H3, HID);

    // 2) per-head fp16 operands
    prep_attn<<<dim3(SEQ / 64, NHEAD), 256>>>();

    // 3) sparse attention -> g_ah (fp16)
    attn_mma<<<dim3(SEQ / 64, NHEAD), 128, AT_SMEM>>>();
    attn_global_mma<<<NHEAD, 128, GA_SMEM>>>();

    // 4) out = attn @ Wout^T  (fp16 2-term)
    gemm_f16<<<dim3(HID / 128, SEQ / 128), 256, GF_SMEM>>>(ah, woh, wol, out, SEQ, HID, HID);
}